// round 10
// baseline (speedup 1.0000x reference)
#include <cuda_runtime.h>
#include <cuda_bf16.h>
#include <cstdint>

// Problem constants
#define EMB   1024
#define NH    16
#define HD    64
#define BATCH 4
#define SEQ   1024
#define MTOT  (BATCH*SEQ)
#define SCALING 0.3952847075210474f   // (64*0.1)^-0.5
#define NEG   (-1e30f)

// Scratch (device globals)
__device__ __nv_bfloat16 g_A_hi[MTOT * EMB];
__device__ __nv_bfloat16 g_A_lo[MTOT * EMB];
__device__ __nv_bfloat16 g_W1_hi[3 * EMB * EMB];
__device__ __nv_bfloat16 g_W1_lo[3 * EMB * EMB];
__device__ __nv_bfloat16 g_W2_hi[EMB * EMB];
__device__ __nv_bfloat16 g_W2_lo[EMB * EMB];
__device__ __nv_bfloat16 g_att_hi[MTOT * EMB];
__device__ __nv_bfloat16 g_att_lo[MTOT * EMB];
__device__ __nv_bfloat16 g_Qh[MTOT * EMB];
__device__ __nv_bfloat16 g_Ql[MTOT * EMB];
__device__ __nv_bfloat16 g_Kh[MTOT * EMB];
__device__ __nv_bfloat16 g_Kl[MTOT * EMB];
__device__ __nv_bfloat16 g_Vh[MTOT * EMB];
__device__ __nv_bfloat16 g_Vl[MTOT * EMB];

// ---------------------------------------------------------------------------
// PTX helpers
// ---------------------------------------------------------------------------
#define LDSM4(r, addr) \
    asm volatile("ldmatrix.sync.aligned.m8n8.x4.shared.b16 {%0,%1,%2,%3}, [%4];" \
                 : "=r"((r)[0]), "=r"((r)[1]), "=r"((r)[2]), "=r"((r)[3]) : "r"(addr))

#define LDSM4T(r, addr) \
    asm volatile("ldmatrix.sync.aligned.m8n8.x4.trans.shared.b16 {%0,%1,%2,%3}, [%4];" \
                 : "=r"((r)[0]), "=r"((r)[1]), "=r"((r)[2]), "=r"((r)[3]) : "r"(addr))

#define MMA_BF16(d, a, b) \
    asm volatile("mma.sync.aligned.m16n8k16.row.col.f32.bf16.bf16.f32 " \
                 "{%0,%1,%2,%3},{%4,%5,%6,%7},{%8,%9},{%0,%1,%2,%3};" \
                 : "+f"((d)[0]), "+f"((d)[1]), "+f"((d)[2]), "+f"((d)[3]) \
                 : "r"((a)[0]), "r"((a)[1]), "r"((a)[2]), "r"((a)[3]), \
                   "r"((b)[0]), "r"((b)[1]))

__device__ __forceinline__ void cp16(uint32_t s, const void* g) {
    asm volatile("cp.async.cg.shared.global [%0], [%1], 16;" :: "r"(s), "l"(g));
}

__device__ __forceinline__ uint32_t packbf(float lo, float hi) {
    uint32_t r;
    asm("cvt.rn.bf16x2.f32 %0, %1, %2;" : "=r"(r) : "f"(hi), "f"(lo));
    return r;
}
__device__ __forceinline__ uint32_t residpack(uint32_t ph, float lo, float hi) {
    float h_lo = __uint_as_float(ph << 16);
    float h_hi = __uint_as_float(ph & 0xffff0000u);
    return packbf(lo - h_lo, hi - h_hi);
}

// ---------------------------------------------------------------------------
// f32 -> bf16 (hi, lo) split
// ---------------------------------------------------------------------------
__global__ __launch_bounds__(256)
void split_kernel(const float* __restrict__ in,
                  __nv_bfloat16* __restrict__ hi,
                  __nv_bfloat16* __restrict__ lo, int n)
{
    int i = (blockIdx.x * blockDim.x + threadIdx.x) * 4;
    if (i >= n) return;
    float4 v = *(const float4*)(in + i);
    float f[4] = {v.x, v.y, v.z, v.w};
    __nv_bfloat16 h[4], l[4];
#pragma unroll
    for (int j = 0; j < 4; j++) {
        h[j] = __float2bfloat16(f[j]);
        l[j] = __float2bfloat16(f[j] - __bfloat162float(h[j]));
    }
    *(uint2*)(hi + i) = *(const uint2*)h;
    *(uint2*)(lo + i) = *(const uint2*)l;
}

// ---------------------------------------------------------------------------
// Tensor-core GEMM (R6 config): C[M,N] = A[M,K]*B[N,K]^T + bias[N].
// CTA 128x128, 128 threads (4 warps, 2m x 2n), warp tile 64x64, BK=32,
// 2-stage cp.async, 2 CTAs/SM.
// mode 0: f32 C.  mode 1: fused head-major bf16 hi/lo QKV epilogue (Q scaled).
// ---------------------------------------------------------------------------
#define AST   40            // smem row stride in halves
#define MAT_H (128 * AST)   // halves per matrix per stage
#define GEMM_SMEM (8 * MAT_H * 2)   // 81920 B (2 stages x 4 matrices)

__global__ __launch_bounds__(128, 2)
void gemm_mma(const __nv_bfloat16* __restrict__ Ah,
              const __nv_bfloat16* __restrict__ Al,
              const __nv_bfloat16* __restrict__ Bh,
              const __nv_bfloat16* __restrict__ Bl,
              const float* __restrict__ bias,
              float* __restrict__ C,
              __nv_bfloat16* __restrict__ Qh, __nv_bfloat16* __restrict__ Ql,
              __nv_bfloat16* __restrict__ Kh, __nv_bfloat16* __restrict__ Kl,
              __nv_bfloat16* __restrict__ Vh, __nv_bfloat16* __restrict__ Vl,
              int M, int N, int K, int mode)
{
    extern __shared__ __align__(16) __nv_bfloat16 smem_b[];
    const uint32_t sm_base = (uint32_t)__cvta_generic_to_shared(smem_b);

    const int t    = threadIdx.x;
    const int lane = t & 31;
    const int w    = t >> 5;
    const int wm   = w & 1;     // m-warp (2)
    const int wn   = w >> 1;    // n-warp (2)
    const int bm   = blockIdx.y * 128;
    const int bn   = blockIdx.x * 128;
    const int nk   = K >> 5;

    float acc[4][8][4];
#pragma unroll
    for (int mi = 0; mi < 4; mi++)
#pragma unroll
        for (int ni = 0; ni < 8; ni++)
#pragma unroll
            for (int q = 0; q < 4; q++) acc[mi][ni][q] = 0.f;

    const __nv_bfloat16* gp[4] = {Ah, Al, Bh, Bl};

    // 16 cp.async chunks per thread per stage (4 matrices x 512 chunks)
    auto issue = [&](int stage, int k0) {
#pragma unroll
        for (int i = 0; i < 16; i++) {
            int c = t + i * 128;
            int mat = c >> 9;
            int idx = c & 511;
            int row = idx >> 2, ck = (idx & 3) * 8;
            int base = (mat < 2) ? bm : bn;
            uint32_t so = sm_base + (uint32_t)(stage * 4 + mat) * MAT_H * 2;
            cp16(so + (uint32_t)(row * AST + ck) * 2,
                 gp[mat] + (size_t)(base + row) * K + k0 + ck);
        }
        asm volatile("cp.async.commit_group;");
    };

    issue(0, 0);
    issue(1, 32);

    for (int kt = 0; kt < nk; kt++) {
        if (kt + 1 < nk) asm volatile("cp.async.wait_group 1;");
        else             asm volatile("cp.async.wait_group 0;");
        __syncthreads();

        const int stage = kt & 1;
        const uint32_t bAh = sm_base + (uint32_t)(stage * 4 + 0) * MAT_H * 2;
        const uint32_t bAl = sm_base + (uint32_t)(stage * 4 + 1) * MAT_H * 2;
        const uint32_t bBh = sm_base + (uint32_t)(stage * 4 + 2) * MAT_H * 2;
        const uint32_t bBl = sm_base + (uint32_t)(stage * 4 + 3) * MAT_H * 2;

#pragma unroll
        for (int ks = 0; ks < 2; ks++) {
            uint32_t ah[4][4], al[4][4], bh[8][2], bl[8][2];

            const int arow = wm * 64 + (lane & 15);
            const int acol = ks * 16 + (lane >> 4) * 8;
#pragma unroll
            for (int mi = 0; mi < 4; mi++) {
                uint32_t off = (uint32_t)((arow + mi * 16) * AST + acol) * 2;
                LDSM4(ah[mi], bAh + off);
                LDSM4(al[mi], bAl + off);
            }

            const int brow = wn * 64 + (lane >> 4) * 8 + (lane & 7);
            const int bcol = ks * 16 + ((lane >> 3) & 1) * 8;
#pragma unroll
            for (int ni2 = 0; ni2 < 4; ni2++) {
                uint32_t off = (uint32_t)((brow + ni2 * 16) * AST + bcol) * 2;
                uint32_t r[4];
                LDSM4(r, bBh + off);
                bh[ni2 * 2][0] = r[0]; bh[ni2 * 2][1] = r[1];
                bh[ni2 * 2 + 1][0] = r[2]; bh[ni2 * 2 + 1][1] = r[3];
                LDSM4(r, bBl + off);
                bl[ni2 * 2][0] = r[0]; bl[ni2 * 2][1] = r[1];
                bl[ni2 * 2 + 1][0] = r[2]; bl[ni2 * 2 + 1][1] = r[3];
            }

#pragma unroll
            for (int mi = 0; mi < 4; mi++)
#pragma unroll
                for (int ni = 0; ni < 8; ni++) {
                    MMA_BF16(acc[mi][ni], ah[mi], bh[ni]);   // hi*hi
                    MMA_BF16(acc[mi][ni], al[mi], bh[ni]);   // lo*hi
                    MMA_BF16(acc[mi][ni], ah[mi], bl[ni]);   // hi*lo
                }
        }
        __syncthreads();

        if (kt + 2 < nk) issue(kt & 1, (kt + 2) << 5);
    }

    if (mode == 0) {
        // f32 epilogue
#pragma unroll
        for (int mi = 0; mi < 4; mi++) {
            const int r0 = bm + wm * 64 + mi * 16 + (lane >> 2);
#pragma unroll
            for (int ni = 0; ni < 8; ni++) {
                const int col = bn + wn * 64 + ni * 8 + (lane & 3) * 2;
                float bx = bias[col], by = bias[col + 1];
                float2 v0 = make_float2(acc[mi][ni][0] + bx, acc[mi][ni][1] + by);
                float2 v1 = make_float2(acc[mi][ni][2] + bx, acc[mi][ni][3] + by);
                *(float2*)&C[(size_t)r0 * N + col] = v0;
                *(float2*)&C[(size_t)(r0 + 8) * N + col] = v1;
            }
        }
    } else {
        // fused qkv-split epilogue: head-major bf16 hi/lo, Q scaled after bias
        const int m = bn >> 10;   // 0=q 1=k 2=v (constant per CTA, bn 128-aligned)
        uint32_t* oh = (uint32_t*)((m == 0) ? Qh : (m == 1) ? Kh : Vh);
        uint32_t* ol = (uint32_t*)((m == 0) ? Ql : (m == 1) ? Kl : Vl);
        const float sc = (m == 0) ? SCALING : 1.0f;
#pragma unroll
        for (int mi = 0; mi < 4; mi++) {
            const int r0 = bm + wm * 64 + mi * 16 + (lane >> 2);
#pragma unroll
            for (int ni = 0; ni < 8; ni++) {
                const int col = bn + wn * 64 + ni * 8 + (lane & 3) * 2;
                const int hh = (col >> 6) & 15, d = col & 63;
                float bx = bias[col], by = bias[col + 1];
                float a0 = (acc[mi][ni][0] + bx) * sc;
                float a1 = (acc[mi][ni][1] + by) * sc;
                float b0 = (acc[mi][ni][2] + bx) * sc;
                float b1 = (acc[mi][ni][3] + by) * sc;
#pragma unroll
                for (int rr = 0; rr < 2; rr++) {
                    int r = r0 + rr * 8;
                    float v0 = rr ? b0 : a0, v1 = rr ? b1 : a1;
                    int bb = r >> 10, s = r & 1023;
                    size_t idx = ((((size_t)(bb * NH + hh)) << 10) + s) * HD + d;
                    uint32_t hp = packbf(v0, v1);
                    oh[idx >> 1] = hp;
                    ol[idx >> 1] = residpack(hp, v0, v1);
                }
            }
        }
    }
}

// ---------------------------------------------------------------------------
// Tensor-core flash attention (R6) + bf16 hi/lo epilogue.
// ---------------------------------------------------------------------------
#define AT_ST 72
#define Q_HI_B 0
#define Q_LO_B 18432
#define TILE_B 36864
#define ATT_MAT_B  9216
#define BUF_B  36864
#define ATT_SMEM 110592

__global__ __launch_bounds__(256)
void attn_mma(const float* __restrict__ bias, const unsigned char* __restrict__ mask,
              __nv_bfloat16* __restrict__ outh, __nv_bfloat16* __restrict__ outl,
              const __nv_bfloat16* __restrict__ Qh, const __nv_bfloat16* __restrict__ Ql,
              const __nv_bfloat16* __restrict__ Kh, const __nv_bfloat16* __restrict__ Kl,
              const __nv_bfloat16* __restrict__ Vh, const __nv_bfloat16* __restrict__ Vl)
{
    extern __shared__ __align__(16) __nv_bfloat16 smA[];
    const uint32_t s_base = (uint32_t)__cvta_generic_to_shared(smA);

    const int t = threadIdx.x, lane = t & 31, wid = t >> 5;
    const int qt = blockIdx.x, h = blockIdx.y, b = blockIdx.z;
    const int qbase = qt * 128;
    const size_t hb = (size_t)(b * NH + h) * SEQ * HD;

    const int lr7 = lane & 7, l8 = (lane >> 3) & 1, l16 = lane >> 4;

    const __nv_bfloat16* qsrc[2] = {Qh, Ql};
    const __nv_bfloat16* ksrc[4] = {Kh, Kl, Vh, Vl};

#pragma unroll
    for (int it = 0; it < 8; it++) {
        int c = t + it * 256;
        int mat = c >> 10, r = (c >> 3) & 127, ck = c & 7;
        cp16(s_base + mat * Q_LO_B + (uint32_t)(r * AT_ST + ck * 8) * 2,
             qsrc[mat] + hb + (size_t)(qbase + r) * HD + ck * 8);
    }
#pragma unroll
    for (int it = 0; it < 8; it++) {
        int c = t + it * 256;
        int mat = c >> 9, r = (c >> 3) & 63, ck = c & 7;
        cp16(s_base + TILE_B + mat * ATT_MAT_B + (uint32_t)(r * AT_ST + ck * 8) * 2,
             ksrc[mat] + hb + (size_t)r * HD + ck * 8);
    }
    asm volatile("cp.async.commit_group;");
#pragma unroll
    for (int it = 0; it < 8; it++) {
        int c = t + it * 256;
        int mat = c >> 9, r = (c >> 3) & 63, ck = c & 7;
        cp16(s_base + TILE_B + BUF_B + mat * ATT_MAT_B + (uint32_t)(r * AT_ST + ck * 8) * 2,
             ksrc[mat] + hb + (size_t)(64 + r) * HD + ck * 8);
    }
    asm volatile("cp.async.commit_group;");
    asm volatile("cp.async.wait_group 1;");
    __syncthreads();

    uint32_t aqh[4][4], aql[4][4];
    {
        const int arow = wid * 16 + (lane & 15);
        const int acol = 8 * l16;
#pragma unroll
        for (int ks = 0; ks < 4; ks++) {
            uint32_t off = (uint32_t)(arow * AT_ST + ks * 16 + acol) * 2;
            LDSM4(aqh[ks], s_base + Q_HI_B + off);
            LDSM4(aql[ks], s_base + Q_LO_B + off);
        }
    }

    float O[8][4];
#pragma unroll
    for (int nf = 0; nf < 8; nf++)
#pragma unroll
        for (int q = 0; q < 4; q++) O[nf][q] = 0.f;
    float m0 = NEG, m1 = NEG, l0 = 0.f, l1 = 0.f;

    const float* bp = bias + (size_t)(b * NH + h) * SEQ * SEQ;
    const unsigned char* mrow = mask + (size_t)b * SEQ;
    const int qr = qbase + wid * 16 + (lane >> 2);
    const int colb = 2 * (lane & 3);

    const int krow = lr7 + 8 * l16;
    const int kcol = 8 * l8;
    const int vrow = lr7 + 8 * l8;
    const int vcol = 8 * l16;

    for (int kt = 0; kt < 16; kt++) {
        const uint32_t tb = s_base + TILE_B + (uint32_t)(kt & 1) * BUF_B;

        float2 bv0[8], bv1[8];
        uchar2 mk[8];
#pragma unroll
        for (int nf = 0; nf < 8; nf++) {
            int col = kt * 64 + nf * 8 + colb;
            bv0[nf] = *(const float2*)&bp[(size_t)qr * SEQ + col];
            bv1[nf] = *(const float2*)&bp[(size_t)(qr + 8) * SEQ + col];
            mk[nf]  = *(const uchar2*)&mrow[col];
        }

        float s[8][4];
#pragma unroll
        for (int nf = 0; nf < 8; nf++)
#pragma unroll
            for (int q = 0; q < 4; q++) s[nf][q] = 0.f;

#pragma unroll
        for (int ks = 0; ks < 4; ks++) {
            uint32_t bh[8][2], bl[8][2];
#pragma unroll
            for (int nf2 = 0; nf2 < 4; nf2++) {
                uint32_t off = (uint32_t)((nf2 * 16 + krow) * AT_ST + ks * 16 + kcol) * 2;
                uint32_t r4[4];
                LDSM4(r4, tb + 0 * ATT_MAT_B + off);
                bh[2*nf2][0] = r4[0]; bh[2*nf2][1] = r4[1];
                bh[2*nf2+1][0] = r4[2]; bh[2*nf2+1][1] = r4[3];
                LDSM4(r4, tb + 1 * ATT_MAT_B + off);
                bl[2*nf2][0] = r4[0]; bl[2*nf2][1] = r4[1];
                bl[2*nf2+1][0] = r4[2]; bl[2*nf2+1][1] = r4[3];
            }
#pragma unroll
            for (int nf = 0; nf < 8; nf++) {
                MMA_BF16(s[nf], aqh[ks], bh[nf]);
                MMA_BF16(s[nf], aql[ks], bh[nf]);
                MMA_BF16(s[nf], aqh[ks], bl[nf]);
            }
        }

#pragma unroll
        for (int nf = 0; nf < 8; nf++) {
            s[nf][0] = mk[nf].x ? NEG : s[nf][0] + bv0[nf].x;
            s[nf][1] = mk[nf].y ? NEG : s[nf][1] + bv0[nf].y;
            s[nf][2] = mk[nf].x ? NEG : s[nf][2] + bv1[nf].x;
            s[nf][3] = mk[nf].y ? NEG : s[nf][3] + bv1[nf].y;
        }

        float mx0 = NEG, mx1 = NEG;
#pragma unroll
        for (int nf = 0; nf < 8; nf++) {
            mx0 = fmaxf(mx0, fmaxf(s[nf][0], s[nf][1]));
            mx1 = fmaxf(mx1, fmaxf(s[nf][2], s[nf][3]));
        }
        mx0 = fmaxf(mx0, __shfl_xor_sync(0xffffffffu, mx0, 1));
        mx0 = fmaxf(mx0, __shfl_xor_sync(0xffffffffu, mx0, 2));
        mx1 = fmaxf(mx1, __shfl_xor_sync(0xffffffffu, mx1, 1));
        mx1 = fmaxf(mx1, __shfl_xor_sync(0xffffffffu, mx1, 2));
        float mn0 = fmaxf(m0, mx0), mn1 = fmaxf(m1, mx1);
        float sc0 = __expf(m0 - mn0), sc1 = __expf(m1 - mn1);
        m0 = mn0; m1 = mn1;
        float su0 = 0.f, su1 = 0.f;
#pragma unroll
        for (int nf = 0; nf < 8; nf++) {
            s[nf][0] = __expf(s[nf][0] - mn0);
            s[nf][1] = __expf(s[nf][1] - mn0);
            s[nf][2] = __expf(s[nf][2] - mn1);
            s[nf][3] = __expf(s[nf][3] - mn1);
            su0 += s[nf][0] + s[nf][1];
            su1 += s[nf][2] + s[nf][3];
        }
        su0 += __shfl_xor_sync(0xffffffffu, su0, 1);
        su0 += __shfl_xor_sync(0xffffffffu, su0, 2);
        su1 += __shfl_xor_sync(0xffffffffu, su1, 1);
        su1 += __shfl_xor_sync(0xffffffffu, su1, 2);
        l0 = l0 * sc0 + su0;
        l1 = l1 * sc1 + su1;
#pragma unroll
        for (int nf = 0; nf < 8; nf++) {
            O[nf][0] *= sc0; O[nf][1] *= sc0;
            O[nf][2] *= sc1; O[nf][3] *= sc1;
        }

#pragma unroll
        for (int ks = 0; ks < 4; ks++) {
            uint32_t aph[4], apl[4];
            {
                const float* p0 = s[2 * ks];
                const float* p1 = s[2 * ks + 1];
                aph[0] = packbf(p0[0], p0[1]);
                aph[1] = packbf(p0[2], p0[3]);
                aph[2] = packbf(p1[0], p1[1]);
                aph[3] = packbf(p1[2], p1[3]);
                apl[0] = residpack(aph[0], p0[0], p0[1]);
                apl[1] = residpack(aph[1], p0[2], p0[3]);
                apl[2] = residpack(aph[2], p1[0], p1[1]);
                apl[3] = residpack(aph[3], p1[2], p1[3]);
            }
            uint32_t vh[8][2], vl[8][2];
#pragma unroll
            for (int nf2 = 0; nf2 < 4; nf2++) {
                uint32_t off = (uint32_t)((ks * 16 + vrow) * AT_ST + nf2 * 16 + vcol) * 2;
                uint32_t r4[4];
                LDSM4T(r4, tb + 2 * ATT_MAT_B + off);
                vh[2*nf2][0] = r4[0]; vh[2*nf2][1] = r4[1];
                vh[2*nf2+1][0] = r4[2]; vh[2*nf2+1][1] = r4[3];
                LDSM4T(r4, tb + 3 * ATT_MAT_B + off);
                vl[2*nf2][0] = r4[0]; vl[2*nf2][1] = r4[1];
                vl[2*nf2+1][0] = r4[2]; vl[2*nf2+1][1] = r4[3];
            }
#pragma unroll
            for (int nf = 0; nf < 8; nf++) {
                MMA_BF16(O[nf], aph, vh[nf]);
                MMA_BF16(O[nf], apl, vh[nf]);
                MMA_BF16(O[nf], aph, vl[nf]);
            }
        }

        __syncthreads();
        if (kt + 2 < 16) {
#pragma unroll
            for (int it = 0; it < 8; it++) {
                int c = t + it * 256;
                int mat = c >> 9, r = (c >> 3) & 63, ck = c & 7;
                cp16(s_base + TILE_B + (uint32_t)(kt & 1) * BUF_B + mat * ATT_MAT_B +
                         (uint32_t)(r * AT_ST + ck * 8) * 2,
                     ksrc[mat] + hb + (size_t)((kt + 2) * 64 + r) * HD + ck * 8);
            }
            asm volatile("cp.async.commit_group;");
        }
        if (kt + 1 < 16) {
            if (kt + 2 < 16) asm volatile("cp.async.wait_group 1;");
            else             asm volatile("cp.async.wait_group 0;");
            __syncthreads();
        }
    }

    float i0 = 1.f / l0, i1 = 1.f / l1;
    int orow = b * SEQ + qbase + wid * 16 + (lane >> 2);
    uint32_t* oh = (uint32_t*)outh;
    uint32_t* ol = (uint32_t*)outl;
#pragma unroll
    for (int nf = 0; nf < 8; nf++) {
        int col = h * HD + nf * 8 + colb;
        float a0 = O[nf][0] * i0, a1 = O[nf][1] * i0;
        float b0 = O[nf][2] * i1, b1 = O[nf][3] * i1;
        uint32_t h0 = packbf(a0, a1);
        uint32_t l0r = residpack(h0, a0, a1);
        uint32_t h1 = packbf(b0, b1);
        uint32_t l1r = residpack(h1, b0, b1);
        size_t idx0 = ((size_t)orow * EMB + col) >> 1;
        size_t idx1 = ((size_t)(orow + 8) * EMB + col) >> 1;
        oh[idx0] = h0; ol[idx0] = l0r;
        oh[idx1] = h1; ol[idx1] = l1r;
    }
}

// ---------------------------------------------------------------------------
extern "C" void kernel_launch(void* const* d_in, const int* in_sizes, int n_in,
                              void* d_out, int out_size)
{
    const float* query         = (const float*)d_in[0];
    const unsigned char* maskp = (const unsigned char*)d_in[1];
    const float* attn_bias     = (const float*)d_in[2];
    const float* Wqkv          = (const float*)d_in[3];
    const float* bqkv          = (const float*)d_in[4];
    const float* Wo            = (const float*)d_in[5];
    const float* bo            = (const float*)d_in[6];
    float* out                 = (float*)d_out;

    __nv_bfloat16 *Ahi, *Alo, *W1hi, *W1lo, *W2hi, *W2lo, *Thi, *Tlo;
    __nv_bfloat16 *Qh, *Ql, *Kh, *Kl, *Vh, *Vl;
    cudaGetSymbolAddress((void**)&Ahi,  g_A_hi);
    cudaGetSymbolAddress((void**)&Alo,  g_A_lo);
    cudaGetSymbolAddress((void**)&W1hi, g_W1_hi);
    cudaGetSymbolAddress((void**)&W1lo, g_W1_lo);
    cudaGetSymbolAddress((void**)&W2hi, g_W2_hi);
    cudaGetSymbolAddress((void**)&W2lo, g_W2_lo);
    cudaGetSymbolAddress((void**)&Thi,  g_att_hi);
    cudaGetSymbolAddress((void**)&Tlo,  g_att_lo);
    cudaGetSymbolAddress((void**)&Qh,   g_Qh);
    cudaGetSymbolAddress((void**)&Ql,   g_Ql);
    cudaGetSymbolAddress((void**)&Kh,   g_Kh);
    cudaGetSymbolAddress((void**)&Kl,   g_Kl);
    cudaGetSymbolAddress((void**)&Vh,   g_Vh);
    cudaGetSymbolAddress((void**)&Vl,   g_Vl);

    cudaFuncSetAttribute(gemm_mma,
                         cudaFuncAttributeMaxDynamicSharedMemorySize, GEMM_SMEM);
    cudaFuncSetAttribute(attn_mma,
                         cudaFuncAttributeMaxDynamicSharedMemorySize, ATT_SMEM);

    // 0) split inputs + weights into bf16 (hi, lo)
    split_kernel<<<(MTOT * EMB) / 1024, 256>>>(query, Ahi, Alo, MTOT * EMB);
    split_kernel<<<(3 * EMB * EMB) / 1024, 256>>>(Wqkv, W1hi, W1lo, 3 * EMB * EMB);
    split_kernel<<<(EMB * EMB) / 1024, 256>>>(Wo, W2hi, W2lo, EMB * EMB);

    // 1) QKV projection, fused head-major bf16 hi/lo epilogue (Q pre-scaled)
    {
        dim3 grid(3 * EMB / 128, MTOT / 128);
        gemm_mma<<<grid, 128, GEMM_SMEM>>>(Ahi, Alo, W1hi, W1lo, bqkv,
                                           nullptr, Qh, Ql, Kh, Kl, Vh, Vl,
                                           MTOT, 3 * EMB, EMB, 1);
    }

    // 2) flash attention, writes bf16 hi/lo attention output
    {
        dim3 grid(SEQ / 128, NH, BATCH);
        attn_mma<<<grid, 256, ATT_SMEM>>>(attn_bias, maskp, Thi, Tlo,
                                          Qh, Ql, Kh, Kl, Vh, Vl);
    }

    // 3) output projection (f32 epilogue into d_out)
    {
        dim3 grid(EMB / 128, MTOT / 128);
        gemm_mma<<<grid, 128, GEMM_SMEM>>>(Thi, Tlo, W2hi, W2lo, bo,
                                           out, nullptr, nullptr, nullptr,
                                           nullptr, nullptr, nullptr,
                                           MTOT, EMB, EMB, 0);
    }
}

// round 11
// speedup vs baseline: 1.5154x; 1.5154x over previous
#include <cuda_runtime.h>
#include <cuda_bf16.h>
#include <cstdint>

// Problem constants
#define EMB   1024
#define NH    16
#define HD    64
#define BATCH 4
#define SEQ   1024
#define MTOT  (BATCH*SEQ)
#define SCALING 0.3952847075210474f   // (64*0.1)^-0.5
#define NEG   (-1e30f)

// Scratch (device globals)
__device__ __nv_bfloat16 g_A_hi[MTOT * EMB];
__device__ __nv_bfloat16 g_A_lo[MTOT * EMB];
__device__ __nv_bfloat16 g_W1_hi[3 * EMB * EMB];
__device__ __nv_bfloat16 g_W1_lo[3 * EMB * EMB];
__device__ __nv_bfloat16 g_W2_hi[EMB * EMB];
__device__ __nv_bfloat16 g_W2_lo[EMB * EMB];
__device__ __nv_bfloat16 g_att_hi[MTOT * EMB];
__device__ __nv_bfloat16 g_att_lo[MTOT * EMB];
__device__ __nv_bfloat16 g_Qh[MTOT * EMB];
__device__ __nv_bfloat16 g_Ql[MTOT * EMB];
__device__ __nv_bfloat16 g_Kh[MTOT * EMB];
__device__ __nv_bfloat16 g_Kl[MTOT * EMB];
__device__ __nv_bfloat16 g_Vh[MTOT * EMB];
__device__ __nv_bfloat16 g_Vl[MTOT * EMB];

// ---------------------------------------------------------------------------
// PTX helpers
// ---------------------------------------------------------------------------
#define LDSM4(r, addr) \
    asm volatile("ldmatrix.sync.aligned.m8n8.x4.shared.b16 {%0,%1,%2,%3}, [%4];" \
                 : "=r"((r)[0]), "=r"((r)[1]), "=r"((r)[2]), "=r"((r)[3]) : "r"(addr))

#define LDSM4T(r, addr) \
    asm volatile("ldmatrix.sync.aligned.m8n8.x4.trans.shared.b16 {%0,%1,%2,%3}, [%4];" \
                 : "=r"((r)[0]), "=r"((r)[1]), "=r"((r)[2]), "=r"((r)[3]) : "r"(addr))

#define MMA_BF16(d, a, b) \
    asm volatile("mma.sync.aligned.m16n8k16.row.col.f32.bf16.bf16.f32 " \
                 "{%0,%1,%2,%3},{%4,%5,%6,%7},{%8,%9},{%0,%1,%2,%3};" \
                 : "+f"((d)[0]), "+f"((d)[1]), "+f"((d)[2]), "+f"((d)[3]) \
                 : "r"((a)[0]), "r"((a)[1]), "r"((a)[2]), "r"((a)[3]), \
                   "r"((b)[0]), "r"((b)[1]))

__device__ __forceinline__ void cp16(uint32_t s, const void* g) {
    asm volatile("cp.async.cg.shared.global [%0], [%1], 16;" :: "r"(s), "l"(g));
}

__device__ __forceinline__ uint32_t packbf(float lo, float hi) {
    uint32_t r;
    asm("cvt.rn.bf16x2.f32 %0, %1, %2;" : "=r"(r) : "f"(hi), "f"(lo));
    return r;
}
__device__ __forceinline__ uint32_t residpack(uint32_t ph, float lo, float hi) {
    float h_lo = __uint_as_float(ph << 16);
    float h_hi = __uint_as_float(ph & 0xffff0000u);
    return packbf(lo - h_lo, hi - h_hi);
}

// ---------------------------------------------------------------------------
// f32 -> bf16 (hi, lo) split
// ---------------------------------------------------------------------------
__global__ __launch_bounds__(256)
void split_kernel(const float* __restrict__ in,
                  __nv_bfloat16* __restrict__ hi,
                  __nv_bfloat16* __restrict__ lo, int n)
{
    int i = (blockIdx.x * blockDim.x + threadIdx.x) * 4;
    if (i >= n) return;
    float4 v = *(const float4*)(in + i);
    float f[4] = {v.x, v.y, v.z, v.w};
    __nv_bfloat16 h[4], l[4];
#pragma unroll
    for (int j = 0; j < 4; j++) {
        h[j] = __float2bfloat16(f[j]);
        l[j] = __float2bfloat16(f[j] - __bfloat162float(h[j]));
    }
    *(uint2*)(hi + i) = *(const uint2*)h;
    *(uint2*)(lo + i) = *(const uint2*)l;
}

// ---------------------------------------------------------------------------
// Tensor-core GEMM (R6 config): C[M,N] = A[M,K]*B[N,K]^T + bias[N].
// CTA 128x128, 128 threads (4 warps, 2m x 2n), warp tile 64x64, BK=32,
// 2-stage cp.async, 2 CTAs/SM.
// mode 0: f32 C.
// mode 1: fused head-major bf16 hi/lo QKV epilogue (Q scaled), smem-staged
//         so all global stores are full coalesced 128B lines.
// ---------------------------------------------------------------------------
#define AST   40            // smem row stride in halves
#define MAT_H (128 * AST)   // halves per matrix per stage
#define GEMM_SMEM (8 * MAT_H * 2)   // 81920 B (2 stages x 4 matrices)
#define EP_ST 68            // staging stride in uint32 (conflict-free)

__global__ __launch_bounds__(128, 2)
void gemm_mma(const __nv_bfloat16* __restrict__ Ah,
              const __nv_bfloat16* __restrict__ Al,
              const __nv_bfloat16* __restrict__ Bh,
              const __nv_bfloat16* __restrict__ Bl,
              const float* __restrict__ bias,
              float* __restrict__ C,
              __nv_bfloat16* __restrict__ Qh, __nv_bfloat16* __restrict__ Ql,
              __nv_bfloat16* __restrict__ Kh, __nv_bfloat16* __restrict__ Kl,
              __nv_bfloat16* __restrict__ Vh, __nv_bfloat16* __restrict__ Vl,
              int M, int N, int K, int mode)
{
    extern __shared__ __align__(16) __nv_bfloat16 smem_b[];
    const uint32_t sm_base = (uint32_t)__cvta_generic_to_shared(smem_b);

    const int t    = threadIdx.x;
    const int lane = t & 31;
    const int w    = t >> 5;
    const int wm   = w & 1;     // m-warp (2)
    const int wn   = w >> 1;    // n-warp (2)
    const int bm   = blockIdx.y * 128;
    const int bn   = blockIdx.x * 128;
    const int nk   = K >> 5;

    float acc[4][8][4];
#pragma unroll
    for (int mi = 0; mi < 4; mi++)
#pragma unroll
        for (int ni = 0; ni < 8; ni++)
#pragma unroll
            for (int q = 0; q < 4; q++) acc[mi][ni][q] = 0.f;

    const __nv_bfloat16* gp[4] = {Ah, Al, Bh, Bl};

    // 16 cp.async chunks per thread per stage (4 matrices x 512 chunks)
    auto issue = [&](int stage, int k0) {
#pragma unroll
        for (int i = 0; i < 16; i++) {
            int c = t + i * 128;
            int mat = c >> 9;
            int idx = c & 511;
            int row = idx >> 2, ck = (idx & 3) * 8;
            int base = (mat < 2) ? bm : bn;
            uint32_t so = sm_base + (uint32_t)(stage * 4 + mat) * MAT_H * 2;
            cp16(so + (uint32_t)(row * AST + ck) * 2,
                 gp[mat] + (size_t)(base + row) * K + k0 + ck);
        }
        asm volatile("cp.async.commit_group;");
    };

    issue(0, 0);
    issue(1, 32);

    for (int kt = 0; kt < nk; kt++) {
        if (kt + 1 < nk) asm volatile("cp.async.wait_group 1;");
        else             asm volatile("cp.async.wait_group 0;");
        __syncthreads();

        const int stage = kt & 1;
        const uint32_t bAh = sm_base + (uint32_t)(stage * 4 + 0) * MAT_H * 2;
        const uint32_t bAl = sm_base + (uint32_t)(stage * 4 + 1) * MAT_H * 2;
        const uint32_t bBh = sm_base + (uint32_t)(stage * 4 + 2) * MAT_H * 2;
        const uint32_t bBl = sm_base + (uint32_t)(stage * 4 + 3) * MAT_H * 2;

#pragma unroll
        for (int ks = 0; ks < 2; ks++) {
            uint32_t ah[4][4], al[4][4], bh[8][2], bl[8][2];

            const int arow = wm * 64 + (lane & 15);
            const int acol = ks * 16 + (lane >> 4) * 8;
#pragma unroll
            for (int mi = 0; mi < 4; mi++) {
                uint32_t off = (uint32_t)((arow + mi * 16) * AST + acol) * 2;
                LDSM4(ah[mi], bAh + off);
                LDSM4(al[mi], bAl + off);
            }

            const int brow = wn * 64 + (lane >> 4) * 8 + (lane & 7);
            const int bcol = ks * 16 + ((lane >> 3) & 1) * 8;
#pragma unroll
            for (int ni2 = 0; ni2 < 4; ni2++) {
                uint32_t off = (uint32_t)((brow + ni2 * 16) * AST + bcol) * 2;
                uint32_t r[4];
                LDSM4(r, bBh + off);
                bh[ni2 * 2][0] = r[0]; bh[ni2 * 2][1] = r[1];
                bh[ni2 * 2 + 1][0] = r[2]; bh[ni2 * 2 + 1][1] = r[3];
                LDSM4(r, bBl + off);
                bl[ni2 * 2][0] = r[0]; bl[ni2 * 2][1] = r[1];
                bl[ni2 * 2 + 1][0] = r[2]; bl[ni2 * 2 + 1][1] = r[3];
            }

#pragma unroll
            for (int mi = 0; mi < 4; mi++)
#pragma unroll
                for (int ni = 0; ni < 8; ni++) {
                    MMA_BF16(acc[mi][ni], ah[mi], bh[ni]);   // hi*hi
                    MMA_BF16(acc[mi][ni], al[mi], bh[ni]);   // lo*hi
                    MMA_BF16(acc[mi][ni], ah[mi], bl[ni]);   // hi*lo
                }
        }
        __syncthreads();

        if (kt + 2 < nk) issue(kt & 1, (kt + 2) << 5);
    }

    if (mode == 0) {
        // f32 epilogue
#pragma unroll
        for (int mi = 0; mi < 4; mi++) {
            const int r0 = bm + wm * 64 + mi * 16 + (lane >> 2);
#pragma unroll
            for (int ni = 0; ni < 8; ni++) {
                const int col = bn + wn * 64 + ni * 8 + (lane & 3) * 2;
                float bx = bias[col], by = bias[col + 1];
                float2 v0 = make_float2(acc[mi][ni][0] + bx, acc[mi][ni][1] + by);
                float2 v1 = make_float2(acc[mi][ni][2] + bx, acc[mi][ni][3] + by);
                *(float2*)&C[(size_t)r0 * N + col] = v0;
                *(float2*)&C[(size_t)(r0 + 8) * N + col] = v1;
            }
        }
    } else {
        // fused qkv-split epilogue, smem-staged for coalesced stores.
        __syncthreads();   // done with pipeline buffers; reuse smem
        uint32_t* sh = (uint32_t*)smem_b;          // [128][EP_ST] hi
        uint32_t* sl = sh + 128 * EP_ST;           // [128][EP_ST] lo
        const int m = bn >> 10;                    // 0=q 1=k 2=v
        const float sc = (m == 0) ? SCALING : 1.0f;

#pragma unroll
        for (int mi = 0; mi < 4; mi++) {
            const int lr0 = wm * 64 + mi * 16 + (lane >> 2);   // local row
#pragma unroll
            for (int ni = 0; ni < 8; ni++) {
                const int lcol = wn * 64 + ni * 8 + (lane & 3) * 2;
                const int colu = lcol >> 1;
                float bx = bias[bn + lcol], by = bias[bn + lcol + 1];
                float a0 = (acc[mi][ni][0] + bx) * sc;
                float a1 = (acc[mi][ni][1] + by) * sc;
                float b0 = (acc[mi][ni][2] + bx) * sc;
                float b1 = (acc[mi][ni][3] + by) * sc;
                uint32_t hp0 = packbf(a0, a1);
                uint32_t hp1 = packbf(b0, b1);
                sh[lr0 * EP_ST + colu] = hp0;
                sl[lr0 * EP_ST + colu] = residpack(hp0, a0, a1);
                sh[(lr0 + 8) * EP_ST + colu] = hp1;
                sl[(lr0 + 8) * EP_ST + colu] = residpack(hp1, b0, b1);
            }
        }
        __syncthreads();

        uint32_t* oh = (uint32_t*)((m == 0) ? Qh : (m == 1) ? Kh : Vh);
        uint32_t* ol = (uint32_t*)((m == 0) ? Ql : (m == 1) ? Kl : Vl);
        const int hh0 = (bn >> 6) & 15;            // two heads: hh0, hh0+1
        const int bb = bm >> 10, s0 = bm & 1023;

        // 2048 16B-chunks per matrix; warp covers 2 rows = 4 full 128B lines
#pragma unroll
        for (int i = 0; i < 16; i++) {
            int c = t + i * 128;
            int row = c >> 4, sub = c & 15;
            int j = sub >> 3, q4 = (sub & 7) * 4;  // head sel, uint32 offset
            size_t g = (((size_t)(bb * NH + hh0 + j)) * SEQ + s0 + row) * 32 + q4;
            uint4 vh = *(uint4*)&sh[row * EP_ST + j * 32 + q4];
            uint4 vl = *(uint4*)&sl[row * EP_ST + j * 32 + q4];
            *(uint4*)&oh[g] = vh;
            *(uint4*)&ol[g] = vl;
        }
    }
}

// ---------------------------------------------------------------------------
// Tensor-core flash attention (R6) + bf16 hi/lo epilogue.
// ---------------------------------------------------------------------------
#define AT_ST 72
#define Q_HI_B 0
#define Q_LO_B 18432
#define TILE_B 36864
#define ATT_MAT_B  9216
#define BUF_B  36864
#define ATT_SMEM 110592

__global__ __launch_bounds__(256)
void attn_mma(const float* __restrict__ bias, const unsigned char* __restrict__ mask,
              __nv_bfloat16* __restrict__ outh, __nv_bfloat16* __restrict__ outl,
              const __nv_bfloat16* __restrict__ Qh, const __nv_bfloat16* __restrict__ Ql,
              const __nv_bfloat16* __restrict__ Kh, const __nv_bfloat16* __restrict__ Kl,
              const __nv_bfloat16* __restrict__ Vh, const __nv_bfloat16* __restrict__ Vl)
{
    extern __shared__ __align__(16) __nv_bfloat16 smA[];
    const uint32_t s_base = (uint32_t)__cvta_generic_to_shared(smA);

    const int t = threadIdx.x, lane = t & 31, wid = t >> 5;
    const int qt = blockIdx.x, h = blockIdx.y, b = blockIdx.z;
    const int qbase = qt * 128;
    const size_t hb = (size_t)(b * NH + h) * SEQ * HD;

    const int lr7 = lane & 7, l8 = (lane >> 3) & 1, l16 = lane >> 4;

    const __nv_bfloat16* qsrc[2] = {Qh, Ql};
    const __nv_bfloat16* ksrc[4] = {Kh, Kl, Vh, Vl};

#pragma unroll
    for (int it = 0; it < 8; it++) {
        int c = t + it * 256;
        int mat = c >> 10, r = (c >> 3) & 127, ck = c & 7;
        cp16(s_base + mat * Q_LO_B + (uint32_t)(r * AT_ST + ck * 8) * 2,
             qsrc[mat] + hb + (size_t)(qbase + r) * HD + ck * 8);
    }
#pragma unroll
    for (int it = 0; it < 8; it++) {
        int c = t + it * 256;
        int mat = c >> 9, r = (c >> 3) & 63, ck = c & 7;
        cp16(s_base + TILE_B + mat * ATT_MAT_B + (uint32_t)(r * AT_ST + ck * 8) * 2,
             ksrc[mat] + hb + (size_t)r * HD + ck * 8);
    }
    asm volatile("cp.async.commit_group;");
#pragma unroll
    for (int it = 0; it < 8; it++) {
        int c = t + it * 256;
        int mat = c >> 9, r = (c >> 3) & 63, ck = c & 7;
        cp16(s_base + TILE_B + BUF_B + mat * ATT_MAT_B + (uint32_t)(r * AT_ST + ck * 8) * 2,
             ksrc[mat] + hb + (size_t)(64 + r) * HD + ck * 8);
    }
    asm volatile("cp.async.commit_group;");
    asm volatile("cp.async.wait_group 1;");
    __syncthreads();

    uint32_t aqh[4][4], aql[4][4];
    {
        const int arow = wid * 16 + (lane & 15);
        const int acol = 8 * l16;
#pragma unroll
        for (int ks = 0; ks < 4; ks++) {
            uint32_t off = (uint32_t)(arow * AT_ST + ks * 16 + acol) * 2;
            LDSM4(aqh[ks], s_base + Q_HI_B + off);
            LDSM4(aql[ks], s_base + Q_LO_B + off);
        }
    }

    float O[8][4];
#pragma unroll
    for (int nf = 0; nf < 8; nf++)
#pragma unroll
        for (int q = 0; q < 4; q++) O[nf][q] = 0.f;
    float m0 = NEG, m1 = NEG, l0 = 0.f, l1 = 0.f;

    const float* bp = bias + (size_t)(b * NH + h) * SEQ * SEQ;
    const unsigned char* mrow = mask + (size_t)b * SEQ;
    const int qr = qbase + wid * 16 + (lane >> 2);
    const int colb = 2 * (lane & 3);

    const int krow = lr7 + 8 * l16;
    const int kcol = 8 * l8;
    const int vrow = lr7 + 8 * l8;
    const int vcol = 8 * l16;

    for (int kt = 0; kt < 16; kt++) {
        const uint32_t tb = s_base + TILE_B + (uint32_t)(kt & 1) * BUF_B;

        float2 bv0[8], bv1[8];
        uchar2 mk[8];
#pragma unroll
        for (int nf = 0; nf < 8; nf++) {
            int col = kt * 64 + nf * 8 + colb;
            bv0[nf] = *(const float2*)&bp[(size_t)qr * SEQ + col];
            bv1[nf] = *(const float2*)&bp[(size_t)(qr + 8) * SEQ + col];
            mk[nf]  = *(const uchar2*)&mrow[col];
        }

        float s[8][4];
#pragma unroll
        for (int nf = 0; nf < 8; nf++)
#pragma unroll
            for (int q = 0; q < 4; q++) s[nf][q] = 0.f;

#pragma unroll
        for (int ks = 0; ks < 4; ks++) {
            uint32_t bh[8][2], bl[8][2];
#pragma unroll
            for (int nf2 = 0; nf2 < 4; nf2++) {
                uint32_t off = (uint32_t)((nf2 * 16 + krow) * AT_ST + ks * 16 + kcol) * 2;
                uint32_t r4[4];
                LDSM4(r4, tb + 0 * ATT_MAT_B + off);
                bh[2*nf2][0] = r4[0]; bh[2*nf2][1] = r4[1];
                bh[2*nf2+1][0] = r4[2]; bh[2*nf2+1][1] = r4[3];
                LDSM4(r4, tb + 1 * ATT_MAT_B + off);
                bl[2*nf2][0] = r4[0]; bl[2*nf2][1] = r4[1];
                bl[2*nf2+1][0] = r4[2]; bl[2*nf2+1][1] = r4[3];
            }
#pragma unroll
            for (int nf = 0; nf < 8; nf++) {
                MMA_BF16(s[nf], aqh[ks], bh[nf]);
                MMA_BF16(s[nf], aql[ks], bh[nf]);
                MMA_BF16(s[nf], aqh[ks], bl[nf]);
            }
        }

#pragma unroll
        for (int nf = 0; nf < 8; nf++) {
            s[nf][0] = mk[nf].x ? NEG : s[nf][0] + bv0[nf].x;
            s[nf][1] = mk[nf].y ? NEG : s[nf][1] + bv0[nf].y;
            s[nf][2] = mk[nf].x ? NEG : s[nf][2] + bv1[nf].x;
            s[nf][3] = mk[nf].y ? NEG : s[nf][3] + bv1[nf].y;
        }

        float mx0 = NEG, mx1 = NEG;
#pragma unroll
        for (int nf = 0; nf < 8; nf++) {
            mx0 = fmaxf(mx0, fmaxf(s[nf][0], s[nf][1]));
            mx1 = fmaxf(mx1, fmaxf(s[nf][2], s[nf][3]));
        }
        mx0 = fmaxf(mx0, __shfl_xor_sync(0xffffffffu, mx0, 1));
        mx0 = fmaxf(mx0, __shfl_xor_sync(0xffffffffu, mx0, 2));
        mx1 = fmaxf(mx1, __shfl_xor_sync(0xffffffffu, mx1, 1));
        mx1 = fmaxf(mx1, __shfl_xor_sync(0xffffffffu, mx1, 2));
        float mn0 = fmaxf(m0, mx0), mn1 = fmaxf(m1, mx1);
        float sc0 = __expf(m0 - mn0), sc1 = __expf(m1 - mn1);
        m0 = mn0; m1 = mn1;
        float su0 = 0.f, su1 = 0.f;
#pragma unroll
        for (int nf = 0; nf < 8; nf++) {
            s[nf][0] = __expf(s[nf][0] - mn0);
            s[nf][1] = __expf(s[nf][1] - mn0);
            s[nf][2] = __expf(s[nf][2] - mn1);
            s[nf][3] = __expf(s[nf][3] - mn1);
            su0 += s[nf][0] + s[nf][1];
            su1 += s[nf][2] + s[nf][3];
        }
        su0 += __shfl_xor_sync(0xffffffffu, su0, 1);
        su0 += __shfl_xor_sync(0xffffffffu, su0, 2);
        su1 += __shfl_xor_sync(0xffffffffu, su1, 1);
        su1 += __shfl_xor_sync(0xffffffffu, su1, 2);
        l0 = l0 * sc0 + su0;
        l1 = l1 * sc1 + su1;
#pragma unroll
        for (int nf = 0; nf < 8; nf++) {
            O[nf][0] *= sc0; O[nf][1] *= sc0;
            O[nf][2] *= sc1; O[nf][3] *= sc1;
        }

#pragma unroll
        for (int ks = 0; ks < 4; ks++) {
            uint32_t aph[4], apl[4];
            {
                const float* p0 = s[2 * ks];
                const float* p1 = s[2 * ks + 1];
                aph[0] = packbf(p0[0], p0[1]);
                aph[1] = packbf(p0[2], p0[3]);
                aph[2] = packbf(p1[0], p1[1]);
                aph[3] = packbf(p1[2], p1[3]);
                apl[0] = residpack(aph[0], p0[0], p0[1]);
                apl[1] = residpack(aph[1], p0[2], p0[3]);
                apl[2] = residpack(aph[2], p1[0], p1[1]);
                apl[3] = residpack(aph[3], p1[2], p1[3]);
            }
            uint32_t vh[8][2], vl[8][2];
#pragma unroll
            for (int nf2 = 0; nf2 < 4; nf2++) {
                uint32_t off = (uint32_t)((ks * 16 + vrow) * AT_ST + nf2 * 16 + vcol) * 2;
                uint32_t r4[4];
                LDSM4T(r4, tb + 2 * ATT_MAT_B + off);
                vh[2*nf2][0] = r4[0]; vh[2*nf2][1] = r4[1];
                vh[2*nf2+1][0] = r4[2]; vh[2*nf2+1][1] = r4[3];
                LDSM4T(r4, tb + 3 * ATT_MAT_B + off);
                vl[2*nf2][0] = r4[0]; vl[2*nf2][1] = r4[1];
                vl[2*nf2+1][0] = r4[2]; vl[2*nf2+1][1] = r4[3];
            }
#pragma unroll
            for (int nf = 0; nf < 8; nf++) {
                MMA_BF16(O[nf], aph, vh[nf]);
                MMA_BF16(O[nf], apl, vh[nf]);
                MMA_BF16(O[nf], aph, vl[nf]);
            }
        }

        __syncthreads();
        if (kt + 2 < 16) {
#pragma unroll
            for (int it = 0; it < 8; it++) {
                int c = t + it * 256;
                int mat = c >> 9, r = (c >> 3) & 63, ck = c & 7;
                cp16(s_base + TILE_B + (uint32_t)(kt & 1) * BUF_B + mat * ATT_MAT_B +
                         (uint32_t)(r * AT_ST + ck * 8) * 2,
                     ksrc[mat] + hb + (size_t)((kt + 2) * 64 + r) * HD + ck * 8);
            }
            asm volatile("cp.async.commit_group;");
        }
        if (kt + 1 < 16) {
            if (kt + 2 < 16) asm volatile("cp.async.wait_group 1;");
            else             asm volatile("cp.async.wait_group 0;");
            __syncthreads();
        }
    }

    float i0 = 1.f / l0, i1 = 1.f / l1;
    int orow = b * SEQ + qbase + wid * 16 + (lane >> 2);
    uint32_t* oh = (uint32_t*)outh;
    uint32_t* ol = (uint32_t*)outl;
#pragma unroll
    for (int nf = 0; nf < 8; nf++) {
        int col = h * HD + nf * 8 + colb;
        float a0 = O[nf][0] * i0, a1 = O[nf][1] * i0;
        float b0 = O[nf][2] * i1, b1 = O[nf][3] * i1;
        uint32_t h0 = packbf(a0, a1);
        uint32_t l0r = residpack(h0, a0, a1);
        uint32_t h1 = packbf(b0, b1);
        uint32_t l1r = residpack(h1, b0, b1);
        size_t idx0 = ((size_t)orow * EMB + col) >> 1;
        size_t idx1 = ((size_t)(orow + 8) * EMB + col) >> 1;
        oh[idx0] = h0; ol[idx0] = l0r;
        oh[idx1] = h1; ol[idx1] = l1r;
    }
}

// ---------------------------------------------------------------------------
extern "C" void kernel_launch(void* const* d_in, const int* in_sizes, int n_in,
                              void* d_out, int out_size)
{
    const float* query         = (const float*)d_in[0];
    const unsigned char* maskp = (const unsigned char*)d_in[1];
    const float* attn_bias     = (const float*)d_in[2];
    const float* Wqkv          = (const float*)d_in[3];
    const float* bqkv          = (const float*)d_in[4];
    const float* Wo            = (const float*)d_in[5];
    const float* bo            = (const float*)d_in[6];
    float* out                 = (float*)d_out;

    __nv_bfloat16 *Ahi, *Alo, *W1hi, *W1lo, *W2hi, *W2lo, *Thi, *Tlo;
    __nv_bfloat16 *Qh, *Ql, *Kh, *Kl, *Vh, *Vl;
    cudaGetSymbolAddress((void**)&Ahi,  g_A_hi);
    cudaGetSymbolAddress((void**)&Alo,  g_A_lo);
    cudaGetSymbolAddress((void**)&W1hi, g_W1_hi);
    cudaGetSymbolAddress((void**)&W1lo, g_W1_lo);
    cudaGetSymbolAddress((void**)&W2hi, g_W2_hi);
    cudaGetSymbolAddress((void**)&W2lo, g_W2_lo);
    cudaGetSymbolAddress((void**)&Thi,  g_att_hi);
    cudaGetSymbolAddress((void**)&Tlo,  g_att_lo);
    cudaGetSymbolAddress((void**)&Qh,   g_Qh);
    cudaGetSymbolAddress((void**)&Ql,   g_Ql);
    cudaGetSymbolAddress((void**)&Kh,   g_Kh);
    cudaGetSymbolAddress((void**)&Kl,   g_Kl);
    cudaGetSymbolAddress((void**)&Vh,   g_Vh);
    cudaGetSymbolAddress((void**)&Vl,   g_Vl);

    cudaFuncSetAttribute(gemm_mma,
                         cudaFuncAttributeMaxDynamicSharedMemorySize, GEMM_SMEM);
    cudaFuncSetAttribute(attn_mma,
                         cudaFuncAttributeMaxDynamicSharedMemorySize, ATT_SMEM);

    // 0) split inputs + weights into bf16 (hi, lo)
    split_kernel<<<(MTOT * EMB) / 1024, 256>>>(query, Ahi, Alo, MTOT * EMB);
    split_kernel<<<(3 * EMB * EMB) / 1024, 256>>>(Wqkv, W1hi, W1lo, 3 * EMB * EMB);
    split_kernel<<<(EMB * EMB) / 1024, 256>>>(Wo, W2hi, W2lo, EMB * EMB);

    // 1) QKV projection, fused head-major bf16 hi/lo epilogue (Q pre-scaled)
    {
        dim3 grid(3 * EMB / 128, MTOT / 128);
        gemm_mma<<<grid, 128, GEMM_SMEM>>>(Ahi, Alo, W1hi, W1lo, bqkv,
                                           nullptr, Qh, Ql, Kh, Kl, Vh, Vl,
                                           MTOT, 3 * EMB, EMB, 1);
    }

    // 2) flash attention, writes bf16 hi/lo attention output
    {
        dim3 grid(SEQ / 128, NH, BATCH);
        attn_mma<<<grid, 256, ATT_SMEM>>>(attn_bias, maskp, Thi, Tlo,
                                          Qh, Ql, Kh, Kl, Vh, Vl);
    }

    // 3) output projection (f32 epilogue into d_out)
    {
        dim3 grid(EMB / 128, MTOT / 128);
        gemm_mma<<<grid, 128, GEMM_SMEM>>>(Thi, Tlo, W2hi, W2lo, bo,
                                           out, nullptr, nullptr, nullptr,
                                           nullptr, nullptr, nullptr,
                                           MTOT, EMB, EMB, 0);
    }
}

// round 12
// speedup vs baseline: 1.5708x; 1.0365x over previous
#include <cuda_runtime.h>
#include <cuda_bf16.h>
#include <cstdint>

// Problem constants
#define EMB   1024
#define NH    16
#define HD    64
#define BATCH 4
#define SEQ   1024
#define MTOT  (BATCH*SEQ)
#define SCALING 0.3952847075210474f   // (64*0.1)^-0.5
#define NEG   (-1e30f)

// Scratch (device globals)
__device__ __nv_bfloat16 g_A_hi[MTOT * EMB];
__device__ __nv_bfloat16 g_A_lo[MTOT * EMB];
__device__ __nv_bfloat16 g_W1_hi[3 * EMB * EMB];
__device__ __nv_bfloat16 g_W1_lo[3 * EMB * EMB];
__device__ __nv_bfloat16 g_W2_hi[EMB * EMB];
__device__ __nv_bfloat16 g_W2_lo[EMB * EMB];
__device__ __nv_bfloat16 g_att_hi[MTOT * EMB];
__device__ __nv_bfloat16 g_att_lo[MTOT * EMB];
__device__ __nv_bfloat16 g_Qh[MTOT * EMB];
__device__ __nv_bfloat16 g_Ql[MTOT * EMB];
__device__ __nv_bfloat16 g_Kh[MTOT * EMB];
__device__ __nv_bfloat16 g_Kl[MTOT * EMB];
__device__ __nv_bfloat16 g_Vh[MTOT * EMB];
__device__ __nv_bfloat16 g_Vl[MTOT * EMB];

// ---------------------------------------------------------------------------
// PTX helpers
// ---------------------------------------------------------------------------
#define LDSM4(r, addr) \
    asm volatile("ldmatrix.sync.aligned.m8n8.x4.shared.b16 {%0,%1,%2,%3}, [%4];" \
                 : "=r"((r)[0]), "=r"((r)[1]), "=r"((r)[2]), "=r"((r)[3]) : "r"(addr))

#define LDSM4T(r, addr) \
    asm volatile("ldmatrix.sync.aligned.m8n8.x4.trans.shared.b16 {%0,%1,%2,%3}, [%4];" \
                 : "=r"((r)[0]), "=r"((r)[1]), "=r"((r)[2]), "=r"((r)[3]) : "r"(addr))

#define MMA_BF16(d, a, b) \
    asm volatile("mma.sync.aligned.m16n8k16.row.col.f32.bf16.bf16.f32 " \
                 "{%0,%1,%2,%3},{%4,%5,%6,%7},{%8,%9},{%0,%1,%2,%3};" \
                 : "+f"((d)[0]), "+f"((d)[1]), "+f"((d)[2]), "+f"((d)[3]) \
                 : "r"((a)[0]), "r"((a)[1]), "r"((a)[2]), "r"((a)[3]), \
                   "r"((b)[0]), "r"((b)[1]))

__device__ __forceinline__ void cp16(uint32_t s, const void* g) {
    asm volatile("cp.async.cg.shared.global [%0], [%1], 16;" :: "r"(s), "l"(g));
}

__device__ __forceinline__ uint32_t packbf(float lo, float hi) {
    uint32_t r;
    asm("cvt.rn.bf16x2.f32 %0, %1, %2;" : "=r"(r) : "f"(hi), "f"(lo));
    return r;
}
__device__ __forceinline__ uint32_t residpack(uint32_t ph, float lo, float hi) {
    float h_lo = __uint_as_float(ph << 16);
    float h_hi = __uint_as_float(ph & 0xffff0000u);
    return packbf(lo - h_lo, hi - h_hi);
}

// ---------------------------------------------------------------------------
// f32 -> bf16 (hi, lo) split
// ---------------------------------------------------------------------------
__global__ __launch_bounds__(256)
void split_kernel(const float* __restrict__ in,
                  __nv_bfloat16* __restrict__ hi,
                  __nv_bfloat16* __restrict__ lo, int n)
{
    int i = (blockIdx.x * blockDim.x + threadIdx.x) * 4;
    if (i >= n) return;
    float4 v = *(const float4*)(in + i);
    float f[4] = {v.x, v.y, v.z, v.w};
    __nv_bfloat16 h[4], l[4];
#pragma unroll
    for (int j = 0; j < 4; j++) {
        h[j] = __float2bfloat16(f[j]);
        l[j] = __float2bfloat16(f[j] - __bfloat162float(h[j]));
    }
    *(uint2*)(hi + i) = *(const uint2*)h;
    *(uint2*)(lo + i) = *(const uint2*)l;
}

// ---------------------------------------------------------------------------
// Tensor-core GEMM (unchanged from R11): C[M,N] = A[M,K]*B[N,K]^T + bias[N].
// CTA 128x128, 128 threads (4 warps, 2m x 2n), warp tile 64x64, BK=32,
// 2-stage cp.async, 2 CTAs/SM.
// mode 0: f32 C.  mode 1: fused head-major bf16 hi/lo QKV epilogue (staged).
// ---------------------------------------------------------------------------
#define AST   40
#define MAT_H (128 * AST)
#define GEMM_SMEM (8 * MAT_H * 2)   // 81920 B
#define EP_ST 68

__global__ __launch_bounds__(128, 2)
void gemm_mma(const __nv_bfloat16* __restrict__ Ah,
              const __nv_bfloat16* __restrict__ Al,
              const __nv_bfloat16* __restrict__ Bh,
              const __nv_bfloat16* __restrict__ Bl,
              const float* __restrict__ bias,
              float* __restrict__ C,
              __nv_bfloat16* __restrict__ Qh, __nv_bfloat16* __restrict__ Ql,
              __nv_bfloat16* __restrict__ Kh, __nv_bfloat16* __restrict__ Kl,
              __nv_bfloat16* __restrict__ Vh, __nv_bfloat16* __restrict__ Vl,
              int M, int N, int K, int mode)
{
    extern __shared__ __align__(16) __nv_bfloat16 smem_b[];
    const uint32_t sm_base = (uint32_t)__cvta_generic_to_shared(smem_b);

    const int t    = threadIdx.x;
    const int lane = t & 31;
    const int w    = t >> 5;
    const int wm   = w & 1;
    const int wn   = w >> 1;
    const int bm   = blockIdx.y * 128;
    const int bn   = blockIdx.x * 128;
    const int nk   = K >> 5;

    float acc[4][8][4];
#pragma unroll
    for (int mi = 0; mi < 4; mi++)
#pragma unroll
        for (int ni = 0; ni < 8; ni++)
#pragma unroll
            for (int q = 0; q < 4; q++) acc[mi][ni][q] = 0.f;

    const __nv_bfloat16* gp[4] = {Ah, Al, Bh, Bl};

    auto issue = [&](int stage, int k0) {
#pragma unroll
        for (int i = 0; i < 16; i++) {
            int c = t + i * 128;
            int mat = c >> 9;
            int idx = c & 511;
            int row = idx >> 2, ck = (idx & 3) * 8;
            int base = (mat < 2) ? bm : bn;
            uint32_t so = sm_base + (uint32_t)(stage * 4 + mat) * MAT_H * 2;
            cp16(so + (uint32_t)(row * AST + ck) * 2,
                 gp[mat] + (size_t)(base + row) * K + k0 + ck);
        }
        asm volatile("cp.async.commit_group;");
    };

    issue(0, 0);
    issue(1, 32);

    for (int kt = 0; kt < nk; kt++) {
        if (kt + 1 < nk) asm volatile("cp.async.wait_group 1;");
        else             asm volatile("cp.async.wait_group 0;");
        __syncthreads();

        const int stage = kt & 1;
        const uint32_t bAh = sm_base + (uint32_t)(stage * 4 + 0) * MAT_H * 2;
        const uint32_t bAl = sm_base + (uint32_t)(stage * 4 + 1) * MAT_H * 2;
        const uint32_t bBh = sm_base + (uint32_t)(stage * 4 + 2) * MAT_H * 2;
        const uint32_t bBl = sm_base + (uint32_t)(stage * 4 + 3) * MAT_H * 2;

#pragma unroll
        for (int ks = 0; ks < 2; ks++) {
            uint32_t ah[4][4], al[4][4], bh[8][2], bl[8][2];

            const int arow = wm * 64 + (lane & 15);
            const int acol = ks * 16 + (lane >> 4) * 8;
#pragma unroll
            for (int mi = 0; mi < 4; mi++) {
                uint32_t off = (uint32_t)((arow + mi * 16) * AST + acol) * 2;
                LDSM4(ah[mi], bAh + off);
                LDSM4(al[mi], bAl + off);
            }

            const int brow = wn * 64 + (lane >> 4) * 8 + (lane & 7);
            const int bcol = ks * 16 + ((lane >> 3) & 1) * 8;
#pragma unroll
            for (int ni2 = 0; ni2 < 4; ni2++) {
                uint32_t off = (uint32_t)((brow + ni2 * 16) * AST + bcol) * 2;
                uint32_t r[4];
                LDSM4(r, bBh + off);
                bh[ni2 * 2][0] = r[0]; bh[ni2 * 2][1] = r[1];
                bh[ni2 * 2 + 1][0] = r[2]; bh[ni2 * 2 + 1][1] = r[3];
                LDSM4(r, bBl + off);
                bl[ni2 * 2][0] = r[0]; bl[ni2 * 2][1] = r[1];
                bl[ni2 * 2 + 1][0] = r[2]; bl[ni2 * 2 + 1][1] = r[3];
            }

#pragma unroll
            for (int mi = 0; mi < 4; mi++)
#pragma unroll
                for (int ni = 0; ni < 8; ni++) {
                    MMA_BF16(acc[mi][ni], ah[mi], bh[ni]);
                    MMA_BF16(acc[mi][ni], al[mi], bh[ni]);
                    MMA_BF16(acc[mi][ni], ah[mi], bl[ni]);
                }
        }
        __syncthreads();

        if (kt + 2 < nk) issue(kt & 1, (kt + 2) << 5);
    }

    if (mode == 0) {
#pragma unroll
        for (int mi = 0; mi < 4; mi++) {
            const int r0 = bm + wm * 64 + mi * 16 + (lane >> 2);
#pragma unroll
            for (int ni = 0; ni < 8; ni++) {
                const int col = bn + wn * 64 + ni * 8 + (lane & 3) * 2;
                float bx = bias[col], by = bias[col + 1];
                float2 v0 = make_float2(acc[mi][ni][0] + bx, acc[mi][ni][1] + by);
                float2 v1 = make_float2(acc[mi][ni][2] + bx, acc[mi][ni][3] + by);
                *(float2*)&C[(size_t)r0 * N + col] = v0;
                *(float2*)&C[(size_t)(r0 + 8) * N + col] = v1;
            }
        }
    } else {
        // fused qkv-split epilogue, smem-staged for coalesced stores
        __syncthreads();
        uint32_t* sh = (uint32_t*)smem_b;
        uint32_t* sl = sh + 128 * EP_ST;
        const int m = bn >> 10;
        const float sc = (m == 0) ? SCALING : 1.0f;

#pragma unroll
        for (int mi = 0; mi < 4; mi++) {
            const int lr0 = wm * 64 + mi * 16 + (lane >> 2);
#pragma unroll
            for (int ni = 0; ni < 8; ni++) {
                const int lcol = wn * 64 + ni * 8 + (lane & 3) * 2;
                const int colu = lcol >> 1;
                float bx = bias[bn + lcol], by = bias[bn + lcol + 1];
                float a0 = (acc[mi][ni][0] + bx) * sc;
                float a1 = (acc[mi][ni][1] + by) * sc;
                float b0 = (acc[mi][ni][2] + bx) * sc;
                float b1 = (acc[mi][ni][3] + by) * sc;
                uint32_t hp0 = packbf(a0, a1);
                uint32_t hp1 = packbf(b0, b1);
                sh[lr0 * EP_ST + colu] = hp0;
                sl[lr0 * EP_ST + colu] = residpack(hp0, a0, a1);
                sh[(lr0 + 8) * EP_ST + colu] = hp1;
                sl[(lr0 + 8) * EP_ST + colu] = residpack(hp1, b0, b1);
            }
        }
        __syncthreads();

        uint32_t* oh = (uint32_t*)((m == 0) ? Qh : (m == 1) ? Kh : Vh);
        uint32_t* ol = (uint32_t*)((m == 0) ? Ql : (m == 1) ? Kl : Vl);
        const int hh0 = (bn >> 6) & 15;
        const int bb = bm >> 10, s0 = bm & 1023;

#pragma unroll
        for (int i = 0; i < 16; i++) {
            int c = t + i * 128;
            int row = c >> 4, sub = c & 15;
            int j = sub >> 3, q4 = (sub & 7) * 4;
            size_t g = (((size_t)(bb * NH + hh0 + j)) * SEQ + s0 + row) * 32 + q4;
            uint4 vh = *(uint4*)&sh[row * EP_ST + j * 32 + q4];
            uint4 vl = *(uint4*)&sl[row * EP_ST + j * 32 + q4];
            *(uint4*)&oh[g] = vh;
            *(uint4*)&ol[g] = vl;
        }
    }
}

// ---------------------------------------------------------------------------
// Tensor-core flash attention. BR=64 q-rows, 128 threads (4 warps x 16 rows),
// smem 92160 B -> 2 CTAs/SM for cross-CTA softmax/MMA overlap.
// ---------------------------------------------------------------------------
#define AT_ST 72
#define Q_HI_B 0
#define Q_LO_B 9216            // 64*72*2
#define TILE_B 18432           // Q total
#define ATT_MAT_B  9216        // 64*72*2 per matrix
#define BUF_B  36864           // 4 matrices per K/V buffer
#define ATT_SMEM (TILE_B + 2 * BUF_B)   // 92160

__global__ __launch_bounds__(128)
void attn_mma(const float* __restrict__ bias, const unsigned char* __restrict__ mask,
              __nv_bfloat16* __restrict__ outh, __nv_bfloat16* __restrict__ outl,
              const __nv_bfloat16* __restrict__ Qh, const __nv_bfloat16* __restrict__ Ql,
              const __nv_bfloat16* __restrict__ Kh, const __nv_bfloat16* __restrict__ Kl,
              const __nv_bfloat16* __restrict__ Vh, const __nv_bfloat16* __restrict__ Vl)
{
    extern __shared__ __align__(16) __nv_bfloat16 smA[];
    const uint32_t s_base = (uint32_t)__cvta_generic_to_shared(smA);

    const int t = threadIdx.x, lane = t & 31, wid = t >> 5;
    const int qt = blockIdx.x, h = blockIdx.y, b = blockIdx.z;
    const int qbase = qt * 64;
    const size_t hb = (size_t)(b * NH + h) * SEQ * HD;

    const int lr7 = lane & 7, l8 = (lane >> 3) & 1, l16 = lane >> 4;

    const __nv_bfloat16* qsrc[2] = {Qh, Ql};
    const __nv_bfloat16* ksrc[4] = {Kh, Kl, Vh, Vl};

    // Q tile: 2 mats x 64 rows x 8 chunks = 1024 chunks over 128 threads
#pragma unroll
    for (int it = 0; it < 8; it++) {
        int c = t + it * 128;
        int mat = c >> 9, r = (c >> 3) & 63, ck = c & 7;
        cp16(s_base + mat * Q_LO_B + (uint32_t)(r * AT_ST + ck * 8) * 2,
             qsrc[mat] + hb + (size_t)(qbase + r) * HD + ck * 8);
    }
    // K/V tile 0: 4 mats x 64 x 8 = 2048 chunks
#pragma unroll
    for (int it = 0; it < 16; it++) {
        int c = t + it * 128;
        int mat = c >> 9, r = (c >> 3) & 63, ck = c & 7;
        cp16(s_base + TILE_B + mat * ATT_MAT_B + (uint32_t)(r * AT_ST + ck * 8) * 2,
             ksrc[mat] + hb + (size_t)r * HD + ck * 8);
    }
    asm volatile("cp.async.commit_group;");
    // K/V tile 1
#pragma unroll
    for (int it = 0; it < 16; it++) {
        int c = t + it * 128;
        int mat = c >> 9, r = (c >> 3) & 63, ck = c & 7;
        cp16(s_base + TILE_B + BUF_B + mat * ATT_MAT_B + (uint32_t)(r * AT_ST + ck * 8) * 2,
             ksrc[mat] + hb + (size_t)(64 + r) * HD + ck * 8);
    }
    asm volatile("cp.async.commit_group;");
    asm volatile("cp.async.wait_group 1;");
    __syncthreads();

    uint32_t aqh[4][4], aql[4][4];
    {
        const int arow = wid * 16 + (lane & 15);
        const int acol = 8 * l16;
#pragma unroll
        for (int ks = 0; ks < 4; ks++) {
            uint32_t off = (uint32_t)(arow * AT_ST + ks * 16 + acol) * 2;
            LDSM4(aqh[ks], s_base + Q_HI_B + off);
            LDSM4(aql[ks], s_base + Q_LO_B + off);
        }
    }

    float O[8][4];
#pragma unroll
    for (int nf = 0; nf < 8; nf++)
#pragma unroll
        for (int q = 0; q < 4; q++) O[nf][q] = 0.f;
    float m0 = NEG, m1 = NEG, l0 = 0.f, l1 = 0.f;

    const float* bp = bias + (size_t)(b * NH + h) * SEQ * SEQ;
    const unsigned char* mrow = mask + (size_t)b * SEQ;
    const int qr = qbase + wid * 16 + (lane >> 2);
    const int colb = 2 * (lane & 3);

    const int krow = lr7 + 8 * l16;
    const int kcol = 8 * l8;
    const int vrow = lr7 + 8 * l8;
    const int vcol = 8 * l16;

    for (int kt = 0; kt < 16; kt++) {
        const uint32_t tb = s_base + TILE_B + (uint32_t)(kt & 1) * BUF_B;

        float2 bv0[8], bv1[8];
        uchar2 mk[8];
#pragma unroll
        for (int nf = 0; nf < 8; nf++) {
            int col = kt * 64 + nf * 8 + colb;
            bv0[nf] = *(const float2*)&bp[(size_t)qr * SEQ + col];
            bv1[nf] = *(const float2*)&bp[(size_t)(qr + 8) * SEQ + col];
            mk[nf]  = *(const uchar2*)&mrow[col];
        }

        float s[8][4];
#pragma unroll
        for (int nf = 0; nf < 8; nf++)
#pragma unroll
            for (int q = 0; q < 4; q++) s[nf][q] = 0.f;

#pragma unroll
        for (int ks = 0; ks < 4; ks++) {
            uint32_t bh[8][2], bl[8][2];
#pragma unroll
            for (int nf2 = 0; nf2 < 4; nf2++) {
                uint32_t off = (uint32_t)((nf2 * 16 + krow) * AT_ST + ks * 16 + kcol) * 2;
                uint32_t r4[4];
                LDSM4(r4, tb + 0 * ATT_MAT_B + off);
                bh[2*nf2][0] = r4[0]; bh[2*nf2][1] = r4[1];
                bh[2*nf2+1][0] = r4[2]; bh[2*nf2+1][1] = r4[3];
                LDSM4(r4, tb + 1 * ATT_MAT_B + off);
                bl[2*nf2][0] = r4[0]; bl[2*nf2][1] = r4[1];
                bl[2*nf2+1][0] = r4[2]; bl[2*nf2+1][1] = r4[3];
            }
#pragma unroll
            for (int nf = 0; nf < 8; nf++) {
                MMA_BF16(s[nf], aqh[ks], bh[nf]);
                MMA_BF16(s[nf], aql[ks], bh[nf]);
                MMA_BF16(s[nf], aqh[ks], bl[nf]);
            }
        }

#pragma unroll
        for (int nf = 0; nf < 8; nf++) {
            s[nf][0] = mk[nf].x ? NEG : s[nf][0] + bv0[nf].x;
            s[nf][1] = mk[nf].y ? NEG : s[nf][1] + bv0[nf].y;
            s[nf][2] = mk[nf].x ? NEG : s[nf][2] + bv1[nf].x;
            s[nf][3] = mk[nf].y ? NEG : s[nf][3] + bv1[nf].y;
        }

        float mx0 = NEG, mx1 = NEG;
#pragma unroll
        for (int nf = 0; nf < 8; nf++) {
            mx0 = fmaxf(mx0, fmaxf(s[nf][0], s[nf][1]));
            mx1 = fmaxf(mx1, fmaxf(s[nf][2], s[nf][3]));
        }
        mx0 = fmaxf(mx0, __shfl_xor_sync(0xffffffffu, mx0, 1));
        mx0 = fmaxf(mx0, __shfl_xor_sync(0xffffffffu, mx0, 2));
        mx1 = fmaxf(mx1, __shfl_xor_sync(0xffffffffu, mx1, 1));
        mx1 = fmaxf(mx1, __shfl_xor_sync(0xffffffffu, mx1, 2));
        float mn0 = fmaxf(m0, mx0), mn1 = fmaxf(m1, mx1);
        float sc0 = __expf(m0 - mn0), sc1 = __expf(m1 - mn1);
        m0 = mn0; m1 = mn1;
        float su0 = 0.f, su1 = 0.f;
#pragma unroll
        for (int nf = 0; nf < 8; nf++) {
            s[nf][0] = __expf(s[nf][0] - mn0);
            s[nf][1] = __expf(s[nf][1] - mn0);
            s[nf][2] = __expf(s[nf][2] - mn1);
            s[nf][3] = __expf(s[nf][3] - mn1);
            su0 += s[nf][0] + s[nf][1];
            su1 += s[nf][2] + s[nf][3];
        }
        su0 += __shfl_xor_sync(0xffffffffu, su0, 1);
        su0 += __shfl_xor_sync(0xffffffffu, su0, 2);
        su1 += __shfl_xor_sync(0xffffffffu, su1, 1);
        su1 += __shfl_xor_sync(0xffffffffu, su1, 2);
        l0 = l0 * sc0 + su0;
        l1 = l1 * sc1 + su1;
#pragma unroll
        for (int nf = 0; nf < 8; nf++) {
            O[nf][0] *= sc0; O[nf][1] *= sc0;
            O[nf][2] *= sc1; O[nf][3] *= sc1;
        }

#pragma unroll
        for (int ks = 0; ks < 4; ks++) {
            uint32_t aph[4], apl[4];
            {
                const float* p0 = s[2 * ks];
                const float* p1 = s[2 * ks + 1];
                aph[0] = packbf(p0[0], p0[1]);
                aph[1] = packbf(p0[2], p0[3]);
                aph[2] = packbf(p1[0], p1[1]);
                aph[3] = packbf(p1[2], p1[3]);
                apl[0] = residpack(aph[0], p0[0], p0[1]);
                apl[1] = residpack(aph[1], p0[2], p0[3]);
                apl[2] = residpack(aph[2], p1[0], p1[1]);
                apl[3] = residpack(aph[3], p1[2], p1[3]);
            }
            uint32_t vh[8][2], vl[8][2];
#pragma unroll
            for (int nf2 = 0; nf2 < 4; nf2++) {
                uint32_t off = (uint32_t)((ks * 16 + vrow) * AT_ST + nf2 * 16 + vcol) * 2;
                uint32_t r4[4];
                LDSM4T(r4, tb + 2 * ATT_MAT_B + off);
                vh[2*nf2][0] = r4[0]; vh[2*nf2][1] = r4[1];
                vh[2*nf2+1][0] = r4[2]; vh[2*nf2+1][1] = r4[3];
                LDSM4T(r4, tb + 3 * ATT_MAT_B + off);
                vl[2*nf2][0] = r4[0]; vl[2*nf2][1] = r4[1];
                vl[2*nf2+1][0] = r4[2]; vl[2*nf2+1][1] = r4[3];
            }
#pragma unroll
            for (int nf = 0; nf < 8; nf++) {
                MMA_BF16(O[nf], aph, vh[nf]);
                MMA_BF16(O[nf], apl, vh[nf]);
                MMA_BF16(O[nf], aph, vl[nf]);
            }
        }

        __syncthreads();
        if (kt + 2 < 16) {
#pragma unroll
            for (int it = 0; it < 16; it++) {
                int c = t + it * 128;
                int mat = c >> 9, r = (c >> 3) & 63, ck = c & 7;
                cp16(s_base + TILE_B + (uint32_t)(kt & 1) * BUF_B + mat * ATT_MAT_B +
                         (uint32_t)(r * AT_ST + ck * 8) * 2,
                     ksrc[mat] + hb + (size_t)((kt + 2) * 64 + r) * HD + ck * 8);
            }
            asm volatile("cp.async.commit_group;");
        }
        if (kt + 1 < 16) {
            if (kt + 2 < 16) asm volatile("cp.async.wait_group 1;");
            else             asm volatile("cp.async.wait_group 0;");
            __syncthreads();
        }
    }

    float i0 = 1.f / l0, i1 = 1.f / l1;
    int orow = b * SEQ + qbase + wid * 16 + (lane >> 2);
    uint32_t* oh = (uint32_t*)outh;
    uint32_t* ol = (uint32_t*)outl;
#pragma unroll
    for (int nf = 0; nf < 8; nf++) {
        int col = h * HD + nf * 8 + colb;
        float a0 = O[nf][0] * i0, a1 = O[nf][1] * i0;
        float b0 = O[nf][2] * i1, b1 = O[nf][3] * i1;
        uint32_t h0 = packbf(a0, a1);
        uint32_t l0r = residpack(h0, a0, a1);
        uint32_t h1 = packbf(b0, b1);
        uint32_t l1r = residpack(h1, b0, b1);
        size_t idx0 = ((size_t)orow * EMB + col) >> 1;
        size_t idx1 = ((size_t)(orow + 8) * EMB + col) >> 1;
        oh[idx0] = h0; ol[idx0] = l0r;
        oh[idx1] = h1; ol[idx1] = l1r;
    }
}

// ---------------------------------------------------------------------------
extern "C" void kernel_launch(void* const* d_in, const int* in_sizes, int n_in,
                              void* d_out, int out_size)
{
    const float* query         = (const float*)d_in[0];
    const unsigned char* maskp = (const unsigned char*)d_in[1];
    const float* attn_bias     = (const float*)d_in[2];
    const float* Wqkv          = (const float*)d_in[3];
    const float* bqkv          = (const float*)d_in[4];
    const float* Wo            = (const float*)d_in[5];
    const float* bo            = (const float*)d_in[6];
    float* out                 = (float*)d_out;

    __nv_bfloat16 *Ahi, *Alo, *W1hi, *W1lo, *W2hi, *W2lo, *Thi, *Tlo;
    __nv_bfloat16 *Qh, *Ql, *Kh, *Kl, *Vh, *Vl;
    cudaGetSymbolAddress((void**)&Ahi,  g_A_hi);
    cudaGetSymbolAddress((void**)&Alo,  g_A_lo);
    cudaGetSymbolAddress((void**)&W1hi, g_W1_hi);
    cudaGetSymbolAddress((void**)&W1lo, g_W1_lo);
    cudaGetSymbolAddress((void**)&W2hi, g_W2_hi);
    cudaGetSymbolAddress((void**)&W2lo, g_W2_lo);
    cudaGetSymbolAddress((void**)&Thi,  g_att_hi);
    cudaGetSymbolAddress((void**)&Tlo,  g_att_lo);
    cudaGetSymbolAddress((void**)&Qh,   g_Qh);
    cudaGetSymbolAddress((void**)&Ql,   g_Ql);
    cudaGetSymbolAddress((void**)&Kh,   g_Kh);
    cudaGetSymbolAddress((void**)&Kl,   g_Kl);
    cudaGetSymbolAddress((void**)&Vh,   g_Vh);
    cudaGetSymbolAddress((void**)&Vl,   g_Vl);

    cudaFuncSetAttribute(gemm_mma,
                         cudaFuncAttributeMaxDynamicSharedMemorySize, GEMM_SMEM);
    cudaFuncSetAttribute(attn_mma,
                         cudaFuncAttributeMaxDynamicSharedMemorySize, ATT_SMEM);

    // 0) split inputs + weights into bf16 (hi, lo)
    split_kernel<<<(MTOT * EMB) / 1024, 256>>>(query, Ahi, Alo, MTOT * EMB);
    split_kernel<<<(3 * EMB * EMB) / 1024, 256>>>(Wqkv, W1hi, W1lo, 3 * EMB * EMB);
    split_kernel<<<(EMB * EMB) / 1024, 256>>>(Wo, W2hi, W2lo, EMB * EMB);

    // 1) QKV projection, fused head-major bf16 hi/lo epilogue (Q pre-scaled)
    {
        dim3 grid(3 * EMB / 128, MTOT / 128);
        gemm_mma<<<grid, 128, GEMM_SMEM>>>(Ahi, Alo, W1hi, W1lo, bqkv,
                                           nullptr, Qh, Ql, Kh, Kl, Vh, Vl,
                                           MTOT, 3 * EMB, EMB, 1);
    }

    // 2) flash attention (BR=64, 2 CTAs/SM), writes bf16 hi/lo attention output
    {
        dim3 grid(SEQ / 64, NH, BATCH);
        attn_mma<<<grid, 128, ATT_SMEM>>>(attn_bias, maskp, Thi, Tlo,
                                          Qh, Ql, Kh, Kl, Vh, Vl);
    }

    // 3) output projection (f32 epilogue into d_out)
    {
        dim3 grid(EMB / 128, MTOT / 128);
        gemm_mma<<<grid, 128, GEMM_SMEM>>>(Thi, Tlo, W2hi, W2lo, bo,
                                           out, nullptr, nullptr, nullptr,
                                           nullptr, nullptr, nullptr,
                                           MTOT, EMB, EMB, 0);
    }
}

// round 13
// speedup vs baseline: 1.6289x; 1.0370x over previous
#include <cuda_runtime.h>
#include <cuda_bf16.h>
#include <cstdint>

// Problem constants
#define EMB   1024
#define NH    16
#define HD    64
#define BATCH 4
#define SEQ   1024
#define MTOT  (BATCH*SEQ)
#define SCALING 0.3952847075210474f   // (64*0.1)^-0.5
#define NEG   (-1e30f)

#define NQ_ELEM  (MTOT * EMB)        // 4194304
#define NW1_ELEM (3 * EMB * EMB)     // 3145728
#define NW2_ELEM (EMB * EMB)         // 1048576
#define NSPLIT   (NQ_ELEM + NW1_ELEM + NW2_ELEM)

// Scratch (device globals)
__device__ __nv_bfloat16 g_A_hi[MTOT * EMB];
__device__ __nv_bfloat16 g_A_lo[MTOT * EMB];
__device__ __nv_bfloat16 g_W1_hi[3 * EMB * EMB];
__device__ __nv_bfloat16 g_W1_lo[3 * EMB * EMB];
__device__ __nv_bfloat16 g_W2_hi[EMB * EMB];
__device__ __nv_bfloat16 g_W2_lo[EMB * EMB];
__device__ __nv_bfloat16 g_att_hi[MTOT * EMB];
__device__ __nv_bfloat16 g_att_lo[MTOT * EMB];
__device__ __nv_bfloat16 g_Qh[MTOT * EMB];
__device__ __nv_bfloat16 g_Ql[MTOT * EMB];
__device__ __nv_bfloat16 g_Kh[MTOT * EMB];
__device__ __nv_bfloat16 g_Kl[MTOT * EMB];
__device__ __nv_bfloat16 g_Vh[MTOT * EMB];
__device__ __nv_bfloat16 g_Vl[MTOT * EMB];

// ---------------------------------------------------------------------------
// PTX helpers
// ---------------------------------------------------------------------------
#define LDSM4(r, addr) \
    asm volatile("ldmatrix.sync.aligned.m8n8.x4.shared.b16 {%0,%1,%2,%3}, [%4];" \
                 : "=r"((r)[0]), "=r"((r)[1]), "=r"((r)[2]), "=r"((r)[3]) : "r"(addr))

#define LDSM4T(r, addr) \
    asm volatile("ldmatrix.sync.aligned.m8n8.x4.trans.shared.b16 {%0,%1,%2,%3}, [%4];" \
                 : "=r"((r)[0]), "=r"((r)[1]), "=r"((r)[2]), "=r"((r)[3]) : "r"(addr))

#define MMA_BF16(d, a, b) \
    asm volatile("mma.sync.aligned.m16n8k16.row.col.f32.bf16.bf16.f32 " \
                 "{%0,%1,%2,%3},{%4,%5,%6,%7},{%8,%9},{%0,%1,%2,%3};" \
                 : "+f"((d)[0]), "+f"((d)[1]), "+f"((d)[2]), "+f"((d)[3]) \
                 : "r"((a)[0]), "r"((a)[1]), "r"((a)[2]), "r"((a)[3]), \
                   "r"((b)[0]), "r"((b)[1]))

__device__ __forceinline__ void cp16(uint32_t s, const void* g) {
    asm volatile("cp.async.cg.shared.global [%0], [%1], 16;" :: "r"(s), "l"(g));
}

__device__ __forceinline__ uint32_t packbf(float lo, float hi) {
    uint32_t r;
    asm("cvt.rn.bf16x2.f32 %0, %1, %2;" : "=r"(r) : "f"(hi), "f"(lo));
    return r;
}
__device__ __forceinline__ uint32_t residpack(uint32_t ph, float lo, float hi) {
    float h_lo = __uint_as_float(ph << 16);
    float h_hi = __uint_as_float(ph & 0xffff0000u);
    return packbf(lo - h_lo, hi - h_hi);
}

// ---------------------------------------------------------------------------
// merged f32 -> bf16 (hi, lo) split for query + Wqkv + Wo (one launch)
// ---------------------------------------------------------------------------
__global__ __launch_bounds__(256)
void split_all(const float* __restrict__ q, const float* __restrict__ w1,
               const float* __restrict__ w2,
               __nv_bfloat16* __restrict__ Ahi, __nv_bfloat16* __restrict__ Alo,
               __nv_bfloat16* __restrict__ W1hi, __nv_bfloat16* __restrict__ W1lo,
               __nv_bfloat16* __restrict__ W2hi, __nv_bfloat16* __restrict__ W2lo)
{
    int i = (blockIdx.x * 256 + threadIdx.x) * 4;
    const float* src;
    __nv_bfloat16 *hi, *lo;
    int off;
    if (i < NQ_ELEM)                { src = q;  hi = Ahi;  lo = Alo;  off = i; }
    else if (i < NQ_ELEM + NW1_ELEM){ src = w1; hi = W1hi; lo = W1lo; off = i - NQ_ELEM; }
    else                            { src = w2; hi = W2hi; lo = W2lo; off = i - NQ_ELEM - NW1_ELEM; }

    float4 v = *(const float4*)(src + off);
    float f[4] = {v.x, v.y, v.z, v.w};
    __nv_bfloat16 h[4], l[4];
#pragma unroll
    for (int j = 0; j < 4; j++) {
        h[j] = __float2bfloat16(f[j]);
        l[j] = __float2bfloat16(f[j] - __bfloat162float(h[j]));
    }
    *(uint2*)(hi + off) = *(const uint2*)h;
    *(uint2*)(lo + off) = *(const uint2*)l;
}

// ---------------------------------------------------------------------------
// Tensor-core GEMM: C[M,N] = A[M,K]*B[N,K]^T + bias[N].
// CTA 128x128, 128 threads (4 warps, 2m x 2n), warp tile 64x64, BK=32,
// 2-stage cp.async, 2 CTAs/SM, ONE __syncthreads per k-iter.
// mode 0: f32 C.  mode 1: fused head-major bf16 hi/lo QKV epilogue (staged).
// ---------------------------------------------------------------------------
#define AST   40
#define MAT_H (128 * AST)
#define GEMM_SMEM (8 * MAT_H * 2)   // 81920 B
#define EP_ST 68

__global__ __launch_bounds__(128, 2)
void gemm_mma(const __nv_bfloat16* __restrict__ Ah,
              const __nv_bfloat16* __restrict__ Al,
              const __nv_bfloat16* __restrict__ Bh,
              const __nv_bfloat16* __restrict__ Bl,
              const float* __restrict__ bias,
              float* __restrict__ C,
              __nv_bfloat16* __restrict__ Qh, __nv_bfloat16* __restrict__ Ql,
              __nv_bfloat16* __restrict__ Kh, __nv_bfloat16* __restrict__ Kl,
              __nv_bfloat16* __restrict__ Vh, __nv_bfloat16* __restrict__ Vl,
              int M, int N, int K, int mode)
{
    extern __shared__ __align__(16) __nv_bfloat16 smem_b[];
    const uint32_t sm_base = (uint32_t)__cvta_generic_to_shared(smem_b);

    const int t    = threadIdx.x;
    const int lane = t & 31;
    const int w    = t >> 5;
    const int wm   = w & 1;
    const int wn   = w >> 1;
    const int bm   = blockIdx.y * 128;
    const int bn   = blockIdx.x * 128;
    const int nk   = K >> 5;

    float acc[4][8][4];
#pragma unroll
    for (int mi = 0; mi < 4; mi++)
#pragma unroll
        for (int ni = 0; ni < 8; ni++)
#pragma unroll
            for (int q = 0; q < 4; q++) acc[mi][ni][q] = 0.f;

    const __nv_bfloat16* gp[4] = {Ah, Al, Bh, Bl};

    auto issue = [&](int stage, int k0) {
#pragma unroll
        for (int i = 0; i < 16; i++) {
            int c = t + i * 128;
            int mat = c >> 9;
            int idx = c & 511;
            int row = idx >> 2, ck = (idx & 3) * 8;
            int base = (mat < 2) ? bm : bn;
            uint32_t so = sm_base + (uint32_t)(stage * 4 + mat) * MAT_H * 2;
            cp16(so + (uint32_t)(row * AST + ck) * 2,
                 gp[mat] + (size_t)(base + row) * K + k0 + ck);
        }
        asm volatile("cp.async.commit_group;");
    };

    issue(0, 0);
    issue(1, 32);
    asm volatile("cp.async.wait_group 1;");   // stage 0 ready
    __syncthreads();

    for (int kt = 0; kt < nk; kt++) {
        const int stage = kt & 1;
        const uint32_t bAh = sm_base + (uint32_t)(stage * 4 + 0) * MAT_H * 2;
        const uint32_t bAl = sm_base + (uint32_t)(stage * 4 + 1) * MAT_H * 2;
        const uint32_t bBh = sm_base + (uint32_t)(stage * 4 + 2) * MAT_H * 2;
        const uint32_t bBl = sm_base + (uint32_t)(stage * 4 + 3) * MAT_H * 2;

#pragma unroll
        for (int ks = 0; ks < 2; ks++) {
            uint32_t ah[4][4], al[4][4], bh[8][2], bl[8][2];

            const int arow = wm * 64 + (lane & 15);
            const int acol = ks * 16 + (lane >> 4) * 8;
#pragma unroll
            for (int mi = 0; mi < 4; mi++) {
                uint32_t off = (uint32_t)((arow + mi * 16) * AST + acol) * 2;
                LDSM4(ah[mi], bAh + off);
                LDSM4(al[mi], bAl + off);
            }

            const int brow = wn * 64 + (lane >> 4) * 8 + (lane & 7);
            const int bcol = ks * 16 + ((lane >> 3) & 1) * 8;
#pragma unroll
            for (int ni2 = 0; ni2 < 4; ni2++) {
                uint32_t off = (uint32_t)((brow + ni2 * 16) * AST + bcol) * 2;
                uint32_t r[4];
                LDSM4(r, bBh + off);
                bh[ni2 * 2][0] = r[0]; bh[ni2 * 2][1] = r[1];
                bh[ni2 * 2 + 1][0] = r[2]; bh[ni2 * 2 + 1][1] = r[3];
                LDSM4(r, bBl + off);
                bl[ni2 * 2][0] = r[0]; bl[ni2 * 2][1] = r[1];
                bl[ni2 * 2 + 1][0] = r[2]; bl[ni2 * 2 + 1][1] = r[3];
            }

#pragma unroll
            for (int mi = 0; mi < 4; mi++)
#pragma unroll
                for (int ni = 0; ni < 8; ni++) {
                    MMA_BF16(acc[mi][ni], ah[mi], bh[ni]);
                    MMA_BF16(acc[mi][ni], al[mi], bh[ni]);
                    MMA_BF16(acc[mi][ni], ah[mi], bl[ni]);
                }
        }

        // single barrier: everyone's next-stage cp.asyncs complete AND
        // everyone done reading this stage; then refill this stage.
        asm volatile("cp.async.wait_group 0;");
        __syncthreads();
        if (kt + 2 < nk) issue(kt & 1, (kt + 2) << 5);
    }

    if (mode == 0) {
#pragma unroll
        for (int mi = 0; mi < 4; mi++) {
            const int r0 = bm + wm * 64 + mi * 16 + (lane >> 2);
#pragma unroll
            for (int ni = 0; ni < 8; ni++) {
                const int col = bn + wn * 64 + ni * 8 + (lane & 3) * 2;
                float bx = bias[col], by = bias[col + 1];
                float2 v0 = make_float2(acc[mi][ni][0] + bx, acc[mi][ni][1] + by);
                float2 v1 = make_float2(acc[mi][ni][2] + bx, acc[mi][ni][3] + by);
                *(float2*)&C[(size_t)r0 * N + col] = v0;
                *(float2*)&C[(size_t)(r0 + 8) * N + col] = v1;
            }
        }
    } else {
        // fused qkv-split epilogue, smem-staged for coalesced stores
        uint32_t* sh = (uint32_t*)smem_b;
        uint32_t* sl = sh + 128 * EP_ST;
        const int m = bn >> 10;
        const float sc = (m == 0) ? SCALING : 1.0f;

#pragma unroll
        for (int mi = 0; mi < 4; mi++) {
            const int lr0 = wm * 64 + mi * 16 + (lane >> 2);
#pragma unroll
            for (int ni = 0; ni < 8; ni++) {
                const int lcol = wn * 64 + ni * 8 + (lane & 3) * 2;
                const int colu = lcol >> 1;
                float bx = bias[bn + lcol], by = bias[bn + lcol + 1];
                float a0 = (acc[mi][ni][0] + bx) * sc;
                float a1 = (acc[mi][ni][1] + by) * sc;
                float b0 = (acc[mi][ni][2] + bx) * sc;
                float b1 = (acc[mi][ni][3] + by) * sc;
                uint32_t hp0 = packbf(a0, a1);
                uint32_t hp1 = packbf(b0, b1);
                sh[lr0 * EP_ST + colu] = hp0;
                sl[lr0 * EP_ST + colu] = residpack(hp0, a0, a1);
                sh[(lr0 + 8) * EP_ST + colu] = hp1;
                sl[(lr0 + 8) * EP_ST + colu] = residpack(hp1, b0, b1);
            }
        }
        __syncthreads();

        uint32_t* oh = (uint32_t*)((m == 0) ? Qh : (m == 1) ? Kh : Vh);
        uint32_t* ol = (uint32_t*)((m == 0) ? Ql : (m == 1) ? Kl : Vl);
        const int hh0 = (bn >> 6) & 15;
        const int bb = bm >> 10, s0 = bm & 1023;

#pragma unroll
        for (int i = 0; i < 16; i++) {
            int c = t + i * 128;
            int row = c >> 4, sub = c & 15;
            int j = sub >> 3, q4 = (sub & 7) * 4;
            size_t g = (((size_t)(bb * NH + hh0 + j)) * SEQ + s0 + row) * 32 + q4;
            uint4 vh = *(uint4*)&sh[row * EP_ST + j * 32 + q4];
            uint4 vl = *(uint4*)&sl[row * EP_ST + j * 32 + q4];
            *(uint4*)&oh[g] = vh;
            *(uint4*)&ol[g] = vl;
        }
    }
}

// ---------------------------------------------------------------------------
// Tensor-core flash attention. BR=64 q-rows, 128 threads (4 warps x 16 rows),
// smem 92160 B -> 2 CTAs/SM; ONE __syncthreads per kv-tile.
// ---------------------------------------------------------------------------
#define AT_ST 72
#define Q_HI_B 0
#define Q_LO_B 9216
#define TILE_B 18432
#define ATT_MAT_B  9216
#define BUF_B  36864
#define ATT_SMEM (TILE_B + 2 * BUF_B)   // 92160

__global__ __launch_bounds__(128)
void attn_mma(const float* __restrict__ bias, const unsigned char* __restrict__ mask,
              __nv_bfloat16* __restrict__ outh, __nv_bfloat16* __restrict__ outl,
              const __nv_bfloat16* __restrict__ Qh, const __nv_bfloat16* __restrict__ Ql,
              const __nv_bfloat16* __restrict__ Kh, const __nv_bfloat16* __restrict__ Kl,
              const __nv_bfloat16* __restrict__ Vh, const __nv_bfloat16* __restrict__ Vl)
{
    extern __shared__ __align__(16) __nv_bfloat16 smA[];
    const uint32_t s_base = (uint32_t)__cvta_generic_to_shared(smA);

    const int t = threadIdx.x, lane = t & 31, wid = t >> 5;
    const int qt = blockIdx.x, h = blockIdx.y, b = blockIdx.z;
    const int qbase = qt * 64;
    const size_t hb = (size_t)(b * NH + h) * SEQ * HD;

    const int lr7 = lane & 7, l8 = (lane >> 3) & 1, l16 = lane >> 4;

    const __nv_bfloat16* qsrc[2] = {Qh, Ql};
    const __nv_bfloat16* ksrc[4] = {Kh, Kl, Vh, Vl};

    // Q + K/V tile 0 (group 0)
#pragma unroll
    for (int it = 0; it < 8; it++) {
        int c = t + it * 128;
        int mat = c >> 9, r = (c >> 3) & 63, ck = c & 7;
        cp16(s_base + mat * Q_LO_B + (uint32_t)(r * AT_ST + ck * 8) * 2,
             qsrc[mat] + hb + (size_t)(qbase + r) * HD + ck * 8);
    }
#pragma unroll
    for (int it = 0; it < 16; it++) {
        int c = t + it * 128;
        int mat = c >> 9, r = (c >> 3) & 63, ck = c & 7;
        cp16(s_base + TILE_B + mat * ATT_MAT_B + (uint32_t)(r * AT_ST + ck * 8) * 2,
             ksrc[mat] + hb + (size_t)r * HD + ck * 8);
    }
    asm volatile("cp.async.commit_group;");
    // K/V tile 1 (group 1)
#pragma unroll
    for (int it = 0; it < 16; it++) {
        int c = t + it * 128;
        int mat = c >> 9, r = (c >> 3) & 63, ck = c & 7;
        cp16(s_base + TILE_B + BUF_B + mat * ATT_MAT_B + (uint32_t)(r * AT_ST + ck * 8) * 2,
             ksrc[mat] + hb + (size_t)(64 + r) * HD + ck * 8);
    }
    asm volatile("cp.async.commit_group;");
    asm volatile("cp.async.wait_group 1;");
    __syncthreads();

    uint32_t aqh[4][4], aql[4][4];
    {
        const int arow = wid * 16 + (lane & 15);
        const int acol = 8 * l16;
#pragma unroll
        for (int ks = 0; ks < 4; ks++) {
            uint32_t off = (uint32_t)(arow * AT_ST + ks * 16 + acol) * 2;
            LDSM4(aqh[ks], s_base + Q_HI_B + off);
            LDSM4(aql[ks], s_base + Q_LO_B + off);
        }
    }

    float O[8][4];
#pragma unroll
    for (int nf = 0; nf < 8; nf++)
#pragma unroll
        for (int q = 0; q < 4; q++) O[nf][q] = 0.f;
    float m0 = NEG, m1 = NEG, l0 = 0.f, l1 = 0.f;

    const float* bp = bias + (size_t)(b * NH + h) * SEQ * SEQ;
    const unsigned char* mrow = mask + (size_t)b * SEQ;
    const int qr = qbase + wid * 16 + (lane >> 2);
    const int colb = 2 * (lane & 3);

    const int krow = lr7 + 8 * l16;
    const int kcol = 8 * l8;
    const int vrow = lr7 + 8 * l8;
    const int vcol = 8 * l16;

    for (int kt = 0; kt < 16; kt++) {
        const uint32_t tb = s_base + TILE_B + (uint32_t)(kt & 1) * BUF_B;

        float2 bv0[8], bv1[8];
        uchar2 mk[8];
#pragma unroll
        for (int nf = 0; nf < 8; nf++) {
            int col = kt * 64 + nf * 8 + colb;
            bv0[nf] = *(const float2*)&bp[(size_t)qr * SEQ + col];
            bv1[nf] = *(const float2*)&bp[(size_t)(qr + 8) * SEQ + col];
            mk[nf]  = *(const uchar2*)&mrow[col];
        }

        float s[8][4];
#pragma unroll
        for (int nf = 0; nf < 8; nf++)
#pragma unroll
            for (int q = 0; q < 4; q++) s[nf][q] = 0.f;

#pragma unroll
        for (int ks = 0; ks < 4; ks++) {
            uint32_t bh[8][2], bl[8][2];
#pragma unroll
            for (int nf2 = 0; nf2 < 4; nf2++) {
                uint32_t off = (uint32_t)((nf2 * 16 + krow) * AT_ST + ks * 16 + kcol) * 2;
                uint32_t r4[4];
                LDSM4(r4, tb + 0 * ATT_MAT_B + off);
                bh[2*nf2][0] = r4[0]; bh[2*nf2][1] = r4[1];
                bh[2*nf2+1][0] = r4[2]; bh[2*nf2+1][1] = r4[3];
                LDSM4(r4, tb + 1 * ATT_MAT_B + off);
                bl[2*nf2][0] = r4[0]; bl[2*nf2][1] = r4[1];
                bl[2*nf2+1][0] = r4[2]; bl[2*nf2+1][1] = r4[3];
            }
#pragma unroll
            for (int nf = 0; nf < 8; nf++) {
                MMA_BF16(s[nf], aqh[ks], bh[nf]);
                MMA_BF16(s[nf], aql[ks], bh[nf]);
                MMA_BF16(s[nf], aqh[ks], bl[nf]);
            }
        }

#pragma unroll
        for (int nf = 0; nf < 8; nf++) {
            s[nf][0] = mk[nf].x ? NEG : s[nf][0] + bv0[nf].x;
            s[nf][1] = mk[nf].y ? NEG : s[nf][1] + bv0[nf].y;
            s[nf][2] = mk[nf].x ? NEG : s[nf][2] + bv1[nf].x;
            s[nf][3] = mk[nf].y ? NEG : s[nf][3] + bv1[nf].y;
        }

        float mx0 = NEG, mx1 = NEG;
#pragma unroll
        for (int nf = 0; nf < 8; nf++) {
            mx0 = fmaxf(mx0, fmaxf(s[nf][0], s[nf][1]));
            mx1 = fmaxf(mx1, fmaxf(s[nf][2], s[nf][3]));
        }
        mx0 = fmaxf(mx0, __shfl_xor_sync(0xffffffffu, mx0, 1));
        mx0 = fmaxf(mx0, __shfl_xor_sync(0xffffffffu, mx0, 2));
        mx1 = fmaxf(mx1, __shfl_xor_sync(0xffffffffu, mx1, 1));
        mx1 = fmaxf(mx1, __shfl_xor_sync(0xffffffffu, mx1, 2));
        float mn0 = fmaxf(m0, mx0), mn1 = fmaxf(m1, mx1);
        float sc0 = __expf(m0 - mn0), sc1 = __expf(m1 - mn1);
        m0 = mn0; m1 = mn1;
        float su0 = 0.f, su1 = 0.f;
#pragma unroll
        for (int nf = 0; nf < 8; nf++) {
            s[nf][0] = __expf(s[nf][0] - mn0);
            s[nf][1] = __expf(s[nf][1] - mn0);
            s[nf][2] = __expf(s[nf][2] - mn1);
            s[nf][3] = __expf(s[nf][3] - mn1);
            su0 += s[nf][0] + s[nf][1];
            su1 += s[nf][2] + s[nf][3];
        }
        su0 += __shfl_xor_sync(0xffffffffu, su0, 1);
        su0 += __shfl_xor_sync(0xffffffffu, su0, 2);
        su1 += __shfl_xor_sync(0xffffffffu, su1, 1);
        su1 += __shfl_xor_sync(0xffffffffu, su1, 2);
        l0 = l0 * sc0 + su0;
        l1 = l1 * sc1 + su1;
#pragma unroll
        for (int nf = 0; nf < 8; nf++) {
            O[nf][0] *= sc0; O[nf][1] *= sc0;
            O[nf][2] *= sc1; O[nf][3] *= sc1;
        }

#pragma unroll
        for (int ks = 0; ks < 4; ks++) {
            uint32_t aph[4], apl[4];
            {
                const float* p0 = s[2 * ks];
                const float* p1 = s[2 * ks + 1];
                aph[0] = packbf(p0[0], p0[1]);
                aph[1] = packbf(p0[2], p0[3]);
                aph[2] = packbf(p1[0], p1[1]);
                aph[3] = packbf(p1[2], p1[3]);
                apl[0] = residpack(aph[0], p0[0], p0[1]);
                apl[1] = residpack(aph[1], p0[2], p0[3]);
                apl[2] = residpack(aph[2], p1[0], p1[1]);
                apl[3] = residpack(aph[3], p1[2], p1[3]);
            }
            uint32_t vh[8][2], vl[8][2];
#pragma unroll
            for (int nf2 = 0; nf2 < 4; nf2++) {
                uint32_t off = (uint32_t)((ks * 16 + vrow) * AT_ST + nf2 * 16 + vcol) * 2;
                uint32_t r4[4];
                LDSM4T(r4, tb + 2 * ATT_MAT_B + off);
                vh[2*nf2][0] = r4[0]; vh[2*nf2][1] = r4[1];
                vh[2*nf2+1][0] = r4[2]; vh[2*nf2+1][1] = r4[3];
                LDSM4T(r4, tb + 3 * ATT_MAT_B + off);
                vl[2*nf2][0] = r4[0]; vl[2*nf2][1] = r4[1];
                vl[2*nf2+1][0] = r4[2]; vl[2*nf2+1][1] = r4[3];
            }
#pragma unroll
            for (int nf = 0; nf < 8; nf++) {
                MMA_BF16(O[nf], aph, vh[nf]);
                MMA_BF16(O[nf], apl, vh[nf]);
                MMA_BF16(O[nf], aph, vl[nf]);
            }
        }

        // single barrier: next tile's loads complete everywhere AND this
        // buffer free everywhere; then refill.
        asm volatile("cp.async.wait_group 0;");
        __syncthreads();
        if (kt + 2 < 16) {
#pragma unroll
            for (int it = 0; it < 16; it++) {
                int c = t + it * 128;
                int mat = c >> 9, r = (c >> 3) & 63, ck = c & 7;
                cp16(s_base + TILE_B + (uint32_t)(kt & 1) * BUF_B + mat * ATT_MAT_B +
                         (uint32_t)(r * AT_ST + ck * 8) * 2,
                     ksrc[mat] + hb + (size_t)((kt + 2) * 64 + r) * HD + ck * 8);
            }
            asm volatile("cp.async.commit_group;");
        }
    }

    float i0 = 1.f / l0, i1 = 1.f / l1;
    int orow = b * SEQ + qbase + wid * 16 + (lane >> 2);
    uint32_t* oh = (uint32_t*)outh;
    uint32_t* ol = (uint32_t*)outl;
#pragma unroll
    for (int nf = 0; nf < 8; nf++) {
        int col = h * HD + nf * 8 + colb;
        float a0 = O[nf][0] * i0, a1 = O[nf][1] * i0;
        float b0 = O[nf][2] * i1, b1 = O[nf][3] * i1;
        uint32_t h0 = packbf(a0, a1);
        uint32_t l0r = residpack(h0, a0, a1);
        uint32_t h1 = packbf(b0, b1);
        uint32_t l1r = residpack(h1, b0, b1);
        size_t idx0 = ((size_t)orow * EMB + col) >> 1;
        size_t idx1 = ((size_t)(orow + 8) * EMB + col) >> 1;
        oh[idx0] = h0; ol[idx0] = l0r;
        oh[idx1] = h1; ol[idx1] = l1r;
    }
}

// ---------------------------------------------------------------------------
extern "C" void kernel_launch(void* const* d_in, const int* in_sizes, int n_in,
                              void* d_out, int out_size)
{
    const float* query         = (const float*)d_in[0];
    const unsigned char* maskp = (const unsigned char*)d_in[1];
    const float* attn_bias     = (const float*)d_in[2];
    const float* Wqkv          = (const float*)d_in[3];
    const float* bqkv          = (const float*)d_in[4];
    const float* Wo            = (const float*)d_in[5];
    const float* bo            = (const float*)d_in[6];
    float* out                 = (float*)d_out;

    __nv_bfloat16 *Ahi, *Alo, *W1hi, *W1lo, *W2hi, *W2lo, *Thi, *Tlo;
    __nv_bfloat16 *Qh, *Ql, *Kh, *Kl, *Vh, *Vl;
    cudaGetSymbolAddress((void**)&Ahi,  g_A_hi);
    cudaGetSymbolAddress((void**)&Alo,  g_A_lo);
    cudaGetSymbolAddress((void**)&W1hi, g_W1_hi);
    cudaGetSymbolAddress((void**)&W1lo, g_W1_lo);
    cudaGetSymbolAddress((void**)&W2hi, g_W2_hi);
    cudaGetSymbolAddress((void**)&W2lo, g_W2_lo);
    cudaGetSymbolAddress((void**)&Thi,  g_att_hi);
    cudaGetSymbolAddress((void**)&Tlo,  g_att_lo);
    cudaGetSymbolAddress((void**)&Qh,   g_Qh);
    cudaGetSymbolAddress((void**)&Ql,   g_Ql);
    cudaGetSymbolAddress((void**)&Kh,   g_Kh);
    cudaGetSymbolAddress((void**)&Kl,   g_Kl);
    cudaGetSymbolAddress((void**)&Vh,   g_Vh);
    cudaGetSymbolAddress((void**)&Vl,   g_Vl);

    cudaFuncSetAttribute(gemm_mma,
                         cudaFuncAttributeMaxDynamicSharedMemorySize, GEMM_SMEM);
    cudaFuncSetAttribute(attn_mma,
                         cudaFuncAttributeMaxDynamicSharedMemorySize, ATT_SMEM);

    // 0) split query + Wqkv + Wo into bf16 (hi, lo) — one launch
    split_all<<<NSPLIT / 1024, 256>>>(query, Wqkv, Wo,
                                      Ahi, Alo, W1hi, W1lo, W2hi, W2lo);

    // 1) QKV projection, fused head-major bf16 hi/lo epilogue (Q pre-scaled)
    {
        dim3 grid(3 * EMB / 128, MTOT / 128);
        gemm_mma<<<grid, 128, GEMM_SMEM>>>(Ahi, Alo, W1hi, W1lo, bqkv,
                                           nullptr, Qh, Ql, Kh, Kl, Vh, Vl,
                                           MTOT, 3 * EMB, EMB, 1);
    }

    // 2) flash attention (BR=64, 2 CTAs/SM), writes bf16 hi/lo attention output
    {
        dim3 grid(SEQ / 64, NH, BATCH);
        attn_mma<<<grid, 128, ATT_SMEM>>>(attn_bias, maskp, Thi, Tlo,
                                          Qh, Ql, Kh, Kl, Vh, Vl);
    }

    // 3) output projection (f32 epilogue into d_out)
    {
        dim3 grid(EMB / 128, MTOT / 128);
        gemm_mma<<<grid, 128, GEMM_SMEM>>>(Thi, Tlo, W2hi, W2lo, bo,
                                           out, nullptr, nullptr, nullptr,
                                           nullptr, nullptr, nullptr,
                                           MTOT, EMB, EMB, 0);
    }
}

// round 14
// speedup vs baseline: 1.8032x; 1.1070x over previous
#include <cuda_runtime.h>
#include <cuda_fp16.h>
#include <cstdint>

// Problem constants
#define EMB   1024
#define NH    16
#define HD    64
#define BATCH 4
#define SEQ   1024
#define MTOT  (BATCH*SEQ)
#define SCALING 0.3952847075210474f   // (64*0.1)^-0.5
#define NEG   (-1e30f)

#define NQ_ELEM  (MTOT * EMB)        // 4194304
#define NW1_ELEM (3 * EMB * EMB)     // 3145728
#define NW2_ELEM (EMB * EMB)         // 1048576
#define NSPLIT   (NQ_ELEM + NW1_ELEM + NW2_ELEM)

// Scratch (device globals) — fp16
__device__ __half g_A_hi[MTOT * EMB];
__device__ __half g_A_lo[MTOT * EMB];
__device__ __half g_W1_hi[3 * EMB * EMB];
__device__ __half g_W1_lo[3 * EMB * EMB];
__device__ __half g_W2_hi[EMB * EMB];          // single (2-term out-proj)
__device__ __half g_att_hi[MTOT * EMB];
__device__ __half g_att_lo[MTOT * EMB];
__device__ __half g_Qh[MTOT * EMB];
__device__ __half g_Ql[MTOT * EMB];
__device__ __half g_Kh[MTOT * EMB];
__device__ __half g_Kl[MTOT * EMB];
__device__ __half g_Vh[MTOT * EMB];            // single (2-term PV)

// ---------------------------------------------------------------------------
// PTX helpers
// ---------------------------------------------------------------------------
#define LDSM4(r, addr) \
    asm volatile("ldmatrix.sync.aligned.m8n8.x4.shared.b16 {%0,%1,%2,%3}, [%4];" \
                 : "=r"((r)[0]), "=r"((r)[1]), "=r"((r)[2]), "=r"((r)[3]) : "r"(addr))

#define LDSM4T(r, addr) \
    asm volatile("ldmatrix.sync.aligned.m8n8.x4.trans.shared.b16 {%0,%1,%2,%3}, [%4];" \
                 : "=r"((r)[0]), "=r"((r)[1]), "=r"((r)[2]), "=r"((r)[3]) : "r"(addr))

#define MMA_F16(d, a, b) \
    asm volatile("mma.sync.aligned.m16n8k16.row.col.f32.f16.f16.f32 " \
                 "{%0,%1,%2,%3},{%4,%5,%6,%7},{%8,%9},{%0,%1,%2,%3};" \
                 : "+f"((d)[0]), "+f"((d)[1]), "+f"((d)[2]), "+f"((d)[3]) \
                 : "r"((a)[0]), "r"((a)[1]), "r"((a)[2]), "r"((a)[3]), \
                   "r"((b)[0]), "r"((b)[1]))

__device__ __forceinline__ void cp16(uint32_t s, const void* g) {
    asm volatile("cp.async.cg.shared.global [%0], [%1], 16;" :: "r"(s), "l"(g));
}

// pack {lo, hi} floats into f16x2 register (lo -> low half)
__device__ __forceinline__ uint32_t packh(float lo, float hi) {
    uint32_t r;
    asm("cvt.rn.f16x2.f32 %0, %1, %2;" : "=r"(r) : "f"(hi), "f"(lo));
    return r;
}
__device__ __forceinline__ uint32_t residpackh(uint32_t ph, float lo, float hi) {
    __half2 h = *(__half2*)&ph;
    return packh(lo - __low2float(h), hi - __high2float(h));
}

// ---------------------------------------------------------------------------
// merged f32 -> f16 (hi, lo) split: query, Wqkv (hi+lo); Wo (hi only)
// ---------------------------------------------------------------------------
__global__ __launch_bounds__(256)
void split_all(const float* __restrict__ q, const float* __restrict__ w1,
               const float* __restrict__ w2,
               __half* __restrict__ Ahi, __half* __restrict__ Alo,
               __half* __restrict__ W1hi, __half* __restrict__ W1lo,
               __half* __restrict__ W2hi)
{
    int i = (blockIdx.x * 256 + threadIdx.x) * 4;
    const float* src;
    __half *hi, *lo;
    int off;
    bool wantlo = true;
    if (i < NQ_ELEM)                { src = q;  hi = Ahi;  lo = Alo;  off = i; }
    else if (i < NQ_ELEM + NW1_ELEM){ src = w1; hi = W1hi; lo = W1lo; off = i - NQ_ELEM; }
    else { src = w2; hi = W2hi; lo = nullptr; off = i - NQ_ELEM - NW1_ELEM; wantlo = false; }

    float4 v = *(const float4*)(src + off);
    float f[4] = {v.x, v.y, v.z, v.w};
    __half h[4], l[4];
#pragma unroll
    for (int j = 0; j < 4; j++) {
        h[j] = __float2half(f[j]);
        l[j] = __float2half(f[j] - __half2float(h[j]));
    }
    *(uint2*)(hi + off) = *(const uint2*)h;
    if (wantlo) *(uint2*)(lo + off) = *(const uint2*)l;
}

// ---------------------------------------------------------------------------
// Tensor-core GEMM: C[M,N] = A[M,K]*B[N,K]^T + bias[N], fp16 split.
// CTA 128x128, 128 threads (4 warps, 2m x 2n), warp tile 64x64, BK=32,
// 2-stage cp.async, 2 CTAs/SM, ONE __syncthreads per k-iter.
// mode 1 (QKV): 3-term (AhBh+AlBh+AhBl) + fused head-major f16 hi/lo epilogue.
// mode 0 (proj): 2-term (AhBh+AlBh, B single) + f32 epilogue.
// ---------------------------------------------------------------------------
#define AST   40
#define MAT_H (128 * AST)
#define GEMM_SMEM (8 * MAT_H * 2)   // 81920 B
#define EP_ST 68

__global__ __launch_bounds__(128, 2)
void gemm_mma(const __half* __restrict__ Ah,
              const __half* __restrict__ Al,
              const __half* __restrict__ Bh,
              const __half* __restrict__ Bl,
              const float* __restrict__ bias,
              float* __restrict__ C,
              __half* __restrict__ Qh, __half* __restrict__ Ql,
              __half* __restrict__ Kh, __half* __restrict__ Kl,
              __half* __restrict__ Vh,
              int M, int N, int K, int mode)
{
    extern __shared__ __align__(16) __half smem_b[];
    const uint32_t sm_base = (uint32_t)__cvta_generic_to_shared(smem_b);

    const int t    = threadIdx.x;
    const int lane = t & 31;
    const int w    = t >> 5;
    const int wm   = w & 1;
    const int wn   = w >> 1;
    const int bm   = blockIdx.y * 128;
    const int bn   = blockIdx.x * 128;
    const int nk   = K >> 5;
    const bool full = (mode == 1);
    const int climit = full ? 2048 : 1536;   // chunks: A 1024, Bh 512, Bl 512

    float acc[4][8][4];
#pragma unroll
    for (int mi = 0; mi < 4; mi++)
#pragma unroll
        for (int ni = 0; ni < 8; ni++)
#pragma unroll
            for (int q = 0; q < 4; q++) acc[mi][ni][q] = 0.f;

    const __half* gp[4] = {Ah, Al, Bh, Bl};

    auto issue = [&](int stage, int k0) {
#pragma unroll
        for (int i = 0; i < 16; i++) {
            int c = t + i * 128;
            if (c >= climit) break;
            int mat = c >> 9;
            int idx = c & 511;
            int row = idx >> 2, ck = (idx & 3) * 8;
            int base = (mat < 2) ? bm : bn;
            uint32_t so = sm_base + (uint32_t)(stage * 4 + mat) * MAT_H * 2;
            cp16(so + (uint32_t)(row * AST + ck) * 2,
                 gp[mat] + (size_t)(base + row) * K + k0 + ck);
        }
        asm volatile("cp.async.commit_group;");
    };

    issue(0, 0);
    issue(1, 32);
    asm volatile("cp.async.wait_group 1;");
    __syncthreads();

    for (int kt = 0; kt < nk; kt++) {
        const int stage = kt & 1;
        const uint32_t bAh = sm_base + (uint32_t)(stage * 4 + 0) * MAT_H * 2;
        const uint32_t bAl = sm_base + (uint32_t)(stage * 4 + 1) * MAT_H * 2;
        const uint32_t bBh = sm_base + (uint32_t)(stage * 4 + 2) * MAT_H * 2;
        const uint32_t bBl = sm_base + (uint32_t)(stage * 4 + 3) * MAT_H * 2;

#pragma unroll
        for (int ks = 0; ks < 2; ks++) {
            uint32_t ah[4][4], al[4][4], bh[8][2], bl[8][2];

            const int arow = wm * 64 + (lane & 15);
            const int acol = ks * 16 + (lane >> 4) * 8;
#pragma unroll
            for (int mi = 0; mi < 4; mi++) {
                uint32_t off = (uint32_t)((arow + mi * 16) * AST + acol) * 2;
                LDSM4(ah[mi], bAh + off);
                LDSM4(al[mi], bAl + off);
            }

            const int brow = wn * 64 + (lane >> 4) * 8 + (lane & 7);
            const int bcol = ks * 16 + ((lane >> 3) & 1) * 8;
#pragma unroll
            for (int ni2 = 0; ni2 < 4; ni2++) {
                uint32_t off = (uint32_t)((brow + ni2 * 16) * AST + bcol) * 2;
                uint32_t r[4];
                LDSM4(r, bBh + off);
                bh[ni2 * 2][0] = r[0]; bh[ni2 * 2][1] = r[1];
                bh[ni2 * 2 + 1][0] = r[2]; bh[ni2 * 2 + 1][1] = r[3];
                if (full) {
                    LDSM4(r, bBl + off);
                    bl[ni2 * 2][0] = r[0]; bl[ni2 * 2][1] = r[1];
                    bl[ni2 * 2 + 1][0] = r[2]; bl[ni2 * 2 + 1][1] = r[3];
                }
            }

#pragma unroll
            for (int mi = 0; mi < 4; mi++)
#pragma unroll
                for (int ni = 0; ni < 8; ni++) {
                    MMA_F16(acc[mi][ni], ah[mi], bh[ni]);       // hi*hi
                    MMA_F16(acc[mi][ni], al[mi], bh[ni]);       // lo*hi
                    if (full) MMA_F16(acc[mi][ni], ah[mi], bl[ni]); // hi*lo
                }
        }

        asm volatile("cp.async.wait_group 0;");
        __syncthreads();
        if (kt + 2 < nk) issue(kt & 1, (kt + 2) << 5);
    }

    if (mode == 0) {
#pragma unroll
        for (int mi = 0; mi < 4; mi++) {
            const int r0 = bm + wm * 64 + mi * 16 + (lane >> 2);
#pragma unroll
            for (int ni = 0; ni < 8; ni++) {
                const int col = bn + wn * 64 + ni * 8 + (lane & 3) * 2;
                float bx = bias[col], by = bias[col + 1];
                float2 v0 = make_float2(acc[mi][ni][0] + bx, acc[mi][ni][1] + by);
                float2 v1 = make_float2(acc[mi][ni][2] + bx, acc[mi][ni][3] + by);
                *(float2*)&C[(size_t)r0 * N + col] = v0;
                *(float2*)&C[(size_t)(r0 + 8) * N + col] = v1;
            }
        }
    } else {
        // fused qkv-split epilogue, smem-staged; Q,K get hi+lo, V hi only
        uint32_t* sh = (uint32_t*)smem_b;
        uint32_t* sl = sh + 128 * EP_ST;
        const int m = bn >> 10;   // 0=q 1=k 2=v
        const float sc = (m == 0) ? SCALING : 1.0f;

#pragma unroll
        for (int mi = 0; mi < 4; mi++) {
            const int lr0 = wm * 64 + mi * 16 + (lane >> 2);
#pragma unroll
            for (int ni = 0; ni < 8; ni++) {
                const int lcol = wn * 64 + ni * 8 + (lane & 3) * 2;
                const int colu = lcol >> 1;
                float bx = bias[bn + lcol], by = bias[bn + lcol + 1];
                float a0 = (acc[mi][ni][0] + bx) * sc;
                float a1 = (acc[mi][ni][1] + by) * sc;
                float b0 = (acc[mi][ni][2] + bx) * sc;
                float b1 = (acc[mi][ni][3] + by) * sc;
                uint32_t hp0 = packh(a0, a1);
                uint32_t hp1 = packh(b0, b1);
                sh[lr0 * EP_ST + colu] = hp0;
                sl[lr0 * EP_ST + colu] = residpackh(hp0, a0, a1);
                sh[(lr0 + 8) * EP_ST + colu] = hp1;
                sl[(lr0 + 8) * EP_ST + colu] = residpackh(hp1, b0, b1);
            }
        }
        __syncthreads();

        uint32_t* oh = (uint32_t*)((m == 0) ? Qh : (m == 1) ? Kh : Vh);
        uint32_t* ol = (uint32_t*)((m == 0) ? Ql : Kl);   // unused for m==2
        const int hh0 = (bn >> 6) & 15;
        const int bb = bm >> 10, s0 = bm & 1023;

#pragma unroll
        for (int i = 0; i < 16; i++) {
            int c = t + i * 128;
            int row = c >> 4, sub = c & 15;
            int j = sub >> 3, q4 = (sub & 7) * 4;
            size_t g = (((size_t)(bb * NH + hh0 + j)) * SEQ + s0 + row) * 32 + q4;
            uint4 vh4 = *(uint4*)&sh[row * EP_ST + j * 32 + q4];
            *(uint4*)&oh[g] = vh4;
            if (m != 2) {
                uint4 vl4 = *(uint4*)&sl[row * EP_ST + j * 32 + q4];
                *(uint4*)&ol[g] = vl4;
            }
        }
    }
}

// ---------------------------------------------------------------------------
// Tensor-core flash attention, fp16. BR=64 q-rows, 128 threads (4 warps),
// S = QK^T 3-term (K hi/lo), PV 2-term (V hi only). 2 CTAs/SM, single barrier.
// K/V tile = 3 matrices: {Kh, Kl, Vh}.
// ---------------------------------------------------------------------------
#define AT_ST 72
#define Q_HI_B 0
#define Q_LO_B 9216
#define TILE_B 18432
#define ATT_MAT_B  9216
#define BUF_B  27648                   // 3 matrices
#define ATT_SMEM (TILE_B + 2 * BUF_B)  // 73728

__global__ __launch_bounds__(128)
void attn_mma(const float* __restrict__ bias, const unsigned char* __restrict__ mask,
              __half* __restrict__ outh, __half* __restrict__ outl,
              const __half* __restrict__ Qh, const __half* __restrict__ Ql,
              const __half* __restrict__ Kh, const __half* __restrict__ Kl,
              const __half* __restrict__ Vh)
{
    extern __shared__ __align__(16) __half smA[];
    const uint32_t s_base = (uint32_t)__cvta_generic_to_shared(smA);

    const int t = threadIdx.x, lane = t & 31, wid = t >> 5;
    const int qt = blockIdx.x, h = blockIdx.y, b = blockIdx.z;
    const int qbase = qt * 64;
    const size_t hb = (size_t)(b * NH + h) * SEQ * HD;

    const int lr7 = lane & 7, l8 = (lane >> 3) & 1, l16 = lane >> 4;

    const __half* qsrc[2] = {Qh, Ql};
    const __half* ksrc[3] = {Kh, Kl, Vh};

    // Q (2 mats, 1024 chunks)
#pragma unroll
    for (int it = 0; it < 8; it++) {
        int c = t + it * 128;
        int mat = c >> 9, r = (c >> 3) & 63, ck = c & 7;
        cp16(s_base + mat * Q_LO_B + (uint32_t)(r * AT_ST + ck * 8) * 2,
             qsrc[mat] + hb + (size_t)(qbase + r) * HD + ck * 8);
    }
    // K/V tile 0 (3 mats, 1536 chunks)
#pragma unroll
    for (int it = 0; it < 12; it++) {
        int c = t + it * 128;
        int mat = c >> 9, r = (c >> 3) & 63, ck = c & 7;
        cp16(s_base + TILE_B + mat * ATT_MAT_B + (uint32_t)(r * AT_ST + ck * 8) * 2,
             ksrc[mat] + hb + (size_t)r * HD + ck * 8);
    }
    asm volatile("cp.async.commit_group;");
    // K/V tile 1
#pragma unroll
    for (int it = 0; it < 12; it++) {
        int c = t + it * 128;
        int mat = c >> 9, r = (c >> 3) & 63, ck = c & 7;
        cp16(s_base + TILE_B + BUF_B + mat * ATT_MAT_B + (uint32_t)(r * AT_ST + ck * 8) * 2,
             ksrc[mat] + hb + (size_t)(64 + r) * HD + ck * 8);
    }
    asm volatile("cp.async.commit_group;");
    asm volatile("cp.async.wait_group 1;");
    __syncthreads();

    uint32_t aqh[4][4], aql[4][4];
    {
        const int arow = wid * 16 + (lane & 15);
        const int acol = 8 * l16;
#pragma unroll
        for (int ks = 0; ks < 4; ks++) {
            uint32_t off = (uint32_t)(arow * AT_ST + ks * 16 + acol) * 2;
            LDSM4(aqh[ks], s_base + Q_HI_B + off);
            LDSM4(aql[ks], s_base + Q_LO_B + off);
        }
    }

    float O[8][4];
#pragma unroll
    for (int nf = 0; nf < 8; nf++)
#pragma unroll
        for (int q = 0; q < 4; q++) O[nf][q] = 0.f;
    float m0 = NEG, m1 = NEG, l0 = 0.f, l1 = 0.f;

    const float* bp = bias + (size_t)(b * NH + h) * SEQ * SEQ;
    const unsigned char* mrow = mask + (size_t)b * SEQ;
    const int qr = qbase + wid * 16 + (lane >> 2);
    const int colb = 2 * (lane & 3);

    const int krow = lr7 + 8 * l16;
    const int kcol = 8 * l8;
    const int vrow = lr7 + 8 * l8;
    const int vcol = 8 * l16;

    for (int kt = 0; kt < 16; kt++) {
        const uint32_t tb = s_base + TILE_B + (uint32_t)(kt & 1) * BUF_B;

        float2 bv0[8], bv1[8];
        uchar2 mk[8];
#pragma unroll
        for (int nf = 0; nf < 8; nf++) {
            int col = kt * 64 + nf * 8 + colb;
            bv0[nf] = *(const float2*)&bp[(size_t)qr * SEQ + col];
            bv1[nf] = *(const float2*)&bp[(size_t)(qr + 8) * SEQ + col];
            mk[nf]  = *(const uchar2*)&mrow[col];
        }

        float s[8][4];
#pragma unroll
        for (int nf = 0; nf < 8; nf++)
#pragma unroll
            for (int q = 0; q < 4; q++) s[nf][q] = 0.f;

#pragma unroll
        for (int ks = 0; ks < 4; ks++) {
            uint32_t bh[8][2], bl[8][2];
#pragma unroll
            for (int nf2 = 0; nf2 < 4; nf2++) {
                uint32_t off = (uint32_t)((nf2 * 16 + krow) * AT_ST + ks * 16 + kcol) * 2;
                uint32_t r4[4];
                LDSM4(r4, tb + 0 * ATT_MAT_B + off);
                bh[2*nf2][0] = r4[0]; bh[2*nf2][1] = r4[1];
                bh[2*nf2+1][0] = r4[2]; bh[2*nf2+1][1] = r4[3];
                LDSM4(r4, tb + 1 * ATT_MAT_B + off);
                bl[2*nf2][0] = r4[0]; bl[2*nf2][1] = r4[1];
                bl[2*nf2+1][0] = r4[2]; bl[2*nf2+1][1] = r4[3];
            }
#pragma unroll
            for (int nf = 0; nf < 8; nf++) {
                MMA_F16(s[nf], aqh[ks], bh[nf]);
                MMA_F16(s[nf], aql[ks], bh[nf]);
                MMA_F16(s[nf], aqh[ks], bl[nf]);
            }
        }

#pragma unroll
        for (int nf = 0; nf < 8; nf++) {
            s[nf][0] = mk[nf].x ? NEG : s[nf][0] + bv0[nf].x;
            s[nf][1] = mk[nf].y ? NEG : s[nf][1] + bv0[nf].y;
            s[nf][2] = mk[nf].x ? NEG : s[nf][2] + bv1[nf].x;
            s[nf][3] = mk[nf].y ? NEG : s[nf][3] + bv1[nf].y;
        }

        float mx0 = NEG, mx1 = NEG;
#pragma unroll
        for (int nf = 0; nf < 8; nf++) {
            mx0 = fmaxf(mx0, fmaxf(s[nf][0], s[nf][1]));
            mx1 = fmaxf(mx1, fmaxf(s[nf][2], s[nf][3]));
        }
        mx0 = fmaxf(mx0, __shfl_xor_sync(0xffffffffu, mx0, 1));
        mx0 = fmaxf(mx0, __shfl_xor_sync(0xffffffffu, mx0, 2));
        mx1 = fmaxf(mx1, __shfl_xor_sync(0xffffffffu, mx1, 1));
        mx1 = fmaxf(mx1, __shfl_xor_sync(0xffffffffu, mx1, 2));
        float mn0 = fmaxf(m0, mx0), mn1 = fmaxf(m1, mx1);
        float sc0 = __expf(m0 - mn0), sc1 = __expf(m1 - mn1);
        m0 = mn0; m1 = mn1;
        float su0 = 0.f, su1 = 0.f;
#pragma unroll
        for (int nf = 0; nf < 8; nf++) {
            s[nf][0] = __expf(s[nf][0] - mn0);
            s[nf][1] = __expf(s[nf][1] - mn0);
            s[nf][2] = __expf(s[nf][2] - mn1);
            s[nf][3] = __expf(s[nf][3] - mn1);
            su0 += s[nf][0] + s[nf][1];
            su1 += s[nf][2] + s[nf][3];
        }
        su0 += __shfl_xor_sync(0xffffffffu, su0, 1);
        su0 += __shfl_xor_sync(0xffffffffu, su0, 2);
        su1 += __shfl_xor_sync(0xffffffffu, su1, 1);
        su1 += __shfl_xor_sync(0xffffffffu, su1, 2);
        l0 = l0 * sc0 + su0;
        l1 = l1 * sc1 + su1;
#pragma unroll
        for (int nf = 0; nf < 8; nf++) {
            O[nf][0] *= sc0; O[nf][1] *= sc0;
            O[nf][2] *= sc1; O[nf][3] *= sc1;
        }

        // PV: 2-term (P hi/lo x V hi)
#pragma unroll
        for (int ks = 0; ks < 4; ks++) {
            uint32_t aph[4], apl[4];
            {
                const float* p0 = s[2 * ks];
                const float* p1 = s[2 * ks + 1];
                aph[0] = packh(p0[0], p0[1]);
                aph[1] = packh(p0[2], p0[3]);
                aph[2] = packh(p1[0], p1[1]);
                aph[3] = packh(p1[2], p1[3]);
                apl[0] = residpackh(aph[0], p0[0], p0[1]);
                apl[1] = residpackh(aph[1], p0[2], p0[3]);
                apl[2] = residpackh(aph[2], p1[0], p1[1]);
                apl[3] = residpackh(aph[3], p1[2], p1[3]);
            }
            uint32_t vh[8][2];
#pragma unroll
            for (int nf2 = 0; nf2 < 4; nf2++) {
                uint32_t off = (uint32_t)((ks * 16 + vrow) * AT_ST + nf2 * 16 + vcol) * 2;
                uint32_t r4[4];
                LDSM4T(r4, tb + 2 * ATT_MAT_B + off);
                vh[2*nf2][0] = r4[0]; vh[2*nf2][1] = r4[1];
                vh[2*nf2+1][0] = r4[2]; vh[2*nf2+1][1] = r4[3];
            }
#pragma unroll
            for (int nf = 0; nf < 8; nf++) {
                MMA_F16(O[nf], aph, vh[nf]);
                MMA_F16(O[nf], apl, vh[nf]);
            }
        }

        asm volatile("cp.async.wait_group 0;");
        __syncthreads();
        if (kt + 2 < 16) {
#pragma unroll
            for (int it = 0; it < 12; it++) {
                int c = t + it * 128;
                int mat = c >> 9, r = (c >> 3) & 63, ck = c & 7;
                cp16(s_base + TILE_B + (uint32_t)(kt & 1) * BUF_B + mat * ATT_MAT_B +
                         (uint32_t)(r * AT_ST + ck * 8) * 2,
                     ksrc[mat] + hb + (size_t)((kt + 2) * 64 + r) * HD + ck * 8);
            }
            asm volatile("cp.async.commit_group;");
        }
    }

    float i0 = 1.f / l0, i1 = 1.f / l1;
    int orow = b * SEQ + qbase + wid * 16 + (lane >> 2);
    uint32_t* oh = (uint32_t*)outh;
    uint32_t* ol = (uint32_t*)outl;
#pragma unroll
    for (int nf = 0; nf < 8; nf++) {
        int col = h * HD + nf * 8 + colb;
        float a0 = O[nf][0] * i0, a1 = O[nf][1] * i0;
        float b0 = O[nf][2] * i1, b1 = O[nf][3] * i1;
        uint32_t h0 = packh(a0, a1);
        uint32_t l0r = residpackh(h0, a0, a1);
        uint32_t h1 = packh(b0, b1);
        uint32_t l1r = residpackh(h1, b0, b1);
        size_t idx0 = ((size_t)orow * EMB + col) >> 1;
        size_t idx1 = ((size_t)(orow + 8) * EMB + col) >> 1;
        oh[idx0] = h0; ol[idx0] = l0r;
        oh[idx1] = h1; ol[idx1] = l1r;
    }
}

// ---------------------------------------------------------------------------
extern "C" void kernel_launch(void* const* d_in, const int* in_sizes, int n_in,
                              void* d_out, int out_size)
{
    const float* query         = (const float*)d_in[0];
    const unsigned char* maskp = (const unsigned char*)d_in[1];
    const float* attn_bias     = (const float*)d_in[2];
    const float* Wqkv          = (const float*)d_in[3];
    const float* bqkv          = (const float*)d_in[4];
    const float* Wo            = (const float*)d_in[5];
    const float* bo            = (const float*)d_in[6];
    float* out                 = (float*)d_out;

    __half *Ahi, *Alo, *W1hi, *W1lo, *W2hi, *Thi, *Tlo;
    __half *Qh, *Ql, *Kh, *Kl, *Vh;
    cudaGetSymbolAddress((void**)&Ahi,  g_A_hi);
    cudaGetSymbolAddress((void**)&Alo,  g_A_lo);
    cudaGetSymbolAddress((void**)&W1hi, g_W1_hi);
    cudaGetSymbolAddress((void**)&W1lo, g_W1_lo);
    cudaGetSymbolAddress((void**)&W2hi, g_W2_hi);
    cudaGetSymbolAddress((void**)&Thi,  g_att_hi);
    cudaGetSymbolAddress((void**)&Tlo,  g_att_lo);
    cudaGetSymbolAddress((void**)&Qh,   g_Qh);
    cudaGetSymbolAddress((void**)&Ql,   g_Ql);
    cudaGetSymbolAddress((void**)&Kh,   g_Kh);
    cudaGetSymbolAddress((void**)&Kl,   g_Kl);
    cudaGetSymbolAddress((void**)&Vh,   g_Vh);

    cudaFuncSetAttribute(gemm_mma,
                         cudaFuncAttributeMaxDynamicSharedMemorySize, GEMM_SMEM);
    cudaFuncSetAttribute(attn_mma,
                         cudaFuncAttributeMaxDynamicSharedMemorySize, ATT_SMEM);

    // 0) split query + Wqkv (hi/lo) + Wo (hi) — one launch
    split_all<<<NSPLIT / 1024, 256>>>(query, Wqkv, Wo,
                                      Ahi, Alo, W1hi, W1lo, W2hi);

    // 1) QKV projection (3-term), fused head-major f16 epilogue (Q pre-scaled)
    {
        dim3 grid(3 * EMB / 128, MTOT / 128);
        gemm_mma<<<grid, 128, GEMM_SMEM>>>(Ahi, Alo, W1hi, W1lo, bqkv,
                                           nullptr, Qh, Ql, Kh, Kl, Vh,
                                           MTOT, 3 * EMB, EMB, 1);
    }

    // 2) flash attention (S 3-term, PV 2-term), writes f16 hi/lo output
    {
        dim3 grid(SEQ / 64, NH, BATCH);
        attn_mma<<<grid, 128, ATT_SMEM>>>(attn_bias, maskp, Thi, Tlo,
                                          Qh, Ql, Kh, Kl, Vh);
    }

    // 3) output projection (2-term, W2 hi only, f32 epilogue into d_out)
    {
        dim3 grid(EMB / 128, MTOT / 128);
        gemm_mma<<<grid, 128, GEMM_SMEM>>>(Thi, Tlo, W2hi, nullptr, bo,
                                           out, nullptr, nullptr, nullptr,
                                           nullptr, nullptr,
                                           MTOT, EMB, EMB, 0);
    }
}

// round 15
// speedup vs baseline: 1.8043x; 1.0006x over previous
#include <cuda_runtime.h>
#include <cuda_fp16.h>
#include <cstdint>

// Problem constants
#define EMB   1024
#define NH    16
#define HD    64
#define BATCH 4
#define SEQ   1024
#define MTOT  (BATCH*SEQ)
#define SCALING 0.3952847075210474f   // (64*0.1)^-0.5
#define NEG   (-1e30f)

#define NQ_ELEM  (MTOT * EMB)
#define NW1_ELEM (3 * EMB * EMB)
#define NW2_ELEM (EMB * EMB)
#define NSPLIT   (NQ_ELEM + NW1_ELEM + NW2_ELEM)

// Scratch (device globals) — fp16
__device__ __half g_A_hi[MTOT * EMB];
__device__ __half g_A_lo[MTOT * EMB];
__device__ __half g_W1_hi[3 * EMB * EMB];
__device__ __half g_W1_lo[3 * EMB * EMB];
__device__ __half g_W2_hi[EMB * EMB];
__device__ __half g_att_hi[MTOT * EMB];
__device__ __half g_att_lo[MTOT * EMB];
__device__ __half g_Qh[MTOT * EMB];
__device__ __half g_Ql[MTOT * EMB];
__device__ __half g_Kh[MTOT * EMB];
__device__ __half g_Kl[MTOT * EMB];
__device__ __half g_Vh[MTOT * EMB];

// ---------------------------------------------------------------------------
// PTX helpers
// ---------------------------------------------------------------------------
#define LDSM4(r, addr) \
    asm volatile("ldmatrix.sync.aligned.m8n8.x4.shared.b16 {%0,%1,%2,%3}, [%4];" \
                 : "=r"((r)[0]), "=r"((r)[1]), "=r"((r)[2]), "=r"((r)[3]) : "r"(addr))

#define LDSM4T(r, addr) \
    asm volatile("ldmatrix.sync.aligned.m8n8.x4.trans.shared.b16 {%0,%1,%2,%3}, [%4];" \
                 : "=r"((r)[0]), "=r"((r)[1]), "=r"((r)[2]), "=r"((r)[3]) : "r"(addr))

#define MMA_F16(d, a, b) \
    asm volatile("mma.sync.aligned.m16n8k16.row.col.f32.f16.f16.f32 " \
                 "{%0,%1,%2,%3},{%4,%5,%6,%7},{%8,%9},{%0,%1,%2,%3};" \
                 : "+f"((d)[0]), "+f"((d)[1]), "+f"((d)[2]), "+f"((d)[3]) \
                 : "r"((a)[0]), "r"((a)[1]), "r"((a)[2]), "r"((a)[3]), \
                   "r"((b)[0]), "r"((b)[1]))

__device__ __forceinline__ void cp16(uint32_t s, const void* g) {
    asm volatile("cp.async.cg.shared.global [%0], [%1], 16;" :: "r"(s), "l"(g));
}

__device__ __forceinline__ uint32_t packh(float lo, float hi) {
    uint32_t r;
    asm("cvt.rn.f16x2.f32 %0, %1, %2;" : "=r"(r) : "f"(hi), "f"(lo));
    return r;
}
__device__ __forceinline__ uint32_t residpackh(uint32_t ph, float lo, float hi) {
    __half2 h = *(__half2*)&ph;
    return packh(lo - __low2float(h), hi - __high2float(h));
}

// ---------------------------------------------------------------------------
// merged f32 -> f16 (hi, lo) split: query, Wqkv (hi+lo); Wo (hi only)
// ---------------------------------------------------------------------------
__global__ __launch_bounds__(256)
void split_all(const float* __restrict__ q, const float* __restrict__ w1,
               const float* __restrict__ w2,
               __half* __restrict__ Ahi, __half* __restrict__ Alo,
               __half* __restrict__ W1hi, __half* __restrict__ W1lo,
               __half* __restrict__ W2hi)
{
    int i = (blockIdx.x * 256 + threadIdx.x) * 4;
    const float* src;
    __half *hi, *lo;
    int off;
    bool wantlo = true;
    if (i < NQ_ELEM)                { src = q;  hi = Ahi;  lo = Alo;  off = i; }
    else if (i < NQ_ELEM + NW1_ELEM){ src = w1; hi = W1hi; lo = W1lo; off = i - NQ_ELEM; }
    else { src = w2; hi = W2hi; lo = nullptr; off = i - NQ_ELEM - NW1_ELEM; wantlo = false; }

    float4 v = *(const float4*)(src + off);
    float f[4] = {v.x, v.y, v.z, v.w};
    __half h[4], l[4];
#pragma unroll
    for (int j = 0; j < 4; j++) {
        h[j] = __float2half(f[j]);
        l[j] = __float2half(f[j] - __half2float(h[j]));
    }
    *(uint2*)(hi + off) = *(const uint2*)h;
    if (wantlo) *(uint2*)(lo + off) = *(const uint2*)l;
}

// ---------------------------------------------------------------------------
// QKV GEMM (3-term fp16, fused head-major f16 hi/lo epilogue, Q pre-scaled).
// CTA 128x128, 128 threads, warp tile 64x64, BK=32, 2-stage, 2 CTAs/SM.
// ---------------------------------------------------------------------------
#define AST   40
#define MAT_H (128 * AST)
#define GEMM_SMEM (8 * MAT_H * 2)   // 81920 B
#define EP_ST 68

__global__ __launch_bounds__(128, 2)
void gemm_qkv(const __half* __restrict__ Ah, const __half* __restrict__ Al,
              const __half* __restrict__ Bh, const __half* __restrict__ Bl,
              const float* __restrict__ bias,
              __half* __restrict__ Qh, __half* __restrict__ Ql,
              __half* __restrict__ Kh, __half* __restrict__ Kl,
              __half* __restrict__ Vh, int K)
{
    extern __shared__ __align__(16) __half smem_b[];
    const uint32_t sm_base = (uint32_t)__cvta_generic_to_shared(smem_b);

    const int t    = threadIdx.x;
    const int lane = t & 31;
    const int w    = t >> 5;
    const int wm   = w & 1;
    const int wn   = w >> 1;
    const int bm   = blockIdx.y * 128;
    const int bn   = blockIdx.x * 128;
    const int nk   = K >> 5;

    float acc[4][8][4];
#pragma unroll
    for (int mi = 0; mi < 4; mi++)
#pragma unroll
        for (int ni = 0; ni < 8; ni++)
#pragma unroll
            for (int q = 0; q < 4; q++) acc[mi][ni][q] = 0.f;

    const __half* gp[4] = {Ah, Al, Bh, Bl};

    auto issue = [&](int stage, int k0) {
#pragma unroll
        for (int i = 0; i < 16; i++) {
            int c = t + i * 128;
            int mat = c >> 9;
            int idx = c & 511;
            int row = idx >> 2, ck = (idx & 3) * 8;
            int base = (mat < 2) ? bm : bn;
            uint32_t so = sm_base + (uint32_t)(stage * 4 + mat) * MAT_H * 2;
            cp16(so + (uint32_t)(row * AST + ck) * 2,
                 gp[mat] + (size_t)(base + row) * K + k0 + ck);
        }
        asm volatile("cp.async.commit_group;");
    };

    issue(0, 0);
    issue(1, 32);
    asm volatile("cp.async.wait_group 1;");
    __syncthreads();

    for (int kt = 0; kt < nk; kt++) {
        const int stage = kt & 1;
        const uint32_t bAh = sm_base + (uint32_t)(stage * 4 + 0) * MAT_H * 2;
        const uint32_t bAl = sm_base + (uint32_t)(stage * 4 + 1) * MAT_H * 2;
        const uint32_t bBh = sm_base + (uint32_t)(stage * 4 + 2) * MAT_H * 2;
        const uint32_t bBl = sm_base + (uint32_t)(stage * 4 + 3) * MAT_H * 2;

#pragma unroll
        for (int ks = 0; ks < 2; ks++) {
            uint32_t ah[4][4], al[4][4], bh[8][2], bl[8][2];

            const int arow = wm * 64 + (lane & 15);
            const int acol = ks * 16 + (lane >> 4) * 8;
#pragma unroll
            for (int mi = 0; mi < 4; mi++) {
                uint32_t off = (uint32_t)((arow + mi * 16) * AST + acol) * 2;
                LDSM4(ah[mi], bAh + off);
                LDSM4(al[mi], bAl + off);
            }

            const int brow = wn * 64 + (lane >> 4) * 8 + (lane & 7);
            const int bcol = ks * 16 + ((lane >> 3) & 1) * 8;
#pragma unroll
            for (int ni2 = 0; ni2 < 4; ni2++) {
                uint32_t off = (uint32_t)((brow + ni2 * 16) * AST + bcol) * 2;
                uint32_t r[4];
                LDSM4(r, bBh + off);
                bh[ni2 * 2][0] = r[0]; bh[ni2 * 2][1] = r[1];
                bh[ni2 * 2 + 1][0] = r[2]; bh[ni2 * 2 + 1][1] = r[3];
                LDSM4(r, bBl + off);
                bl[ni2 * 2][0] = r[0]; bl[ni2 * 2][1] = r[1];
                bl[ni2 * 2 + 1][0] = r[2]; bl[ni2 * 2 + 1][1] = r[3];
            }

#pragma unroll
            for (int mi = 0; mi < 4; mi++)
#pragma unroll
                for (int ni = 0; ni < 8; ni++) {
                    MMA_F16(acc[mi][ni], ah[mi], bh[ni]);
                    MMA_F16(acc[mi][ni], al[mi], bh[ni]);
                    MMA_F16(acc[mi][ni], ah[mi], bl[ni]);
                }
        }

        asm volatile("cp.async.wait_group 0;");
        __syncthreads();
        if (kt + 2 < nk) issue(kt & 1, (kt + 2) << 5);
    }

    // fused qkv-split epilogue, smem-staged; Q,K get hi+lo, V hi only
    uint32_t* sh = (uint32_t*)smem_b;
    uint32_t* sl = sh + 128 * EP_ST;
    const int m = bn >> 10;
    const float sc = (m == 0) ? SCALING : 1.0f;

#pragma unroll
    for (int mi = 0; mi < 4; mi++) {
        const int lr0 = wm * 64 + mi * 16 + (lane >> 2);
#pragma unroll
        for (int ni = 0; ni < 8; ni++) {
            const int lcol = wn * 64 + ni * 8 + (lane & 3) * 2;
            const int colu = lcol >> 1;
            float bx = bias[bn + lcol], by = bias[bn + lcol + 1];
            float a0 = (acc[mi][ni][0] + bx) * sc;
            float a1 = (acc[mi][ni][1] + by) * sc;
            float b0 = (acc[mi][ni][2] + bx) * sc;
            float b1 = (acc[mi][ni][3] + by) * sc;
            uint32_t hp0 = packh(a0, a1);
            uint32_t hp1 = packh(b0, b1);
            sh[lr0 * EP_ST + colu] = hp0;
            sl[lr0 * EP_ST + colu] = residpackh(hp0, a0, a1);
            sh[(lr0 + 8) * EP_ST + colu] = hp1;
            sl[(lr0 + 8) * EP_ST + colu] = residpackh(hp1, b0, b1);
        }
    }
    __syncthreads();

    uint32_t* oh = (uint32_t*)((m == 0) ? Qh : (m == 1) ? Kh : Vh);
    uint32_t* ol = (uint32_t*)((m == 0) ? Ql : Kl);
    const int hh0 = (bn >> 6) & 15;
    const int bb = bm >> 10, s0 = bm & 1023;

#pragma unroll
    for (int i = 0; i < 16; i++) {
        int c = t + i * 128;
        int row = c >> 4, sub = c & 15;
        int j = sub >> 3, q4 = (sub & 7) * 4;
        size_t g = (((size_t)(bb * NH + hh0 + j)) * SEQ + s0 + row) * 32 + q4;
        uint4 vh4 = *(uint4*)&sh[row * EP_ST + j * 32 + q4];
        *(uint4*)&oh[g] = vh4;
        if (m != 2) {
            uint4 vl4 = *(uint4*)&sl[row * EP_ST + j * 32 + q4];
            *(uint4*)&ol[g] = vl4;
        }
    }
}

// ---------------------------------------------------------------------------
// Output projection GEMM (2-term: Ah,Al x Bh). 3-stage pipeline (3 mats x
// 30KB = 90KB smem, 2 CTAs/SM) to hide load latency in the single wave.
// ---------------------------------------------------------------------------
#define PST_B 30720   // 3 matrices x 10240 B per stage
#define PROJ_SMEM (3 * PST_B)   // 92160

__global__ __launch_bounds__(128, 2)
void gemm_proj(const __half* __restrict__ Ah, const __half* __restrict__ Al,
               const __half* __restrict__ Bh,
               const float* __restrict__ bias,
               float* __restrict__ C, int N, int K)
{
    extern __shared__ __align__(16) __half smem_b[];
    const uint32_t sm_base = (uint32_t)__cvta_generic_to_shared(smem_b);

    const int t    = threadIdx.x;
    const int lane = t & 31;
    const int w    = t >> 5;
    const int wm   = w & 1;
    const int wn   = w >> 1;
    const int bm   = blockIdx.y * 128;
    const int bn   = blockIdx.x * 128;
    const int nk   = K >> 5;

    float acc[4][8][4];
#pragma unroll
    for (int mi = 0; mi < 4; mi++)
#pragma unroll
        for (int ni = 0; ni < 8; ni++)
#pragma unroll
            for (int q = 0; q < 4; q++) acc[mi][ni][q] = 0.f;

    const __half* gp[3] = {Ah, Al, Bh};

    auto issue = [&](int stage, int k0) {
#pragma unroll
        for (int i = 0; i < 12; i++) {
            int c = t + i * 128;
            int mat = c >> 9;
            int idx = c & 511;
            int row = idx >> 2, ck = (idx & 3) * 8;
            int base = (mat < 2) ? bm : bn;
            uint32_t so = sm_base + (uint32_t)stage * PST_B + (uint32_t)mat * (MAT_H * 2);
            cp16(so + (uint32_t)(row * AST + ck) * 2,
                 gp[mat] + (size_t)(base + row) * K + k0 + ck);
        }
        asm volatile("cp.async.commit_group;");
    };

    issue(0, 0);
    issue(1, 32);
    asm volatile("cp.async.wait_group 1;");   // stage 0 ready
    __syncthreads();

    for (int kt = 0; kt < nk; kt++) {
        if (kt + 2 < nk) issue((kt + 2) % 3, (kt + 2) << 5);

        const uint32_t sb  = sm_base + (uint32_t)(kt % 3) * PST_B;
        const uint32_t bAh = sb;
        const uint32_t bAl = sb + MAT_H * 2;
        const uint32_t bBh = sb + 2 * (MAT_H * 2);

#pragma unroll
        for (int ks = 0; ks < 2; ks++) {
            uint32_t ah[4][4], al[4][4], bh[8][2];

            const int arow = wm * 64 + (lane & 15);
            const int acol = ks * 16 + (lane >> 4) * 8;
#pragma unroll
            for (int mi = 0; mi < 4; mi++) {
                uint32_t off = (uint32_t)((arow + mi * 16) * AST + acol) * 2;
                LDSM4(ah[mi], bAh + off);
                LDSM4(al[mi], bAl + off);
            }

            const int brow = wn * 64 + (lane >> 4) * 8 + (lane & 7);
            const int bcol = ks * 16 + ((lane >> 3) & 1) * 8;
#pragma unroll
            for (int ni2 = 0; ni2 < 4; ni2++) {
                uint32_t off = (uint32_t)((brow + ni2 * 16) * AST + bcol) * 2;
                uint32_t r[4];
                LDSM4(r, bBh + off);
                bh[ni2 * 2][0] = r[0]; bh[ni2 * 2][1] = r[1];
                bh[ni2 * 2 + 1][0] = r[2]; bh[ni2 * 2 + 1][1] = r[3];
            }

#pragma unroll
            for (int mi = 0; mi < 4; mi++)
#pragma unroll
                for (int ni = 0; ni < 8; ni++) {
                    MMA_F16(acc[mi][ni], ah[mi], bh[ni]);
                    MMA_F16(acc[mi][ni], al[mi], bh[ni]);
                }
        }

        // group kt+1 must be complete before next iter reads it
        if (kt + 2 < nk) asm volatile("cp.async.wait_group 1;");
        else             asm volatile("cp.async.wait_group 0;");
        __syncthreads();
    }

#pragma unroll
    for (int mi = 0; mi < 4; mi++) {
        const int r0 = bm + wm * 64 + mi * 16 + (lane >> 2);
#pragma unroll
        for (int ni = 0; ni < 8; ni++) {
            const int col = bn + wn * 64 + ni * 8 + (lane & 3) * 2;
            float bx = bias[col], by = bias[col + 1];
            float2 v0 = make_float2(acc[mi][ni][0] + bx, acc[mi][ni][1] + by);
            float2 v1 = make_float2(acc[mi][ni][2] + bx, acc[mi][ni][3] + by);
            *(float2*)&C[(size_t)r0 * N + col] = v0;
            *(float2*)&C[(size_t)(r0 + 8) * N + col] = v1;
        }
    }
}

// ---------------------------------------------------------------------------
// Tensor-core flash attention, fp16. BR=64, 128 threads, 3 CTAs/SM.
// S 3-term (K hi/lo), PV 2-term (V hi). K/V tile = 3 matrices.
// ---------------------------------------------------------------------------
#define AT_ST 72
#define Q_HI_B 0
#define Q_LO_B 9216
#define TILE_B 18432
#define ATT_MAT_B  9216
#define BUF_B  27648
#define ATT_SMEM (TILE_B + 2 * BUF_B)  // 73728

__global__ __launch_bounds__(128, 3)
void attn_mma(const float* __restrict__ bias, const unsigned char* __restrict__ mask,
              __half* __restrict__ outh, __half* __restrict__ outl,
              const __half* __restrict__ Qh, const __half* __restrict__ Ql,
              const __half* __restrict__ Kh, const __half* __restrict__ Kl,
              const __half* __restrict__ Vh)
{
    extern __shared__ __align__(16) __half smA[];
    const uint32_t s_base = (uint32_t)__cvta_generic_to_shared(smA);

    const int t = threadIdx.x, lane = t & 31, wid = t >> 5;
    const int qt = blockIdx.x, h = blockIdx.y, b = blockIdx.z;
    const int qbase = qt * 64;
    const size_t hb = (size_t)(b * NH + h) * SEQ * HD;

    const int lr7 = lane & 7, l8 = (lane >> 3) & 1, l16 = lane >> 4;

    const __half* qsrc[2] = {Qh, Ql};
    const __half* ksrc[3] = {Kh, Kl, Vh};

#pragma unroll
    for (int it = 0; it < 8; it++) {
        int c = t + it * 128;
        int mat = c >> 9, r = (c >> 3) & 63, ck = c & 7;
        cp16(s_base + mat * Q_LO_B + (uint32_t)(r * AT_ST + ck * 8) * 2,
             qsrc[mat] + hb + (size_t)(qbase + r) * HD + ck * 8);
    }
#pragma unroll
    for (int it = 0; it < 12; it++) {
        int c = t + it * 128;
        int mat = c >> 9, r = (c >> 3) & 63, ck = c & 7;
        cp16(s_base + TILE_B + mat * ATT_MAT_B + (uint32_t)(r * AT_ST + ck * 8) * 2,
             ksrc[mat] + hb + (size_t)r * HD + ck * 8);
    }
    asm volatile("cp.async.commit_group;");
#pragma unroll
    for (int it = 0; it < 12; it++) {
        int c = t + it * 128;
        int mat = c >> 9, r = (c >> 3) & 63, ck = c & 7;
        cp16(s_base + TILE_B + BUF_B + mat * ATT_MAT_B + (uint32_t)(r * AT_ST + ck * 8) * 2,
             ksrc[mat] + hb + (size_t)(64 + r) * HD + ck * 8);
    }
    asm volatile("cp.async.commit_group;");
    asm volatile("cp.async.wait_group 1;");
    __syncthreads();

    uint32_t aqh[4][4], aql[4][4];
    {
        const int arow = wid * 16 + (lane & 15);
        const int acol = 8 * l16;
#pragma unroll
        for (int ks = 0; ks < 4; ks++) {
            uint32_t off = (uint32_t)(arow * AT_ST + ks * 16 + acol) * 2;
            LDSM4(aqh[ks], s_base + Q_HI_B + off);
            LDSM4(aql[ks], s_base + Q_LO_B + off);
        }
    }

    float O[8][4];
#pragma unroll
    for (int nf = 0; nf < 8; nf++)
#pragma unroll
        for (int q = 0; q < 4; q++) O[nf][q] = 0.f;
    float m0 = NEG, m1 = NEG, l0 = 0.f, l1 = 0.f;

    const float* bp = bias + (size_t)(b * NH + h) * SEQ * SEQ;
    const unsigned char* mrow = mask + (size_t)b * SEQ;
    const int qr = qbase + wid * 16 + (lane >> 2);
    const int colb = 2 * (lane & 3);

    const int krow = lr7 + 8 * l16;
    const int kcol = 8 * l8;
    const int vrow = lr7 + 8 * l8;
    const int vcol = 8 * l16;

    for (int kt = 0; kt < 16; kt++) {
        const uint32_t tb = s_base + TILE_B + (uint32_t)(kt & 1) * BUF_B;

        float2 bv0[8], bv1[8];
        uchar2 mk[8];
#pragma unroll
        for (int nf = 0; nf < 8; nf++) {
            int col = kt * 64 + nf * 8 + colb;
            bv0[nf] = *(const float2*)&bp[(size_t)qr * SEQ + col];
            bv1[nf] = *(const float2*)&bp[(size_t)(qr + 8) * SEQ + col];
            mk[nf]  = *(const uchar2*)&mrow[col];
        }

        float s[8][4];
#pragma unroll
        for (int nf = 0; nf < 8; nf++)
#pragma unroll
            for (int q = 0; q < 4; q++) s[nf][q] = 0.f;

#pragma unroll
        for (int ks = 0; ks < 4; ks++) {
            uint32_t bh[8][2], bl[8][2];
#pragma unroll
            for (int nf2 = 0; nf2 < 4; nf2++) {
                uint32_t off = (uint32_t)((nf2 * 16 + krow) * AT_ST + ks * 16 + kcol) * 2;
                uint32_t r4[4];
                LDSM4(r4, tb + 0 * ATT_MAT_B + off);
                bh[2*nf2][0] = r4[0]; bh[2*nf2][1] = r4[1];
                bh[2*nf2+1][0] = r4[2]; bh[2*nf2+1][1] = r4[3];
                LDSM4(r4, tb + 1 * ATT_MAT_B + off);
                bl[2*nf2][0] = r4[0]; bl[2*nf2][1] = r4[1];
                bl[2*nf2+1][0] = r4[2]; bl[2*nf2+1][1] = r4[3];
            }
#pragma unroll
            for (int nf = 0; nf < 8; nf++) {
                MMA_F16(s[nf], aqh[ks], bh[nf]);
                MMA_F16(s[nf], aql[ks], bh[nf]);
                MMA_F16(s[nf], aqh[ks], bl[nf]);
            }
        }

#pragma unroll
        for (int nf = 0; nf < 8; nf++) {
            s[nf][0] = mk[nf].x ? NEG : s[nf][0] + bv0[nf].x;
            s[nf][1] = mk[nf].y ? NEG : s[nf][1] + bv0[nf].y;
            s[nf][2] = mk[nf].x ? NEG : s[nf][2] + bv1[nf].x;
            s[nf][3] = mk[nf].y ? NEG : s[nf][3] + bv1[nf].y;
        }

        float mx0 = NEG, mx1 = NEG;
#pragma unroll
        for (int nf = 0; nf < 8; nf++) {
            mx0 = fmaxf(mx0, fmaxf(s[nf][0], s[nf][1]));
            mx1 = fmaxf(mx1, fmaxf(s[nf][2], s[nf][3]));
        }
        mx0 = fmaxf(mx0, __shfl_xor_sync(0xffffffffu, mx0, 1));
        mx0 = fmaxf(mx0, __shfl_xor_sync(0xffffffffu, mx0, 2));
        mx1 = fmaxf(mx1, __shfl_xor_sync(0xffffffffu, mx1, 1));
        mx1 = fmaxf(mx1, __shfl_xor_sync(0xffffffffu, mx1, 2));
        float mn0 = fmaxf(m0, mx0), mn1 = fmaxf(m1, mx1);
        float sc0 = __expf(m0 - mn0), sc1 = __expf(m1 - mn1);
        m0 = mn0; m1 = mn1;
        float su0 = 0.f, su1 = 0.f;
#pragma unroll
        for (int nf = 0; nf < 8; nf++) {
            s[nf][0] = __expf(s[nf][0] - mn0);
            s[nf][1] = __expf(s[nf][1] - mn0);
            s[nf][2] = __expf(s[nf][2] - mn1);
            s[nf][3] = __expf(s[nf][3] - mn1);
            su0 += s[nf][0] + s[nf][1];
            su1 += s[nf][2] + s[nf][3];
        }
        su0 += __shfl_xor_sync(0xffffffffu, su0, 1);
        su0 += __shfl_xor_sync(0xffffffffu, su0, 2);
        su1 += __shfl_xor_sync(0xffffffffu, su1, 1);
        su1 += __shfl_xor_sync(0xffffffffu, su1, 2);
        l0 = l0 * sc0 + su0;
        l1 = l1 * sc1 + su1;
#pragma unroll
        for (int nf = 0; nf < 8; nf++) {
            O[nf][0] *= sc0; O[nf][1] *= sc0;
            O[nf][2] *= sc1; O[nf][3] *= sc1;
        }

#pragma unroll
        for (int ks = 0; ks < 4; ks++) {
            uint32_t aph[4], apl[4];
            {
                const float* p0 = s[2 * ks];
                const float* p1 = s[2 * ks + 1];
                aph[0] = packh(p0[0], p0[1]);
                aph[1] = packh(p0[2], p0[3]);
                aph[2] = packh(p1[0], p1[1]);
                aph[3] = packh(p1[2], p1[3]);
                apl[0] = residpackh(aph[0], p0[0], p0[1]);
                apl[1] = residpackh(aph[1], p0[2], p0[3]);
                apl[2] = residpackh(aph[2], p1[0], p1[1]);
                apl[3] = residpackh(aph[3], p1[2], p1[3]);
            }
            uint32_t vh[8][2];
#pragma unroll
            for (int nf2 = 0; nf2 < 4; nf2++) {
                uint32_t off = (uint32_t)((ks * 16 + vrow) * AT_ST + nf2 * 16 + vcol) * 2;
                uint32_t r4[4];
                LDSM4T(r4, tb + 2 * ATT_MAT_B + off);
                vh[2*nf2][0] = r4[0]; vh[2*nf2][1] = r4[1];
                vh[2*nf2+1][0] = r4[2]; vh[2*nf2+1][1] = r4[3];
            }
#pragma unroll
            for (int nf = 0; nf < 8; nf++) {
                MMA_F16(O[nf], aph, vh[nf]);
                MMA_F16(O[nf], apl, vh[nf]);
            }
        }

        asm volatile("cp.async.wait_group 0;");
        __syncthreads();
        if (kt + 2 < 16) {
#pragma unroll
            for (int it = 0; it < 12; it++) {
                int c = t + it * 128;
                int mat = c >> 9, r = (c >> 3) & 63, ck = c & 7;
                cp16(s_base + TILE_B + (uint32_t)(kt & 1) * BUF_B + mat * ATT_MAT_B +
                         (uint32_t)(r * AT_ST + ck * 8) * 2,
                     ksrc[mat] + hb + (size_t)((kt + 2) * 64 + r) * HD + ck * 8);
            }
            asm volatile("cp.async.commit_group;");
        }
    }

    float i0 = 1.f / l0, i1 = 1.f / l1;
    int orow = b * SEQ + qbase + wid * 16 + (lane >> 2);
    uint32_t* oh = (uint32_t*)outh;
    uint32_t* ol = (uint32_t*)outl;
#pragma unroll
    for (int nf = 0; nf < 8; nf++) {
        int col = h * HD + nf * 8 + colb;
        float a0 = O[nf][0] * i0, a1 = O[nf][1] * i0;
        float b0 = O[nf][2] * i1, b1 = O[nf][3] * i1;
        uint32_t h0 = packh(a0, a1);
        uint32_t l0r = residpackh(h0, a0, a1);
        uint32_t h1 = packh(b0, b1);
        uint32_t l1r = residpackh(h1, b0, b1);
        size_t idx0 = ((size_t)orow * EMB + col) >> 1;
        size_t idx1 = ((size_t)(orow + 8) * EMB + col) >> 1;
        oh[idx0] = h0; ol[idx0] = l0r;
        oh[idx1] = h1; ol[idx1] = l1r;
    }
}

// ---------------------------------------------------------------------------
extern "C" void kernel_launch(void* const* d_in, const int* in_sizes, int n_in,
                              void* d_out, int out_size)
{
    const float* query         = (const float*)d_in[0];
    const unsigned char* maskp = (const unsigned char*)d_in[1];
    const float* attn_bias     = (const float*)d_in[2];
    const float* Wqkv          = (const float*)d_in[3];
    const float* bqkv          = (const float*)d_in[4];
    const float* Wo            = (const float*)d_in[5];
    const float* bo            = (const float*)d_in[6];
    float* out                 = (float*)d_out;

    __half *Ahi, *Alo, *W1hi, *W1lo, *W2hi, *Thi, *Tlo;
    __half *Qh, *Ql, *Kh, *Kl, *Vh;
    cudaGetSymbolAddress((void**)&Ahi,  g_A_hi);
    cudaGetSymbolAddress((void**)&Alo,  g_A_lo);
    cudaGetSymbolAddress((void**)&W1hi, g_W1_hi);
    cudaGetSymbolAddress((void**)&W1lo, g_W1_lo);
    cudaGetSymbolAddress((void**)&W2hi, g_W2_hi);
    cudaGetSymbolAddress((void**)&Thi,  g_att_hi);
    cudaGetSymbolAddress((void**)&Tlo,  g_att_lo);
    cudaGetSymbolAddress((void**)&Qh,   g_Qh);
    cudaGetSymbolAddress((void**)&Ql,   g_Ql);
    cudaGetSymbolAddress((void**)&Kh,   g_Kh);
    cudaGetSymbolAddress((void**)&Kl,   g_Kl);
    cudaGetSymbolAddress((void**)&Vh,   g_Vh);

    cudaFuncSetAttribute(gemm_qkv,
                         cudaFuncAttributeMaxDynamicSharedMemorySize, GEMM_SMEM);
    cudaFuncSetAttribute(gemm_proj,
                         cudaFuncAttributeMaxDynamicSharedMemorySize, PROJ_SMEM);
    cudaFuncSetAttribute(attn_mma,
                         cudaFuncAttributeMaxDynamicSharedMemorySize, ATT_SMEM);

    // 0) split query + Wqkv (hi/lo) + Wo (hi) — one launch
    split_all<<<NSPLIT / 1024, 256>>>(query, Wqkv, Wo,
                                      Ahi, Alo, W1hi, W1lo, W2hi);

    // 1) QKV projection (3-term), fused head-major f16 epilogue
    {
        dim3 grid(3 * EMB / 128, MTOT / 128);
        gemm_qkv<<<grid, 128, GEMM_SMEM>>>(Ahi, Alo, W1hi, W1lo, bqkv,
                                           Qh, Ql, Kh, Kl, Vh, EMB);
    }

    // 2) flash attention (S 3-term, PV 2-term), 3 CTAs/SM
    {
        dim3 grid(SEQ / 64, NH, BATCH);
        attn_mma<<<grid, 128, ATT_SMEM>>>(attn_bias, maskp, Thi, Tlo,
                                          Qh, Ql, Kh, Kl, Vh);
    }

    // 3) output projection (2-term, 3-stage pipeline, f32 epilogue)
    {
        dim3 grid(EMB / 128, MTOT / 128);
        gemm_proj<<<grid, 128, PROJ_SMEM>>>(Thi, Tlo, W2hi, bo, out, EMB, EMB);
    }
}

// round 16
// speedup vs baseline: 1.8444x; 1.0222x over previous
#include <cuda_runtime.h>
#include <cuda_fp16.h>
#include <cstdint>

// Problem constants
#define EMB   1024
#define NH    16
#define HD    64
#define BATCH 4
#define SEQ   1024
#define MTOT  (BATCH*SEQ)
#define SCALING 0.3952847075210474f   // (64*0.1)^-0.5
#define NEG   (-1e30f)

#define NQ_ELEM  (MTOT * EMB)
#define NW1_ELEM (3 * EMB * EMB)
#define NW2_ELEM (EMB * EMB)
#define NSPLIT   (NQ_ELEM + NW1_ELEM + NW2_ELEM)

// Scratch (device globals) — fp16
__device__ __half g_A_hi[MTOT * EMB];
__device__ __half g_A_lo[MTOT * EMB];
__device__ __half g_W1_hi[3 * EMB * EMB];
__device__ __half g_W1_lo[3 * EMB * EMB];
__device__ __half g_W2_hi[EMB * EMB];
__device__ __half g_att_hi[MTOT * EMB];
__device__ __half g_att_lo[MTOT * EMB];
__device__ __half g_Qh[MTOT * EMB];
__device__ __half g_Ql[MTOT * EMB];
__device__ __half g_Kh[MTOT * EMB];
__device__ __half g_Kl[MTOT * EMB];
__device__ __half g_Vh[MTOT * EMB];

// ---------------------------------------------------------------------------
// PTX helpers
// ---------------------------------------------------------------------------
#define LDSM4(r, addr) \
    asm volatile("ldmatrix.sync.aligned.m8n8.x4.shared.b16 {%0,%1,%2,%3}, [%4];" \
                 : "=r"((r)[0]), "=r"((r)[1]), "=r"((r)[2]), "=r"((r)[3]) : "r"(addr))

#define LDSM4T(r, addr) \
    asm volatile("ldmatrix.sync.aligned.m8n8.x4.trans.shared.b16 {%0,%1,%2,%3}, [%4];" \
                 : "=r"((r)[0]), "=r"((r)[1]), "=r"((r)[2]), "=r"((r)[3]) : "r"(addr))

#define MMA_F16(d, a, b) \
    asm volatile("mma.sync.aligned.m16n8k16.row.col.f32.f16.f16.f32 " \
                 "{%0,%1,%2,%3},{%4,%5,%6,%7},{%8,%9},{%0,%1,%2,%3};" \
                 : "+f"((d)[0]), "+f"((d)[1]), "+f"((d)[2]), "+f"((d)[3]) \
                 : "r"((a)[0]), "r"((a)[1]), "r"((a)[2]), "r"((a)[3]), \
                   "r"((b)[0]), "r"((b)[1]))

__device__ __forceinline__ void cp16(uint32_t s, const void* g) {
    asm volatile("cp.async.cg.shared.global [%0], [%1], 16;" :: "r"(s), "l"(g));
}

__device__ __forceinline__ uint32_t packh(float lo, float hi) {
    uint32_t r;
    asm("cvt.rn.f16x2.f32 %0, %1, %2;" : "=r"(r) : "f"(hi), "f"(lo));
    return r;
}
__device__ __forceinline__ uint32_t residpackh(uint32_t ph, float lo, float hi) {
    __half2 h = *(__half2*)&ph;
    return packh(lo - __low2float(h), hi - __high2float(h));
}

// ---------------------------------------------------------------------------
// merged f32 -> f16 (hi, lo) split: query, Wqkv (hi+lo); Wo (hi only)
// ---------------------------------------------------------------------------
__global__ __launch_bounds__(256)
void split_all(const float* __restrict__ q, const float* __restrict__ w1,
               const float* __restrict__ w2,
               __half* __restrict__ Ahi, __half* __restrict__ Alo,
               __half* __restrict__ W1hi, __half* __restrict__ W1lo,
               __half* __restrict__ W2hi)
{
    int i = (blockIdx.x * 256 + threadIdx.x) * 4;
    const float* src;
    __half *hi, *lo;
    int off;
    bool wantlo = true;
    if (i < NQ_ELEM)                { src = q;  hi = Ahi;  lo = Alo;  off = i; }
    else if (i < NQ_ELEM + NW1_ELEM){ src = w1; hi = W1hi; lo = W1lo; off = i - NQ_ELEM; }
    else { src = w2; hi = W2hi; lo = nullptr; off = i - NQ_ELEM - NW1_ELEM; wantlo = false; }

    float4 v = *(const float4*)(src + off);
    float f[4] = {v.x, v.y, v.z, v.w};
    __half h[4], l[4];
#pragma unroll
    for (int j = 0; j < 4; j++) {
        h[j] = __float2half(f[j]);
        l[j] = __float2half(f[j] - __half2float(h[j]));
    }
    *(uint2*)(hi + off) = *(const uint2*)h;
    if (wantlo) *(uint2*)(lo + off) = *(const uint2*)l;
}

// ---------------------------------------------------------------------------
// QKV GEMM (3-term fp16, fused head-major f16 hi/lo epilogue, Q pre-scaled).
// CTA 128x128, 128 threads, warp tile 64x64, BK=32, 2-stage, 2 CTAs/SM.
// ---------------------------------------------------------------------------
#define AST   40
#define MAT_H (128 * AST)
#define GEMM_SMEM (8 * MAT_H * 2)   // 81920 B
#define EP_ST 68

__global__ __launch_bounds__(128, 2)
void gemm_qkv(const __half* __restrict__ Ah, const __half* __restrict__ Al,
              const __half* __restrict__ Bh, const __half* __restrict__ Bl,
              const float* __restrict__ bias,
              __half* __restrict__ Qh, __half* __restrict__ Ql,
              __half* __restrict__ Kh, __half* __restrict__ Kl,
              __half* __restrict__ Vh, int K)
{
    extern __shared__ __align__(16) __half smem_b[];
    const uint32_t sm_base = (uint32_t)__cvta_generic_to_shared(smem_b);

    const int t    = threadIdx.x;
    const int lane = t & 31;
    const int w    = t >> 5;
    const int wm   = w & 1;
    const int wn   = w >> 1;
    const int bm   = blockIdx.y * 128;
    const int bn   = blockIdx.x * 128;
    const int nk   = K >> 5;

    float acc[4][8][4];
#pragma unroll
    for (int mi = 0; mi < 4; mi++)
#pragma unroll
        for (int ni = 0; ni < 8; ni++)
#pragma unroll
            for (int q = 0; q < 4; q++) acc[mi][ni][q] = 0.f;

    const __half* gp[4] = {Ah, Al, Bh, Bl};

    auto issue = [&](int stage, int k0) {
#pragma unroll
        for (int i = 0; i < 16; i++) {
            int c = t + i * 128;
            int mat = c >> 9;
            int idx = c & 511;
            int row = idx >> 2, ck = (idx & 3) * 8;
            int base = (mat < 2) ? bm : bn;
            uint32_t so = sm_base + (uint32_t)(stage * 4 + mat) * MAT_H * 2;
            cp16(so + (uint32_t)(row * AST + ck) * 2,
                 gp[mat] + (size_t)(base + row) * K + k0 + ck);
        }
        asm volatile("cp.async.commit_group;");
    };

    issue(0, 0);
    issue(1, 32);
    asm volatile("cp.async.wait_group 1;");
    __syncthreads();

    for (int kt = 0; kt < nk; kt++) {
        const int stage = kt & 1;
        const uint32_t bAh = sm_base + (uint32_t)(stage * 4 + 0) * MAT_H * 2;
        const uint32_t bAl = sm_base + (uint32_t)(stage * 4 + 1) * MAT_H * 2;
        const uint32_t bBh = sm_base + (uint32_t)(stage * 4 + 2) * MAT_H * 2;
        const uint32_t bBl = sm_base + (uint32_t)(stage * 4 + 3) * MAT_H * 2;

#pragma unroll
        for (int ks = 0; ks < 2; ks++) {
            uint32_t ah[4][4], al[4][4], bh[8][2], bl[8][2];

            const int arow = wm * 64 + (lane & 15);
            const int acol = ks * 16 + (lane >> 4) * 8;
#pragma unroll
            for (int mi = 0; mi < 4; mi++) {
                uint32_t off = (uint32_t)((arow + mi * 16) * AST + acol) * 2;
                LDSM4(ah[mi], bAh + off);
                LDSM4(al[mi], bAl + off);
            }

            const int brow = wn * 64 + (lane >> 4) * 8 + (lane & 7);
            const int bcol = ks * 16 + ((lane >> 3) & 1) * 8;
#pragma unroll
            for (int ni2 = 0; ni2 < 4; ni2++) {
                uint32_t off = (uint32_t)((brow + ni2 * 16) * AST + bcol) * 2;
                uint32_t r[4];
                LDSM4(r, bBh + off);
                bh[ni2 * 2][0] = r[0]; bh[ni2 * 2][1] = r[1];
                bh[ni2 * 2 + 1][0] = r[2]; bh[ni2 * 2 + 1][1] = r[3];
                LDSM4(r, bBl + off);
                bl[ni2 * 2][0] = r[0]; bl[ni2 * 2][1] = r[1];
                bl[ni2 * 2 + 1][0] = r[2]; bl[ni2 * 2 + 1][1] = r[3];
            }

#pragma unroll
            for (int mi = 0; mi < 4; mi++)
#pragma unroll
                for (int ni = 0; ni < 8; ni++) {
                    MMA_F16(acc[mi][ni], ah[mi], bh[ni]);
                    MMA_F16(acc[mi][ni], al[mi], bh[ni]);
                    MMA_F16(acc[mi][ni], ah[mi], bl[ni]);
                }
        }

        asm volatile("cp.async.wait_group 0;");
        __syncthreads();
        if (kt + 2 < nk) issue(kt & 1, (kt + 2) << 5);
    }

    // fused qkv-split epilogue, smem-staged; Q,K get hi+lo, V hi only
    uint32_t* sh = (uint32_t*)smem_b;
    uint32_t* sl = sh + 128 * EP_ST;
    const int m = bn >> 10;
    const float sc = (m == 0) ? SCALING : 1.0f;

#pragma unroll
    for (int mi = 0; mi < 4; mi++) {
        const int lr0 = wm * 64 + mi * 16 + (lane >> 2);
#pragma unroll
        for (int ni = 0; ni < 8; ni++) {
            const int lcol = wn * 64 + ni * 8 + (lane & 3) * 2;
            const int colu = lcol >> 1;
            float bx = bias[bn + lcol], by = bias[bn + lcol + 1];
            float a0 = (acc[mi][ni][0] + bx) * sc;
            float a1 = (acc[mi][ni][1] + by) * sc;
            float b0 = (acc[mi][ni][2] + bx) * sc;
            float b1 = (acc[mi][ni][3] + by) * sc;
            uint32_t hp0 = packh(a0, a1);
            uint32_t hp1 = packh(b0, b1);
            sh[lr0 * EP_ST + colu] = hp0;
            sl[lr0 * EP_ST + colu] = residpackh(hp0, a0, a1);
            sh[(lr0 + 8) * EP_ST + colu] = hp1;
            sl[(lr0 + 8) * EP_ST + colu] = residpackh(hp1, b0, b1);
        }
    }
    __syncthreads();

    uint32_t* oh = (uint32_t*)((m == 0) ? Qh : (m == 1) ? Kh : Vh);
    uint32_t* ol = (uint32_t*)((m == 0) ? Ql : Kl);
    const int hh0 = (bn >> 6) & 15;
    const int bb = bm >> 10, s0 = bm & 1023;

#pragma unroll
    for (int i = 0; i < 16; i++) {
        int c = t + i * 128;
        int row = c >> 4, sub = c & 15;
        int j = sub >> 3, q4 = (sub & 7) * 4;
        size_t g = (((size_t)(bb * NH + hh0 + j)) * SEQ + s0 + row) * 32 + q4;
        uint4 vh4 = *(uint4*)&sh[row * EP_ST + j * 32 + q4];
        *(uint4*)&oh[g] = vh4;
        if (m != 2) {
            uint4 vl4 = *(uint4*)&sl[row * EP_ST + j * 32 + q4];
            *(uint4*)&ol[g] = vl4;
        }
    }
}

// ---------------------------------------------------------------------------
// Output projection GEMM (2-term). 3-stage pipeline, 2 CTAs/SM.
// ---------------------------------------------------------------------------
#define PST_B 30720
#define PROJ_SMEM (3 * PST_B)   // 92160

__global__ __launch_bounds__(128, 2)
void gemm_proj(const __half* __restrict__ Ah, const __half* __restrict__ Al,
               const __half* __restrict__ Bh,
               const float* __restrict__ bias,
               float* __restrict__ C, int N, int K)
{
    extern __shared__ __align__(16) __half smem_b[];
    const uint32_t sm_base = (uint32_t)__cvta_generic_to_shared(smem_b);

    const int t    = threadIdx.x;
    const int lane = t & 31;
    const int w    = t >> 5;
    const int wm   = w & 1;
    const int wn   = w >> 1;
    const int bm   = blockIdx.y * 128;
    const int bn   = blockIdx.x * 128;
    const int nk   = K >> 5;

    float acc[4][8][4];
#pragma unroll
    for (int mi = 0; mi < 4; mi++)
#pragma unroll
        for (int ni = 0; ni < 8; ni++)
#pragma unroll
            for (int q = 0; q < 4; q++) acc[mi][ni][q] = 0.f;

    const __half* gp[3] = {Ah, Al, Bh};

    auto issue = [&](int stage, int k0) {
#pragma unroll
        for (int i = 0; i < 12; i++) {
            int c = t + i * 128;
            int mat = c >> 9;
            int idx = c & 511;
            int row = idx >> 2, ck = (idx & 3) * 8;
            int base = (mat < 2) ? bm : bn;
            uint32_t so = sm_base + (uint32_t)stage * PST_B + (uint32_t)mat * (MAT_H * 2);
            cp16(so + (uint32_t)(row * AST + ck) * 2,
                 gp[mat] + (size_t)(base + row) * K + k0 + ck);
        }
        asm volatile("cp.async.commit_group;");
    };

    issue(0, 0);
    issue(1, 32);
    asm volatile("cp.async.wait_group 1;");
    __syncthreads();

    for (int kt = 0; kt < nk; kt++) {
        if (kt + 2 < nk) issue((kt + 2) % 3, (kt + 2) << 5);

        const uint32_t sb  = sm_base + (uint32_t)(kt % 3) * PST_B;
        const uint32_t bAh = sb;
        const uint32_t bAl = sb + MAT_H * 2;
        const uint32_t bBh = sb + 2 * (MAT_H * 2);

#pragma unroll
        for (int ks = 0; ks < 2; ks++) {
            uint32_t ah[4][4], al[4][4], bh[8][2];

            const int arow = wm * 64 + (lane & 15);
            const int acol = ks * 16 + (lane >> 4) * 8;
#pragma unroll
            for (int mi = 0; mi < 4; mi++) {
                uint32_t off = (uint32_t)((arow + mi * 16) * AST + acol) * 2;
                LDSM4(ah[mi], bAh + off);
                LDSM4(al[mi], bAl + off);
            }

            const int brow = wn * 64 + (lane >> 4) * 8 + (lane & 7);
            const int bcol = ks * 16 + ((lane >> 3) & 1) * 8;
#pragma unroll
            for (int ni2 = 0; ni2 < 4; ni2++) {
                uint32_t off = (uint32_t)((brow + ni2 * 16) * AST + bcol) * 2;
                uint32_t r[4];
                LDSM4(r, bBh + off);
                bh[ni2 * 2][0] = r[0]; bh[ni2 * 2][1] = r[1];
                bh[ni2 * 2 + 1][0] = r[2]; bh[ni2 * 2 + 1][1] = r[3];
            }

#pragma unroll
            for (int mi = 0; mi < 4; mi++)
#pragma unroll
                for (int ni = 0; ni < 8; ni++) {
                    MMA_F16(acc[mi][ni], ah[mi], bh[ni]);
                    MMA_F16(acc[mi][ni], al[mi], bh[ni]);
                }
        }

        if (kt + 2 < nk) asm volatile("cp.async.wait_group 1;");
        else             asm volatile("cp.async.wait_group 0;");
        __syncthreads();
    }

#pragma unroll
    for (int mi = 0; mi < 4; mi++) {
        const int r0 = bm + wm * 64 + mi * 16 + (lane >> 2);
#pragma unroll
        for (int ni = 0; ni < 8; ni++) {
            const int col = bn + wn * 64 + ni * 8 + (lane & 3) * 2;
            float bx = bias[col], by = bias[col + 1];
            float2 v0 = make_float2(acc[mi][ni][0] + bx, acc[mi][ni][1] + by);
            float2 v1 = make_float2(acc[mi][ni][2] + bx, acc[mi][ni][3] + by);
            *(float2*)&C[(size_t)r0 * N + col] = v0;
            *(float2*)&C[(size_t)(r0 + 8) * N + col] = v1;
        }
    }
}

// ---------------------------------------------------------------------------
// Tensor-core flash attention (R14 config: no occupancy cap -> 2 CTAs/SM).
// S 3-term (K hi/lo), PV 2-term (V hi). K/V tile = 3 matrices.
// ---------------------------------------------------------------------------
#define AT_ST 72
#define Q_HI_B 0
#define Q_LO_B 9216
#define TILE_B 18432
#define ATT_MAT_B  9216
#define BUF_B  27648
#define ATT_SMEM (TILE_B + 2 * BUF_B)  // 73728

__global__ __launch_bounds__(128)
void attn_mma(const float* __restrict__ bias, const unsigned char* __restrict__ mask,
              __half* __restrict__ outh, __half* __restrict__ outl,
              const __half* __restrict__ Qh, const __half* __restrict__ Ql,
              const __half* __restrict__ Kh, const __half* __restrict__ Kl,
              const __half* __restrict__ Vh)
{
    extern __shared__ __align__(16) __half smA[];
    const uint32_t s_base = (uint32_t)__cvta_generic_to_shared(smA);

    const int t = threadIdx.x, lane = t & 31, wid = t >> 5;
    const int qt = blockIdx.x, h = blockIdx.y, b = blockIdx.z;
    const int qbase = qt * 64;
    const size_t hb = (size_t)(b * NH + h) * SEQ * HD;

    const int lr7 = lane & 7, l8 = (lane >> 3) & 1, l16 = lane >> 4;

    const __half* qsrc[2] = {Qh, Ql};
    const __half* ksrc[3] = {Kh, Kl, Vh};

#pragma unroll
    for (int it = 0; it < 8; it++) {
        int c = t + it * 128;
        int mat = c >> 9, r = (c >> 3) & 63, ck = c & 7;
        cp16(s_base + mat * Q_LO_B + (uint32_t)(r * AT_ST + ck * 8) * 2,
             qsrc[mat] + hb + (size_t)(qbase + r) * HD + ck * 8);
    }
#pragma unroll
    for (int it = 0; it < 12; it++) {
        int c = t + it * 128;
        int mat = c >> 9, r = (c >> 3) & 63, ck = c & 7;
        cp16(s_base + TILE_B + mat * ATT_MAT_B + (uint32_t)(r * AT_ST + ck * 8) * 2,
             ksrc[mat] + hb + (size_t)r * HD + ck * 8);
    }
    asm volatile("cp.async.commit_group;");
#pragma unroll
    for (int it = 0; it < 12; it++) {
        int c = t + it * 128;
        int mat = c >> 9, r = (c >> 3) & 63, ck = c & 7;
        cp16(s_base + TILE_B + BUF_B + mat * ATT_MAT_B + (uint32_t)(r * AT_ST + ck * 8) * 2,
             ksrc[mat] + hb + (size_t)(64 + r) * HD + ck * 8);
    }
    asm volatile("cp.async.commit_group;");
    asm volatile("cp.async.wait_group 1;");
    __syncthreads();

    uint32_t aqh[4][4], aql[4][4];
    {
        const int arow = wid * 16 + (lane & 15);
        const int acol = 8 * l16;
#pragma unroll
        for (int ks = 0; ks < 4; ks++) {
            uint32_t off = (uint32_t)(arow * AT_ST + ks * 16 + acol) * 2;
            LDSM4(aqh[ks], s_base + Q_HI_B + off);
            LDSM4(aql[ks], s_base + Q_LO_B + off);
        }
    }

    float O[8][4];
#pragma unroll
    for (int nf = 0; nf < 8; nf++)
#pragma unroll
        for (int q = 0; q < 4; q++) O[nf][q] = 0.f;
    float m0 = NEG, m1 = NEG, l0 = 0.f, l1 = 0.f;

    const float* bp = bias + (size_t)(b * NH + h) * SEQ * SEQ;
    const unsigned char* mrow = mask + (size_t)b * SEQ;
    const int qr = qbase + wid * 16 + (lane >> 2);
    const int colb = 2 * (lane & 3);

    const int krow = lr7 + 8 * l16;
    const int kcol = 8 * l8;
    const int vrow = lr7 + 8 * l8;
    const int vcol = 8 * l16;

    for (int kt = 0; kt < 16; kt++) {
        const uint32_t tb = s_base + TILE_B + (uint32_t)(kt & 1) * BUF_B;

        float2 bv0[8], bv1[8];
        uchar2 mk[8];
#pragma unroll
        for (int nf = 0; nf < 8; nf++) {
            int col = kt * 64 + nf * 8 + colb;
            bv0[nf] = *(const float2*)&bp[(size_t)qr * SEQ + col];
            bv1[nf] = *(const float2*)&bp[(size_t)(qr + 8) * SEQ + col];
            mk[nf]  = *(const uchar2*)&mrow[col];
        }

        float s[8][4];
#pragma unroll
        for (int nf = 0; nf < 8; nf++)
#pragma unroll
            for (int q = 0; q < 4; q++) s[nf][q] = 0.f;

#pragma unroll
        for (int ks = 0; ks < 4; ks++) {
            uint32_t bh[8][2], bl[8][2];
#pragma unroll
            for (int nf2 = 0; nf2 < 4; nf2++) {
                uint32_t off = (uint32_t)((nf2 * 16 + krow) * AT_ST + ks * 16 + kcol) * 2;
                uint32_t r4[4];
                LDSM4(r4, tb + 0 * ATT_MAT_B + off);
                bh[2*nf2][0] = r4[0]; bh[2*nf2][1] = r4[1];
                bh[2*nf2+1][0] = r4[2]; bh[2*nf2+1][1] = r4[3];
                LDSM4(r4, tb + 1 * ATT_MAT_B + off);
                bl[2*nf2][0] = r4[0]; bl[2*nf2][1] = r4[1];
                bl[2*nf2+1][0] = r4[2]; bl[2*nf2+1][1] = r4[3];
            }
#pragma unroll
            for (int nf = 0; nf < 8; nf++) {
                MMA_F16(s[nf], aqh[ks], bh[nf]);
                MMA_F16(s[nf], aql[ks], bh[nf]);
                MMA_F16(s[nf], aqh[ks], bl[nf]);
            }
        }

#pragma unroll
        for (int nf = 0; nf < 8; nf++) {
            s[nf][0] = mk[nf].x ? NEG : s[nf][0] + bv0[nf].x;
            s[nf][1] = mk[nf].y ? NEG : s[nf][1] + bv0[nf].y;
            s[nf][2] = mk[nf].x ? NEG : s[nf][2] + bv1[nf].x;
            s[nf][3] = mk[nf].y ? NEG : s[nf][3] + bv1[nf].y;
        }

        float mx0 = NEG, mx1 = NEG;
#pragma unroll
        for (int nf = 0; nf < 8; nf++) {
            mx0 = fmaxf(mx0, fmaxf(s[nf][0], s[nf][1]));
            mx1 = fmaxf(mx1, fmaxf(s[nf][2], s[nf][3]));
        }
        mx0 = fmaxf(mx0, __shfl_xor_sync(0xffffffffu, mx0, 1));
        mx0 = fmaxf(mx0, __shfl_xor_sync(0xffffffffu, mx0, 2));
        mx1 = fmaxf(mx1, __shfl_xor_sync(0xffffffffu, mx1, 1));
        mx1 = fmaxf(mx1, __shfl_xor_sync(0xffffffffu, mx1, 2));
        float mn0 = fmaxf(m0, mx0), mn1 = fmaxf(m1, mx1);
        float sc0 = __expf(m0 - mn0), sc1 = __expf(m1 - mn1);
        m0 = mn0; m1 = mn1;
        float su0 = 0.f, su1 = 0.f;
#pragma unroll
        for (int nf = 0; nf < 8; nf++) {
            s[nf][0] = __expf(s[nf][0] - mn0);
            s[nf][1] = __expf(s[nf][1] - mn0);
            s[nf][2] = __expf(s[nf][2] - mn1);
            s[nf][3] = __expf(s[nf][3] - mn1);
            su0 += s[nf][0] + s[nf][1];
            su1 += s[nf][2] + s[nf][3];
        }
        su0 += __shfl_xor_sync(0xffffffffu, su0, 1);
        su0 += __shfl_xor_sync(0xffffffffu, su0, 2);
        su1 += __shfl_xor_sync(0xffffffffu, su1, 1);
        su1 += __shfl_xor_sync(0xffffffffu, su1, 2);
        l0 = l0 * sc0 + su0;
        l1 = l1 * sc1 + su1;
#pragma unroll
        for (int nf = 0; nf < 8; nf++) {
            O[nf][0] *= sc0; O[nf][1] *= sc0;
            O[nf][2] *= sc1; O[nf][3] *= sc1;
        }

#pragma unroll
        for (int ks = 0; ks < 4; ks++) {
            uint32_t aph[4], apl[4];
            {
                const float* p0 = s[2 * ks];
                const float* p1 = s[2 * ks + 1];
                aph[0] = packh(p0[0], p0[1]);
                aph[1] = packh(p0[2], p0[3]);
                aph[2] = packh(p1[0], p1[1]);
                aph[3] = packh(p1[2], p1[3]);
                apl[0] = residpackh(aph[0], p0[0], p0[1]);
                apl[1] = residpackh(aph[1], p0[2], p0[3]);
                apl[2] = residpackh(aph[2], p1[0], p1[1]);
                apl[3] = residpackh(aph[3], p1[2], p1[3]);
            }
            uint32_t vh[8][2];
#pragma unroll
            for (int nf2 = 0; nf2 < 4; nf2++) {
                uint32_t off = (uint32_t)((ks * 16 + vrow) * AT_ST + nf2 * 16 + vcol) * 2;
                uint32_t r4[4];
                LDSM4T(r4, tb + 2 * ATT_MAT_B + off);
                vh[2*nf2][0] = r4[0]; vh[2*nf2][1] = r4[1];
                vh[2*nf2+1][0] = r4[2]; vh[2*nf2+1][1] = r4[3];
            }
#pragma unroll
            for (int nf = 0; nf < 8; nf++) {
                MMA_F16(O[nf], aph, vh[nf]);
                MMA_F16(O[nf], apl, vh[nf]);
            }
        }

        asm volatile("cp.async.wait_group 0;");
        __syncthreads();
        if (kt + 2 < 16) {
#pragma unroll
            for (int it = 0; it < 12; it++) {
                int c = t + it * 128;
                int mat = c >> 9, r = (c >> 3) & 63, ck = c & 7;
                cp16(s_base + TILE_B + (uint32_t)(kt & 1) * BUF_B + mat * ATT_MAT_B +
                         (uint32_t)(r * AT_ST + ck * 8) * 2,
                     ksrc[mat] + hb + (size_t)((kt + 2) * 64 + r) * HD + ck * 8);
            }
            asm volatile("cp.async.commit_group;");
        }
    }

    float i0 = 1.f / l0, i1 = 1.f / l1;
    int orow = b * SEQ + qbase + wid * 16 + (lane >> 2);
    uint32_t* oh = (uint32_t*)outh;
    uint32_t* ol = (uint32_t*)outl;
#pragma unroll
    for (int nf = 0; nf < 8; nf++) {
        int col = h * HD + nf * 8 + colb;
        float a0 = O[nf][0] * i0, a1 = O[nf][1] * i0;
        float b0 = O[nf][2] * i1, b1 = O[nf][3] * i1;
        uint32_t h0 = packh(a0, a1);
        uint32_t l0r = residpackh(h0, a0, a1);
        uint32_t h1 = packh(b0, b1);
        uint32_t l1r = residpackh(h1, b0, b1);
        size_t idx0 = ((size_t)orow * EMB + col) >> 1;
        size_t idx1 = ((size_t)(orow + 8) * EMB + col) >> 1;
        oh[idx0] = h0; ol[idx0] = l0r;
        oh[idx1] = h1; ol[idx1] = l1r;
    }
}

// ---------------------------------------------------------------------------
extern "C" void kernel_launch(void* const* d_in, const int* in_sizes, int n_in,
                              void* d_out, int out_size)
{
    const float* query         = (const float*)d_in[0];
    const unsigned char* maskp = (const unsigned char*)d_in[1];
    const float* attn_bias     = (const float*)d_in[2];
    const float* Wqkv          = (const float*)d_in[3];
    const float* bqkv          = (const float*)d_in[4];
    const float* Wo            = (const float*)d_in[5];
    const float* bo            = (const float*)d_in[6];
    float* out                 = (float*)d_out;

    __half *Ahi, *Alo, *W1hi, *W1lo, *W2hi, *Thi, *Tlo;
    __half *Qh, *Ql, *Kh, *Kl, *Vh;
    cudaGetSymbolAddress((void**)&Ahi,  g_A_hi);
    cudaGetSymbolAddress((void**)&Alo,  g_A_lo);
    cudaGetSymbolAddress((void**)&W1hi, g_W1_hi);
    cudaGetSymbolAddress((void**)&W1lo, g_W1_lo);
    cudaGetSymbolAddress((void**)&W2hi, g_W2_hi);
    cudaGetSymbolAddress((void**)&Thi,  g_att_hi);
    cudaGetSymbolAddress((void**)&Tlo,  g_att_lo);
    cudaGetSymbolAddress((void**)&Qh,   g_Qh);
    cudaGetSymbolAddress((void**)&Ql,   g_Ql);
    cudaGetSymbolAddress((void**)&Kh,   g_Kh);
    cudaGetSymbolAddress((void**)&Kl,   g_Kl);
    cudaGetSymbolAddress((void**)&Vh,   g_Vh);

    cudaFuncSetAttribute(gemm_qkv,
                         cudaFuncAttributeMaxDynamicSharedMemorySize, GEMM_SMEM);
    cudaFuncSetAttribute(gemm_proj,
                         cudaFuncAttributeMaxDynamicSharedMemorySize, PROJ_SMEM);
    cudaFuncSetAttribute(attn_mma,
                         cudaFuncAttributeMaxDynamicSharedMemorySize, ATT_SMEM);

    // 0) split query + Wqkv (hi/lo) + Wo (hi) — one launch
    split_all<<<NSPLIT / 1024, 256>>>(query, Wqkv, Wo,
                                      Ahi, Alo, W1hi, W1lo, W2hi);

    // 1) QKV projection (3-term), fused head-major f16 epilogue
    {
        dim3 grid(3 * EMB / 128, MTOT / 128);
        gemm_qkv<<<grid, 128, GEMM_SMEM>>>(Ahi, Alo, W1hi, W1lo, bqkv,
                                           Qh, Ql, Kh, Kl, Vh, EMB);
    }

    // 2) flash attention (S 3-term, PV 2-term), 2 CTAs/SM
    {
        dim3 grid(SEQ / 64, NH, BATCH);
        attn_mma<<<grid, 128, ATT_SMEM>>>(attn_bias, maskp, Thi, Tlo,
                                          Qh, Ql, Kh, Kl, Vh);
    }

    // 3) output projection (2-term, 3-stage pipeline, f32 epilogue)
    {
        dim3 grid(EMB / 128, MTOT / 128);
        gemm_proj<<<grid, 128, PROJ_SMEM>>>(Thi, Tlo, W2hi, bo, out, EMB, EMB);
    }
}

// round 17
// speedup vs baseline: 1.9063x; 1.0336x over previous
#include <cuda_runtime.h>
#include <cuda_fp16.h>
#include <cstdint>

// Problem constants
#define EMB   1024
#define NH    16
#define HD    64
#define BATCH 4
#define SEQ   1024
#define MTOT  (BATCH*SEQ)
#define SCALING 0.3952847075210474f   // (64*0.1)^-0.5
#define LOG2E  1.4426950408889634f
#define NEG   (-1e30f)

#define NQ_ELEM  (MTOT * EMB)
#define NW1_ELEM (3 * EMB * EMB)
#define NW2_ELEM (EMB * EMB)
#define NSPLIT   (NQ_ELEM + NW1_ELEM + NW2_ELEM)

// Scratch (device globals) — fp16
__device__ __half g_A_hi[MTOT * EMB];
__device__ __half g_A_lo[MTOT * EMB];
__device__ __half g_W1_hi[3 * EMB * EMB];
__device__ __half g_W1_lo[3 * EMB * EMB];
__device__ __half g_W2_hi[EMB * EMB];
__device__ __half g_att_hi[MTOT * EMB];
__device__ __half g_att_lo[MTOT * EMB];
__device__ __half g_Qh[MTOT * EMB];
__device__ __half g_Ql[MTOT * EMB];
__device__ __half g_Kh[MTOT * EMB];
__device__ __half g_Kl[MTOT * EMB];
__device__ __half g_Vh[MTOT * EMB];

// ---------------------------------------------------------------------------
// PTX helpers
// ---------------------------------------------------------------------------
#define LDSM4(r, addr) \
    asm volatile("ldmatrix.sync.aligned.m8n8.x4.shared.b16 {%0,%1,%2,%3}, [%4];" \
                 : "=r"((r)[0]), "=r"((r)[1]), "=r"((r)[2]), "=r"((r)[3]) : "r"(addr))

#define LDSM4T(r, addr) \
    asm volatile("ldmatrix.sync.aligned.m8n8.x4.trans.shared.b16 {%0,%1,%2,%3}, [%4];" \
                 : "=r"((r)[0]), "=r"((r)[1]), "=r"((r)[2]), "=r"((r)[3]) : "r"(addr))

#define MMA_F16(d, a, b) \
    asm volatile("mma.sync.aligned.m16n8k16.row.col.f32.f16.f16.f32 " \
                 "{%0,%1,%2,%3},{%4,%5,%6,%7},{%8,%9},{%0,%1,%2,%3};" \
                 : "+f"((d)[0]), "+f"((d)[1]), "+f"((d)[2]), "+f"((d)[3]) \
                 : "r"((a)[0]), "r"((a)[1]), "r"((a)[2]), "r"((a)[3]), \
                   "r"((b)[0]), "r"((b)[1]))

__device__ __forceinline__ void cp16(uint32_t s, const void* g) {
    asm volatile("cp.async.cg.shared.global [%0], [%1], 16;" :: "r"(s), "l"(g));
}

__device__ __forceinline__ uint32_t packh(float lo, float hi) {
    uint32_t r;
    asm("cvt.rn.f16x2.f32 %0, %1, %2;" : "=r"(r) : "f"(hi), "f"(lo));
    return r;
}
__device__ __forceinline__ uint32_t residpackh(uint32_t ph, float lo, float hi) {
    __half2 h = *(__half2*)&ph;
    return packh(lo - __low2float(h), hi - __high2float(h));
}

// ---------------------------------------------------------------------------
// merged f32 -> f16 (hi, lo) split: query, Wqkv (hi+lo); Wo (hi only)
// ---------------------------------------------------------------------------
__global__ __launch_bounds__(256)
void split_all(const float* __restrict__ q, const float* __restrict__ w1,
               const float* __restrict__ w2,
               __half* __restrict__ Ahi, __half* __restrict__ Alo,
               __half* __restrict__ W1hi, __half* __restrict__ W1lo,
               __half* __restrict__ W2hi)
{
    int i = (blockIdx.x * 256 + threadIdx.x) * 4;
    const float* src;
    __half *hi, *lo;
    int off;
    bool wantlo = true;
    if (i < NQ_ELEM)                { src = q;  hi = Ahi;  lo = Alo;  off = i; }
    else if (i < NQ_ELEM + NW1_ELEM){ src = w1; hi = W1hi; lo = W1lo; off = i - NQ_ELEM; }
    else { src = w2; hi = W2hi; lo = nullptr; off = i - NQ_ELEM - NW1_ELEM; wantlo = false; }

    float4 v = *(const float4*)(src + off);
    float f[4] = {v.x, v.y, v.z, v.w};
    __half h[4], l[4];
#pragma unroll
    for (int j = 0; j < 4; j++) {
        h[j] = __float2half(f[j]);
        l[j] = __float2half(f[j] - __half2float(h[j]));
    }
    *(uint2*)(hi + off) = *(const uint2*)h;
    if (wantlo) *(uint2*)(lo + off) = *(const uint2*)l;
}

// ---------------------------------------------------------------------------
// QKV GEMM (fp16 split, fused head-major f16 hi/lo epilogue, Q pre-scaled by
// SCALING*LOG2E for the exp2 softmax).
// Q/K CTAs (bn < 2048): 3-term.  V CTAs (bn >= 2048): 2-term (Bl dropped —
// V error already dominated by hi-only storage).
// CTA 128x128, 128 threads, warp tile 64x64, BK=32, 2-stage, 2 CTAs/SM.
// ---------------------------------------------------------------------------
#define AST   40
#define MAT_H (128 * AST)
#define GEMM_SMEM (8 * MAT_H * 2)   // 81920 B
#define EP_ST 68

__global__ __launch_bounds__(128, 2)
void gemm_qkv(const __half* __restrict__ Ah, const __half* __restrict__ Al,
              const __half* __restrict__ Bh, const __half* __restrict__ Bl,
              const float* __restrict__ bias,
              __half* __restrict__ Qh, __half* __restrict__ Ql,
              __half* __restrict__ Kh, __half* __restrict__ Kl,
              __half* __restrict__ Vh, int K)
{
    extern __shared__ __align__(16) __half smem_b[];
    const uint32_t sm_base = (uint32_t)__cvta_generic_to_shared(smem_b);

    const int t    = threadIdx.x;
    const int lane = t & 31;
    const int w    = t >> 5;
    const int wm   = w & 1;
    const int wn   = w >> 1;
    const int bm   = blockIdx.y * 128;
    const int bn   = blockIdx.x * 128;
    const int nk   = K >> 5;
    const int m    = bn >> 10;          // 0=q 1=k 2=v (uniform per CTA)
    const bool full = (m != 2);         // V: 2-term

    float acc[4][8][4];
#pragma unroll
    for (int mi = 0; mi < 4; mi++)
#pragma unroll
        for (int ni = 0; ni < 8; ni++)
#pragma unroll
            for (int q = 0; q < 4; q++) acc[mi][ni][q] = 0.f;

    const __half* gp[4] = {Ah, Al, Bh, Bl};
    const int climit = full ? 2048 : 1536;

    auto issue = [&](int stage, int k0) {
#pragma unroll
        for (int i = 0; i < 16; i++) {
            int c = t + i * 128;
            if (c >= climit) break;
            int mat = c >> 9;
            int idx = c & 511;
            int row = idx >> 2, ck = (idx & 3) * 8;
            int base = (mat < 2) ? bm : bn;
            uint32_t so = sm_base + (uint32_t)(stage * 4 + mat) * MAT_H * 2;
            cp16(so + (uint32_t)(row * AST + ck) * 2,
                 gp[mat] + (size_t)(base + row) * K + k0 + ck);
        }
        asm volatile("cp.async.commit_group;");
    };

    issue(0, 0);
    issue(1, 32);
    asm volatile("cp.async.wait_group 1;");
    __syncthreads();

    for (int kt = 0; kt < nk; kt++) {
        const int stage = kt & 1;
        const uint32_t bAh = sm_base + (uint32_t)(stage * 4 + 0) * MAT_H * 2;
        const uint32_t bAl = sm_base + (uint32_t)(stage * 4 + 1) * MAT_H * 2;
        const uint32_t bBh = sm_base + (uint32_t)(stage * 4 + 2) * MAT_H * 2;
        const uint32_t bBl = sm_base + (uint32_t)(stage * 4 + 3) * MAT_H * 2;

#pragma unroll
        for (int ks = 0; ks < 2; ks++) {
            uint32_t ah[4][4], al[4][4], bh[8][2], bl[8][2];

            const int arow = wm * 64 + (lane & 15);
            const int acol = ks * 16 + (lane >> 4) * 8;
#pragma unroll
            for (int mi = 0; mi < 4; mi++) {
                uint32_t off = (uint32_t)((arow + mi * 16) * AST + acol) * 2;
                LDSM4(ah[mi], bAh + off);
                LDSM4(al[mi], bAl + off);
            }

            const int brow = wn * 64 + (lane >> 4) * 8 + (lane & 7);
            const int bcol = ks * 16 + ((lane >> 3) & 1) * 8;
#pragma unroll
            for (int ni2 = 0; ni2 < 4; ni2++) {
                uint32_t off = (uint32_t)((brow + ni2 * 16) * AST + bcol) * 2;
                uint32_t r[4];
                LDSM4(r, bBh + off);
                bh[ni2 * 2][0] = r[0]; bh[ni2 * 2][1] = r[1];
                bh[ni2 * 2 + 1][0] = r[2]; bh[ni2 * 2 + 1][1] = r[3];
                if (full) {
                    LDSM4(r, bBl + off);
                    bl[ni2 * 2][0] = r[0]; bl[ni2 * 2][1] = r[1];
                    bl[ni2 * 2 + 1][0] = r[2]; bl[ni2 * 2 + 1][1] = r[3];
                }
            }

#pragma unroll
            for (int mi = 0; mi < 4; mi++)
#pragma unroll
                for (int ni = 0; ni < 8; ni++) {
                    MMA_F16(acc[mi][ni], ah[mi], bh[ni]);
                    MMA_F16(acc[mi][ni], al[mi], bh[ni]);
                    if (full) MMA_F16(acc[mi][ni], ah[mi], bl[ni]);
                }
        }

        asm volatile("cp.async.wait_group 0;");
        __syncthreads();
        if (kt + 2 < nk) issue(kt & 1, (kt + 2) << 5);
    }

    // fused qkv-split epilogue, smem-staged; Q,K get hi+lo, V hi only.
    // Q pre-scaled by SCALING*LOG2E (exp2-based softmax downstream).
    uint32_t* sh = (uint32_t*)smem_b;
    uint32_t* sl = sh + 128 * EP_ST;
    const float sc = (m == 0) ? (SCALING * LOG2E) : 1.0f;

#pragma unroll
    for (int mi = 0; mi < 4; mi++) {
        const int lr0 = wm * 64 + mi * 16 + (lane >> 2);
#pragma unroll
        for (int ni = 0; ni < 8; ni++) {
            const int lcol = wn * 64 + ni * 8 + (lane & 3) * 2;
            const int colu = lcol >> 1;
            float bx = bias[bn + lcol], by = bias[bn + lcol + 1];
            float a0 = (acc[mi][ni][0] + bx) * sc;
            float a1 = (acc[mi][ni][1] + by) * sc;
            float b0 = (acc[mi][ni][2] + bx) * sc;
            float b1 = (acc[mi][ni][3] + by) * sc;
            uint32_t hp0 = packh(a0, a1);
            uint32_t hp1 = packh(b0, b1);
            sh[lr0 * EP_ST + colu] = hp0;
            sl[lr0 * EP_ST + colu] = residpackh(hp0, a0, a1);
            sh[(lr0 + 8) * EP_ST + colu] = hp1;
            sl[(lr0 + 8) * EP_ST + colu] = residpackh(hp1, b0, b1);
        }
    }
    __syncthreads();

    uint32_t* oh = (uint32_t*)((m == 0) ? Qh : (m == 1) ? Kh : Vh);
    uint32_t* ol = (uint32_t*)((m == 0) ? Ql : Kl);
    const int hh0 = (bn >> 6) & 15;
    const int bb = bm >> 10, s0 = bm & 1023;

#pragma unroll
    for (int i = 0; i < 16; i++) {
        int c = t + i * 128;
        int row = c >> 4, sub = c & 15;
        int j = sub >> 3, q4 = (sub & 7) * 4;
        size_t g = (((size_t)(bb * NH + hh0 + j)) * SEQ + s0 + row) * 32 + q4;
        uint4 vh4 = *(uint4*)&sh[row * EP_ST + j * 32 + q4];
        *(uint4*)&oh[g] = vh4;
        if (m != 2) {
            uint4 vl4 = *(uint4*)&sl[row * EP_ST + j * 32 + q4];
            *(uint4*)&ol[g] = vl4;
        }
    }
}

// ---------------------------------------------------------------------------
// Output projection GEMM (2-term). 3-stage pipeline, 2 CTAs/SM.
// ---------------------------------------------------------------------------
#define PST_B 30720
#define PROJ_SMEM (3 * PST_B)   // 92160

__global__ __launch_bounds__(128, 2)
void gemm_proj(const __half* __restrict__ Ah, const __half* __restrict__ Al,
               const __half* __restrict__ Bh,
               const float* __restrict__ bias,
               float* __restrict__ C, int N, int K)
{
    extern __shared__ __align__(16) __half smem_b[];
    const uint32_t sm_base = (uint32_t)__cvta_generic_to_shared(smem_b);

    const int t    = threadIdx.x;
    const int lane = t & 31;
    const int w    = t >> 5;
    const int wm   = w & 1;
    const int wn   = w >> 1;
    const int bm   = blockIdx.y * 128;
    const int bn   = blockIdx.x * 128;
    const int nk   = K >> 5;

    float acc[4][8][4];
#pragma unroll
    for (int mi = 0; mi < 4; mi++)
#pragma unroll
        for (int ni = 0; ni < 8; ni++)
#pragma unroll
            for (int q = 0; q < 4; q++) acc[mi][ni][q] = 0.f;

    const __half* gp[3] = {Ah, Al, Bh};

    auto issue = [&](int stage, int k0) {
#pragma unroll
        for (int i = 0; i < 12; i++) {
            int c = t + i * 128;
            int mat = c >> 9;
            int idx = c & 511;
            int row = idx >> 2, ck = (idx & 3) * 8;
            int base = (mat < 2) ? bm : bn;
            uint32_t so = sm_base + (uint32_t)stage * PST_B + (uint32_t)mat * (MAT_H * 2);
            cp16(so + (uint32_t)(row * AST + ck) * 2,
                 gp[mat] + (size_t)(base + row) * K + k0 + ck);
        }
        asm volatile("cp.async.commit_group;");
    };

    issue(0, 0);
    issue(1, 32);
    asm volatile("cp.async.wait_group 1;");
    __syncthreads();

    for (int kt = 0; kt < nk; kt++) {
        if (kt + 2 < nk) issue((kt + 2) % 3, (kt + 2) << 5);

        const uint32_t sb  = sm_base + (uint32_t)(kt % 3) * PST_B;
        const uint32_t bAh = sb;
        const uint32_t bAl = sb + MAT_H * 2;
        const uint32_t bBh = sb + 2 * (MAT_H * 2);

#pragma unroll
        for (int ks = 0; ks < 2; ks++) {
            uint32_t ah[4][4], al[4][4], bh[8][2];

            const int arow = wm * 64 + (lane & 15);
            const int acol = ks * 16 + (lane >> 4) * 8;
#pragma unroll
            for (int mi = 0; mi < 4; mi++) {
                uint32_t off = (uint32_t)((arow + mi * 16) * AST + acol) * 2;
                LDSM4(ah[mi], bAh + off);
                LDSM4(al[mi], bAl + off);
            }

            const int brow = wn * 64 + (lane >> 4) * 8 + (lane & 7);
            const int bcol = ks * 16 + ((lane >> 3) & 1) * 8;
#pragma unroll
            for (int ni2 = 0; ni2 < 4; ni2++) {
                uint32_t off = (uint32_t)((brow + ni2 * 16) * AST + bcol) * 2;
                uint32_t r[4];
                LDSM4(r, bBh + off);
                bh[ni2 * 2][0] = r[0]; bh[ni2 * 2][1] = r[1];
                bh[ni2 * 2 + 1][0] = r[2]; bh[ni2 * 2 + 1][1] = r[3];
            }

#pragma unroll
            for (int mi = 0; mi < 4; mi++)
#pragma unroll
                for (int ni = 0; ni < 8; ni++) {
                    MMA_F16(acc[mi][ni], ah[mi], bh[ni]);
                    MMA_F16(acc[mi][ni], al[mi], bh[ni]);
                }
        }

        if (kt + 2 < nk) asm volatile("cp.async.wait_group 1;");
        else             asm volatile("cp.async.wait_group 0;");
        __syncthreads();
    }

#pragma unroll
    for (int mi = 0; mi < 4; mi++) {
        const int r0 = bm + wm * 64 + mi * 16 + (lane >> 2);
#pragma unroll
        for (int ni = 0; ni < 8; ni++) {
            const int col = bn + wn * 64 + ni * 8 + (lane & 3) * 2;
            float bx = bias[col], by = bias[col + 1];
            float2 v0 = make_float2(acc[mi][ni][0] + bx, acc[mi][ni][1] + by);
            float2 v1 = make_float2(acc[mi][ni][2] + bx, acc[mi][ni][3] + by);
            *(float2*)&C[(size_t)r0 * N + col] = v0;
            *(float2*)&C[(size_t)(r0 + 8) * N + col] = v1;
        }
    }
}

// ---------------------------------------------------------------------------
// Flash attention (2 CTAs/SM). S 3-term (K hi/lo), PV 2-term (V hi).
// exp2-based softmax: Q pre-scaled by SCALING*LOG2E; bias folded via FMA.
// ---------------------------------------------------------------------------
#define AT_ST 72
#define Q_HI_B 0
#define Q_LO_B 9216
#define TILE_B 18432
#define ATT_MAT_B  9216
#define BUF_B  27648
#define ATT_SMEM (TILE_B + 2 * BUF_B)  // 73728

__global__ __launch_bounds__(128)
void attn_mma(const float* __restrict__ bias, const unsigned char* __restrict__ mask,
              __half* __restrict__ outh, __half* __restrict__ outl,
              const __half* __restrict__ Qh, const __half* __restrict__ Ql,
              const __half* __restrict__ Kh, const __half* __restrict__ Kl,
              const __half* __restrict__ Vh)
{
    extern __shared__ __align__(16) __half smA[];
    const uint32_t s_base = (uint32_t)__cvta_generic_to_shared(smA);

    const int t = threadIdx.x, lane = t & 31, wid = t >> 5;
    const int qt = blockIdx.x, h = blockIdx.y, b = blockIdx.z;
    const int qbase = qt * 64;
    const size_t hb = (size_t)(b * NH + h) * SEQ * HD;

    const int lr7 = lane & 7, l8 = (lane >> 3) & 1, l16 = lane >> 4;

    const __half* qsrc[2] = {Qh, Ql};
    const __half* ksrc[3] = {Kh, Kl, Vh};

#pragma unroll
    for (int it = 0; it < 8; it++) {
        int c = t + it * 128;
        int mat = c >> 9, r = (c >> 3) & 63, ck = c & 7;
        cp16(s_base + mat * Q_LO_B + (uint32_t)(r * AT_ST + ck * 8) * 2,
             qsrc[mat] + hb + (size_t)(qbase + r) * HD + ck * 8);
    }
#pragma unroll
    for (int it = 0; it < 12; it++) {
        int c = t + it * 128;
        int mat = c >> 9, r = (c >> 3) & 63, ck = c & 7;
        cp16(s_base + TILE_B + mat * ATT_MAT_B + (uint32_t)(r * AT_ST + ck * 8) * 2,
             ksrc[mat] + hb + (size_t)r * HD + ck * 8);
    }
    asm volatile("cp.async.commit_group;");
#pragma unroll
    for (int it = 0; it < 12; it++) {
        int c = t + it * 128;
        int mat = c >> 9, r = (c >> 3) & 63, ck = c & 7;
        cp16(s_base + TILE_B + BUF_B + mat * ATT_MAT_B + (uint32_t)(r * AT_ST + ck * 8) * 2,
             ksrc[mat] + hb + (size_t)(64 + r) * HD + ck * 8);
    }
    asm volatile("cp.async.commit_group;");
    asm volatile("cp.async.wait_group 1;");
    __syncthreads();

    uint32_t aqh[4][4], aql[4][4];
    {
        const int arow = wid * 16 + (lane & 15);
        const int acol = 8 * l16;
#pragma unroll
        for (int ks = 0; ks < 4; ks++) {
            uint32_t off = (uint32_t)(arow * AT_ST + ks * 16 + acol) * 2;
            LDSM4(aqh[ks], s_base + Q_HI_B + off);
            LDSM4(aql[ks], s_base + Q_LO_B + off);
        }
    }

    float O[8][4];
#pragma unroll
    for (int nf = 0; nf < 8; nf++)
#pragma unroll
        for (int q = 0; q < 4; q++) O[nf][q] = 0.f;
    float m0 = NEG, m1 = NEG, l0 = 0.f, l1 = 0.f;

    const float* bp = bias + (size_t)(b * NH + h) * SEQ * SEQ;
    const unsigned char* mrow = mask + (size_t)b * SEQ;
    const int qr = qbase + wid * 16 + (lane >> 2);
    const int colb = 2 * (lane & 3);

    const int krow = lr7 + 8 * l16;
    const int kcol = 8 * l8;
    const int vrow = lr7 + 8 * l8;
    const int vcol = 8 * l16;

    for (int kt = 0; kt < 16; kt++) {
        const uint32_t tb = s_base + TILE_B + (uint32_t)(kt & 1) * BUF_B;

        float2 bv0[8], bv1[8];
        uchar2 mk[8];
#pragma unroll
        for (int nf = 0; nf < 8; nf++) {
            int col = kt * 64 + nf * 8 + colb;
            bv0[nf] = *(const float2*)&bp[(size_t)qr * SEQ + col];
            bv1[nf] = *(const float2*)&bp[(size_t)(qr + 8) * SEQ + col];
            mk[nf]  = *(const uchar2*)&mrow[col];
        }

        float s[8][4];
#pragma unroll
        for (int nf = 0; nf < 8; nf++)
#pragma unroll
            for (int q = 0; q < 4; q++) s[nf][q] = 0.f;

#pragma unroll
        for (int ks = 0; ks < 4; ks++) {
            uint32_t bh[8][2], bl[8][2];
#pragma unroll
            for (int nf2 = 0; nf2 < 4; nf2++) {
                uint32_t off = (uint32_t)((nf2 * 16 + krow) * AT_ST + ks * 16 + kcol) * 2;
                uint32_t r4[4];
                LDSM4(r4, tb + 0 * ATT_MAT_B + off);
                bh[2*nf2][0] = r4[0]; bh[2*nf2][1] = r4[1];
                bh[2*nf2+1][0] = r4[2]; bh[2*nf2+1][1] = r4[3];
                LDSM4(r4, tb + 1 * ATT_MAT_B + off);
                bl[2*nf2][0] = r4[0]; bl[2*nf2][1] = r4[1];
                bl[2*nf2+1][0] = r4[2]; bl[2*nf2+1][1] = r4[3];
            }
#pragma unroll
            for (int nf = 0; nf < 8; nf++) {
                MMA_F16(s[nf], aqh[ks], bh[nf]);
                MMA_F16(s[nf], aql[ks], bh[nf]);
                MMA_F16(s[nf], aqh[ks], bl[nf]);
            }
        }

        // bias folded with LOG2E (S already in log2 domain from Q scaling)
#pragma unroll
        for (int nf = 0; nf < 8; nf++) {
            s[nf][0] = mk[nf].x ? NEG : fmaf(bv0[nf].x, LOG2E, s[nf][0]);
            s[nf][1] = mk[nf].y ? NEG : fmaf(bv0[nf].y, LOG2E, s[nf][1]);
            s[nf][2] = mk[nf].x ? NEG : fmaf(bv1[nf].x, LOG2E, s[nf][2]);
            s[nf][3] = mk[nf].y ? NEG : fmaf(bv1[nf].y, LOG2E, s[nf][3]);
        }

        float mx0 = NEG, mx1 = NEG;
#pragma unroll
        for (int nf = 0; nf < 8; nf++) {
            mx0 = fmaxf(mx0, fmaxf(s[nf][0], s[nf][1]));
            mx1 = fmaxf(mx1, fmaxf(s[nf][2], s[nf][3]));
        }
        mx0 = fmaxf(mx0, __shfl_xor_sync(0xffffffffu, mx0, 1));
        mx0 = fmaxf(mx0, __shfl_xor_sync(0xffffffffu, mx0, 2));
        mx1 = fmaxf(mx1, __shfl_xor_sync(0xffffffffu, mx1, 1));
        mx1 = fmaxf(mx1, __shfl_xor_sync(0xffffffffu, mx1, 2));
        float mn0 = fmaxf(m0, mx0), mn1 = fmaxf(m1, mx1);
        float sc0 = exp2f(m0 - mn0), sc1 = exp2f(m1 - mn1);
        m0 = mn0; m1 = mn1;
        float su0 = 0.f, su1 = 0.f;
#pragma unroll
        for (int nf = 0; nf < 8; nf++) {
            s[nf][0] = exp2f(s[nf][0] - mn0);
            s[nf][1] = exp2f(s[nf][1] - mn0);
            s[nf][2] = exp2f(s[nf][2] - mn1);
            s[nf][3] = exp2f(s[nf][3] - mn1);
            su0 += s[nf][0] + s[nf][1];
            su1 += s[nf][2] + s[nf][3];
        }
        su0 += __shfl_xor_sync(0xffffffffu, su0, 1);
        su0 += __shfl_xor_sync(0xffffffffu, su0, 2);
        su1 += __shfl_xor_sync(0xffffffffu, su1, 1);
        su1 += __shfl_xor_sync(0xffffffffu, su1, 2);
        l0 = l0 * sc0 + su0;
        l1 = l1 * sc1 + su1;
#pragma unroll
        for (int nf = 0; nf < 8; nf++) {
            O[nf][0] *= sc0; O[nf][1] *= sc0;
            O[nf][2] *= sc1; O[nf][3] *= sc1;
        }

#pragma unroll
        for (int ks = 0; ks < 4; ks++) {
            uint32_t aph[4], apl[4];
            {
                const float* p0 = s[2 * ks];
                const float* p1 = s[2 * ks + 1];
                aph[0] = packh(p0[0], p0[1]);
                aph[1] = packh(p0[2], p0[3]);
                aph[2] = packh(p1[0], p1[1]);
                aph[3] = packh(p1[2], p1[3]);
                apl[0] = residpackh(aph[0], p0[0], p0[1]);
                apl[1] = residpackh(aph[1], p0[2], p0[3]);
                apl[2] = residpackh(aph[2], p1[0], p1[1]);
                apl[3] = residpackh(aph[3], p1[2], p1[3]);
            }
            uint32_t vh[8][2];
#pragma unroll
            for (int nf2 = 0; nf2 < 4; nf2++) {
                uint32_t off = (uint32_t)((ks * 16 + vrow) * AT_ST + nf2 * 16 + vcol) * 2;
                uint32_t r4[4];
                LDSM4T(r4, tb + 2 * ATT_MAT_B + off);
                vh[2*nf2][0] = r4[0]; vh[2*nf2][1] = r4[1];
                vh[2*nf2+1][0] = r4[2]; vh[2*nf2+1][1] = r4[3];
            }
#pragma unroll
            for (int nf = 0; nf < 8; nf++) {
                MMA_F16(O[nf], aph, vh[nf]);
                MMA_F16(O[nf], apl, vh[nf]);
            }
        }

        asm volatile("cp.async.wait_group 0;");
        __syncthreads();
        if (kt + 2 < 16) {
#pragma unroll
            for (int it = 0; it < 12; it++) {
                int c = t + it * 128;
                int mat = c >> 9, r = (c >> 3) & 63, ck = c & 7;
                cp16(s_base + TILE_B + (uint32_t)(kt & 1) * BUF_B + mat * ATT_MAT_B +
                         (uint32_t)(r * AT_ST + ck * 8) * 2,
                     ksrc[mat] + hb + (size_t)((kt + 2) * 64 + r) * HD + ck * 8);
            }
            asm volatile("cp.async.commit_group;");
        }
    }

    float i0 = 1.f / l0, i1 = 1.f / l1;
    int orow = b * SEQ + qbase + wid * 16 + (lane >> 2);
    uint32_t* oh = (uint32_t*)outh;
    uint32_t* ol = (uint32_t*)outl;
#pragma unroll
    for (int nf = 0; nf < 8; nf++) {
        int col = h * HD + nf * 8 + colb;
        float a0 = O[nf][0] * i0, a1 = O[nf][1] * i0;
        float b0 = O[nf][2] * i1, b1 = O[nf][3] * i1;
        uint32_t h0 = packh(a0, a1);
        uint32_t l0r = residpackh(h0, a0, a1);
        uint32_t h1 = packh(b0, b1);
        uint32_t l1r = residpackh(h1, b0, b1);
        size_t idx0 = ((size_t)orow * EMB + col) >> 1;
        size_t idx1 = ((size_t)(orow + 8) * EMB + col) >> 1;
        oh[idx0] = h0; ol[idx0] = l0r;
        oh[idx1] = h1; ol[idx1] = l1r;
    }
}

// ---------------------------------------------------------------------------
extern "C" void kernel_launch(void* const* d_in, const int* in_sizes, int n_in,
                              void* d_out, int out_size)
{
    const float* query         = (const float*)d_in[0];
    const unsigned char* maskp = (const unsigned char*)d_in[1];
    const float* attn_bias     = (const float*)d_in[2];
    const float* Wqkv          = (const float*)d_in[3];
    const float* bqkv          = (const float*)d_in[4];
    const float* Wo            = (const float*)d_in[5];
    const float* bo            = (const float*)d_in[6];
    float* out                 = (float*)d_out;

    __half *Ahi, *Alo, *W1hi, *W1lo, *W2hi, *Thi, *Tlo;
    __half *Qh, *Ql, *Kh, *Kl, *Vh;
    cudaGetSymbolAddress((void**)&Ahi,  g_A_hi);
    cudaGetSymbolAddress((void**)&Alo,  g_A_lo);
    cudaGetSymbolAddress((void**)&W1hi, g_W1_hi);
    cudaGetSymbolAddress((void**)&W1lo, g_W1_lo);
    cudaGetSymbolAddress((void**)&W2hi, g_W2_hi);
    cudaGetSymbolAddress((void**)&Thi,  g_att_hi);
    cudaGetSymbolAddress((void**)&Tlo,  g_att_lo);
    cudaGetSymbolAddress((void**)&Qh,   g_Qh);
    cudaGetSymbolAddress((void**)&Ql,   g_Ql);
    cudaGetSymbolAddress((void**)&Kh,   g_Kh);
    cudaGetSymbolAddress((void**)&Kl,   g_Kl);
    cudaGetSymbolAddress((void**)&Vh,   g_Vh);

    cudaFuncSetAttribute(gemm_qkv,
                         cudaFuncAttributeMaxDynamicSharedMemorySize, GEMM_SMEM);
    cudaFuncSetAttribute(gemm_proj,
                         cudaFuncAttributeMaxDynamicSharedMemorySize, PROJ_SMEM);
    cudaFuncSetAttribute(attn_mma,
                         cudaFuncAttributeMaxDynamicSharedMemorySize, ATT_SMEM);

    // 0) split query + Wqkv (hi/lo) + Wo (hi) — one launch
    split_all<<<NSPLIT / 1024, 256>>>(query, Wqkv, Wo,
                                      Ahi, Alo, W1hi, W1lo, W2hi);

    // 1) QKV projection (Q/K 3-term, V 2-term), fused head-major f16 epilogue
    {
        dim3 grid(3 * EMB / 128, MTOT / 128);
        gemm_qkv<<<grid, 128, GEMM_SMEM>>>(Ahi, Alo, W1hi, W1lo, bqkv,
                                           Qh, Ql, Kh, Kl, Vh, EMB);
    }

    // 2) flash attention (S 3-term, PV 2-term, exp2 softmax), 2 CTAs/SM
    {
        dim3 grid(SEQ / 64, NH, BATCH);
        attn_mma<<<grid, 128, ATT_SMEM>>>(attn_bias, maskp, Thi, Tlo,
                                          Qh, Ql, Kh, Kl, Vh);
    }

    // 3) output projection (2-term, 3-stage pipeline, f32 epilogue)
    {
        dim3 grid(EMB / 128, MTOT / 128);
        gemm_proj<<<grid, 128, PROJ_SMEM>>>(Thi, Tlo, W2hi, bo, out, EMB, EMB);
    }
}